// round 1
// baseline (speedup 1.0000x reference)
#include <cuda_runtime.h>
#include <math.h>

// ---------------- problem constants ----------------
#define D_MODEL 1024
#define NHEAD   16
#define DHEAD   64
#define FF_DIM  4096
#define NSEQ    256
#define NB      4
#define NTOK    50257
#define NEXP    2000
#define NKTOP   20
#define NROWS   (NB*NSEQ)      // 1024
#define QKV_LD  3072
#define NBLK_V  393            // ceil(50257/128)

// ---------------- scratch (static device memory; no allocation) ----------------
__device__ float g_x    [NROWS*D_MODEL];
__device__ float g_qkv  [NROWS*QKV_LD];
__device__ float g_attn [NROWS*D_MODEL];
__device__ float g_tmp  [NROWS*D_MODEL];
__device__ float g_ffh  [NROWS*FF_DIM];
__device__ float g_sm_attn[NB*D_MODEL];
__device__ float g_sm_x   [NB*D_MODEL];
__device__ float g_sm_tmp [NB*D_MODEL];
__device__ float g_sm_ctx [NB*D_MODEL];
__device__ float g_sm_ffh [NB*FF_DIM];
__device__ float g_pmax[NROWS*NBLK_V];
__device__ float g_psum[NROWS*NBLK_V];
__device__ float g_lse [NROWS];
__device__ float g_lab [NB*(NSEQ-1)];
__device__ float g_stats[32];   // [0..19] jw, [20] imp

// ---------------- embedding gather ----------------
__global__ void embed_kernel(const int* __restrict__ inputs, const float* __restrict__ emb)
{
    int r = blockIdx.x;                 // b*256+s
    int tok = inputs[r];
    const float* src = emb + (size_t)tok * D_MODEL;
    float* dst = g_x + (size_t)r * D_MODEL;
    for (int d = threadIdx.x; d < D_MODEL; d += blockDim.x) dst[d] = src[d];
}

// ---------------- generic tiled GEMM: C[m,n] = A[m,:]·W[n,:] + bias[n] ----------------
// A (M,K) row-major, W (N,K) row-major.  M,N multiples of 128, K multiple of 16.
#define BM 128
#define BN 128
#define BK 16
__global__ __launch_bounds__(256) void gemm_kernel(
    const float* __restrict__ A, const float* __restrict__ W,
    const float* __restrict__ bias, float* __restrict__ C,
    int K, int ldC, int relu)
{
    __shared__ float As[BK][BM+4];
    __shared__ float Bs[BK][BN+4];
    int tid = threadIdx.x;
    int tx = tid & 15, ty = tid >> 4;
    int m0 = blockIdx.y * BM;
    int n0 = blockIdx.x * BN;
    float acc[8][8];
    #pragma unroll
    for (int i = 0; i < 8; i++)
        #pragma unroll
        for (int j = 0; j < 8; j++) acc[i][j] = 0.f;

    for (int k0 = 0; k0 < K; k0 += BK) {
        #pragma unroll
        for (int i = tid; i < BM*BK; i += 256) {
            int r = i >> 4, c = i & 15;
            As[c][r] = A[(size_t)(m0 + r) * K + k0 + c];
        }
        #pragma unroll
        for (int i = tid; i < BN*BK; i += 256) {
            int r = i >> 4, c = i & 15;
            Bs[c][r] = W[(size_t)(n0 + r) * K + k0 + c];
        }
        __syncthreads();
        #pragma unroll
        for (int k = 0; k < BK; k++) {
            float a[8], b[8];
            #pragma unroll
            for (int i = 0; i < 8; i++) a[i] = As[k][ty*8+i];
            #pragma unroll
            for (int j = 0; j < 8; j++) b[j] = Bs[k][tx*8+j];
            #pragma unroll
            for (int i = 0; i < 8; i++)
                #pragma unroll
                for (int j = 0; j < 8; j++) acc[i][j] += a[i]*b[j];
        }
        __syncthreads();
    }
    #pragma unroll
    for (int i = 0; i < 8; i++) {
        int m = m0 + ty*8 + i;
        #pragma unroll
        for (int j = 0; j < 8; j++) {
            int n = n0 + tx*8 + j;
            float v = acc[i][j] + (bias ? bias[n] : 0.f);
            if (relu) v = fmaxf(v, 0.f);
            C[(size_t)m*ldC + n] = v;
        }
    }
}

// ---------------- fused decoder GEMM + per-tile online logsumexp partials -----------
__global__ __launch_bounds__(256) void gemm_lse_kernel(
    const float* __restrict__ A, const float* __restrict__ W, int K)
{
    __shared__ float As[BK][BM+4];
    __shared__ float Bs[BK][BN+4];
    __shared__ float rbuf[128][17];
    __shared__ float rowmax[128];
    int tid = threadIdx.x;
    int tx = tid & 15, ty = tid >> 4;
    int m0 = blockIdx.y * BM;
    int n0 = blockIdx.x * BN;
    float acc[8][8];
    #pragma unroll
    for (int i = 0; i < 8; i++)
        #pragma unroll
        for (int j = 0; j < 8; j++) acc[i][j] = 0.f;

    for (int k0 = 0; k0 < K; k0 += BK) {
        #pragma unroll
        for (int i = tid; i < BM*BK; i += 256) {
            int r = i >> 4, c = i & 15;
            As[c][r] = A[(size_t)(m0 + r) * K + k0 + c];
        }
        #pragma unroll
        for (int i = tid; i < BN*BK; i += 256) {
            int r = i >> 4, c = i & 15;
            int n = n0 + r;
            Bs[c][r] = (n < NTOK) ? W[(size_t)n * K + k0 + c] : 0.f;
        }
        __syncthreads();
        #pragma unroll
        for (int k = 0; k < BK; k++) {
            float a[8], b[8];
            #pragma unroll
            for (int i = 0; i < 8; i++) a[i] = As[k][ty*8+i];
            #pragma unroll
            for (int j = 0; j < 8; j++) b[j] = Bs[k][tx*8+j];
            #pragma unroll
            for (int i = 0; i < 8; i++)
                #pragma unroll
                for (int j = 0; j < 8; j++) acc[i][j] += a[i]*b[j];
        }
        __syncthreads();
    }
    // per-row max over this tile's valid columns
    #pragma unroll
    for (int i = 0; i < 8; i++) {
        float mx = -INFINITY;
        #pragma unroll
        for (int j = 0; j < 8; j++) {
            int n = n0 + tx*8 + j;
            if (n < NTOK) mx = fmaxf(mx, acc[i][j]);
        }
        rbuf[ty*8+i][tx] = mx;
    }
    __syncthreads();
    if (tid < 128) {
        float m = -INFINITY;
        #pragma unroll
        for (int x = 0; x < 16; x++) m = fmaxf(m, rbuf[tid][x]);
        rowmax[tid] = m;
    }
    __syncthreads();
    #pragma unroll
    for (int i = 0; i < 8; i++) {
        float rm = rowmax[ty*8+i];
        float s = 0.f;
        #pragma unroll
        for (int j = 0; j < 8; j++) {
            int n = n0 + tx*8 + j;
            if (n < NTOK) s += expf(acc[i][j] - rm);
        }
        rbuf[ty*8+i][tx] = s;
    }
    __syncthreads();
    if (tid < 128) {
        float s = 0.f;
        #pragma unroll
        for (int x = 0; x < 16; x++) s += rbuf[tid][x];
        int row = m0 + tid;
        g_pmax[(size_t)row*NBLK_V + blockIdx.x] = rowmax[tid];
        g_psum[(size_t)row*NBLK_V + blockIdx.x] = s;
    }
}

__global__ void lse_reduce_kernel()
{
    int r = blockIdx.x, tid = threadIdx.x;
    __shared__ float red[128];
    float m = -INFINITY;
    for (int i = tid; i < NBLK_V; i += 128) m = fmaxf(m, g_pmax[(size_t)r*NBLK_V + i]);
    red[tid] = m; __syncthreads();
    for (int s = 64; s > 0; s >>= 1) { if (tid < s) red[tid] = fmaxf(red[tid], red[tid+s]); __syncthreads(); }
    float gm = red[0]; __syncthreads();
    double sum = 0.0;
    for (int i = tid; i < NBLK_V; i += 128)
        sum += (double)g_psum[(size_t)r*NBLK_V + i] * exp((double)g_pmax[(size_t)r*NBLK_V + i] - (double)gm);
    __shared__ double redd[128];
    redd[tid] = sum; __syncthreads();
    for (int s = 64; s > 0; s >>= 1) { if (tid < s) redd[tid] += redd[tid+s]; __syncthreads(); }
    if (tid == 0) g_lse[r] = gm + (float)log(redd[0]);
}

// ---------------- small-M GEMM (per-output-column block, warp-reduced) -------------
__global__ void rowdot_kernel(
    const float* __restrict__ A, long strideA,
    const float* __restrict__ W, const float* __restrict__ bias,
    float* __restrict__ C, long strideC,
    int M, int K, float alpha, int relu)
{
    int n = blockIdx.x;
    int tid = threadIdx.x;   // 128
    const float* w = W + (size_t)n * K;
    __shared__ float red[128];
    for (int m = 0; m < M; m++) {
        const float* a = A + (size_t)m * strideA;
        float s = 0.f;
        for (int k = tid; k < K; k += 128) s += a[k]*w[k];
        red[tid] = s; __syncthreads();
        for (int st = 64; st > 0; st >>= 1) { if (tid < st) red[tid] += red[tid+st]; __syncthreads(); }
        if (tid == 0) {
            float v = alpha*red[0] + (bias ? bias[n] : 0.f);
            if (relu) v = fmaxf(v, 0.f);
            C[(size_t)m*strideC + n] = v;
        }
        __syncthreads();
    }
}

// ---------------- attention (one block per (q,h,b)) ----------------
__global__ __launch_bounds__(256) void attn_kernel(
    const float* __restrict__ qkv, float* __restrict__ out, int nq, int sq_base)
{
    int qi = blockIdx.x, h = blockIdx.y, b = blockIdx.z;
    int sq = sq_base + qi;
    int tid = threadIdx.x;
    __shared__ float qrow[DHEAD];
    __shared__ float sc[NSEQ];
    __shared__ float red[256];
    __shared__ float sden;
    __shared__ float osum[4][DHEAD];
    const float* base = qkv + (size_t)b * NSEQ * QKV_LD;
    if (tid < DHEAD) qrow[tid] = base[(size_t)sq*QKV_LD + h*DHEAD + tid];
    __syncthreads();
    {
        const float* krow = base + (size_t)tid*QKV_LD + D_MODEL + h*DHEAD;
        float d = 0.f;
        #pragma unroll
        for (int t = 0; t < DHEAD; t++) d += qrow[t]*krow[t];
        sc[tid] = d * 0.125f;  // 1/sqrt(64)
    }
    __syncthreads();
    // softmax
    red[tid] = sc[tid]; __syncthreads();
    for (int s = 128; s > 0; s >>= 1) { if (tid < s) red[tid] = fmaxf(red[tid], red[tid+s]); __syncthreads(); }
    float mx = red[0]; __syncthreads();
    float e = expf(sc[tid] - mx);
    red[tid] = e; __syncthreads();
    for (int s = 128; s > 0; s >>= 1) { if (tid < s) red[tid] += red[tid+s]; __syncthreads(); }
    if (tid == 0) sden = red[0];
    __syncthreads();
    sc[tid] = e;
    __syncthreads();
    // o = sum_j p_j * v_j
    int d = tid & 63, g = tid >> 6;
    const float* vb = base + 2*D_MODEL + h*DHEAD + d;
    float o = 0.f;
    for (int j = g*64; j < (g+1)*64; j++) o += sc[j] * vb[(size_t)j*QKV_LD];
    osum[g][d] = o; __syncthreads();
    if (tid < DHEAD) {
        float r = (osum[0][tid]+osum[1][tid]+osum[2][tid]+osum[3][tid]) / sden;
        out[((size_t)(b*nq + qi))*D_MODEL + h*DHEAD + tid] = r;
    }
}

// ---------------- residual + layernorm ----------------
__global__ void ln_kernel(
    const float* __restrict__ in1, long s1,
    const float* __restrict__ in2, long s2,
    float* __restrict__ out, long so,
    const float* __restrict__ gam, const float* __restrict__ bet)
{
    int r = blockIdx.x, tid = threadIdx.x;   // 256 threads
    __shared__ float xr[D_MODEL];
    __shared__ float red[256];
    const float* p1 = in1 + (size_t)r*s1;
    const float* p2 = in2 + (size_t)r*s2;
    float ls = 0.f;
    for (int d = tid; d < D_MODEL; d += 256) { float v = p1[d]+p2[d]; xr[d] = v; ls += v; }
    red[tid] = ls; __syncthreads();
    for (int s = 128; s > 0; s >>= 1) { if (tid < s) red[tid] += red[tid+s]; __syncthreads(); }
    float mean = red[0] * (1.f/D_MODEL); __syncthreads();
    float lv = 0.f;
    for (int d = tid; d < D_MODEL; d += 256) { float t = xr[d]-mean; lv += t*t; }
    red[tid] = lv; __syncthreads();
    for (int s = 128; s > 0; s >>= 1) { if (tid < s) red[tid] += red[tid+s]; __syncthreads(); }
    float rstd = 1.f / sqrtf(red[0]*(1.f/D_MODEL) + 1e-5f);
    for (int d = tid; d < D_MODEL; d += 256)
        out[(size_t)r*so + d] = (xr[d]-mean)*rstd*gam[d] + bet[d];
}

// ---------------- gating statistics + top-k + softmax + importance ----------------
__global__ void stats_kernel(const float* __restrict__ w, const float* __restrict__ noise)
{
    __shared__ float tot[NEXP];
    __shared__ double redd[256];
    __shared__ float fv[256];
    __shared__ int   fi[256];
    __shared__ float topv[NKTOP];
    __shared__ double smean, sstd;
    int tid = threadIdx.x;
    // fm = mean over batch
    double ls = 0.0;
    for (int n = tid; n < NEXP; n += 256) {
        float f = 0.25f*(w[n] + w[NEXP+n] + w[2*NEXP+n] + w[3*NEXP+n]);
        tot[n] = f; ls += (double)f;
    }
    redd[tid] = ls; __syncthreads();
    for (int s = 128; s > 0; s >>= 1) { if (tid < s) redd[tid] += redd[tid+s]; __syncthreads(); }
    if (tid == 0) smean = redd[0] / NEXP;
    __syncthreads();
    double mfm = smean;
    ls = 0.0;
    for (int n = tid; n < NEXP; n += 256) { double t = (double)tot[n]-mfm; ls += t*t; }
    redd[tid] = ls; __syncthreads();
    for (int s = 128; s > 0; s >>= 1) { if (tid < s) redd[tid] += redd[tid+s]; __syncthreads(); }
    if (tid == 0) sstd = sqrt(redd[0] / (NEXP-1));
    __syncthreads();
    float stdfm = (float)sstd;
    for (int n = tid; n < NEXP; n += 256) tot[n] = tot[n] + noise[n]*stdfm;
    __syncthreads();
    // mean/std of total -> importance
    ls = 0.0;
    for (int n = tid; n < NEXP; n += 256) ls += (double)tot[n];
    redd[tid] = ls; __syncthreads();
    for (int s = 128; s > 0; s >>= 1) { if (tid < s) redd[tid] += redd[tid+s]; __syncthreads(); }
    if (tid == 0) smean = redd[0] / NEXP;
    __syncthreads();
    double mt = smean;
    ls = 0.0;
    for (int n = tid; n < NEXP; n += 256) { double t = (double)tot[n]-mt; ls += t*t; }
    redd[tid] = ls; __syncthreads();
    for (int s = 128; s > 0; s >>= 1) { if (tid < s) redd[tid] += redd[tid+s]; __syncthreads(); }
    if (tid == 0) {
        double st = sqrt(redd[0] / (NEXP-1));
        double ratio = st / mt;
        g_stats[20] = (float)(0.1 * ratio * ratio);
    }
    __syncthreads();
    // top-k (iterative argmax -> descending order like jax.lax.top_k)
    for (int it = 0; it < NKTOP; it++) {
        float bv = -INFINITY; int bi = 0x7fffffff;
        for (int n = tid; n < NEXP; n += 256) {
            float v = tot[n];
            if (v > bv || (v == bv && n < bi)) { bv = v; bi = n; }
        }
        fv[tid] = bv; fi[tid] = bi; __syncthreads();
        for (int s = 128; s > 0; s >>= 1) {
            if (tid < s) {
                float v2 = fv[tid+s]; int i2 = fi[tid+s];
                if (v2 > fv[tid] || (v2 == fv[tid] && i2 < fi[tid])) { fv[tid] = v2; fi[tid] = i2; }
            }
            __syncthreads();
        }
        if (tid == 0) { topv[it] = fv[0]; tot[fi[0]] = -INFINITY; }
        __syncthreads();
    }
    if (tid == 0) {
        float m = topv[0];
        float s = 0.f;
        float e[NKTOP];
        for (int k = 0; k < NKTOP; k++) { e[k] = expf(topv[k]-m); s += e[k]; }
        for (int k = 0; k < NKTOP; k++) g_stats[k] = e[k]/s;
    }
}

// ---------------- response mixture ----------------
__global__ void mix_kernel(const float* __restrict__ responses)
{
    __shared__ float w[NKTOP];
    if (threadIdx.x < NKTOP) w[threadIdx.x] = g_stats[threadIdx.x];
    __syncthreads();
    int i = blockIdx.x*blockDim.x + threadIdx.x;
    if (i < NROWS*D_MODEL) {
        float s = 0.f;
        #pragma unroll
        for (int k = 0; k < NKTOP; k++) s += w[k]*responses[(size_t)k*(NROWS*D_MODEL) + i];
        g_x[i] = s;
    }
}

// ---------------- label logit + final loss ----------------
__global__ void lablogit_kernel(const int* __restrict__ inputs, const float* __restrict__ dec_w)
{
    int s = blockIdx.x, b = blockIdx.y, tid = threadIdx.x;
    int lbl = inputs[b*NSEQ + s + 1];
    const float* a = g_x + ((size_t)(b*NSEQ + s))*D_MODEL;
    const float* wp = dec_w + (size_t)lbl*D_MODEL;
    __shared__ float red[128];
    float acc = 0.f;
    for (int k = tid; k < D_MODEL; k += 128) acc += a[k]*wp[k];
    red[tid] = acc; __syncthreads();
    for (int st = 64; st > 0; st >>= 1) { if (tid < st) red[tid] += red[tid+st]; __syncthreads(); }
    if (tid == 0) g_lab[b*(NSEQ-1)+s] = red[0];
}

__global__ void final_kernel(float* __restrict__ out)
{
    __shared__ double red[256];
    int tid = threadIdx.x;
    double s = 0.0;
    for (int i = tid; i < NB*(NSEQ-1); i += 256) {
        int b = i/(NSEQ-1), sp = i%(NSEQ-1);
        s += (double)g_lab[i] - (double)g_lse[b*NSEQ+sp];
    }
    red[tid] = s; __syncthreads();
    for (int st = 128; st > 0; st >>= 1) { if (tid < st) red[tid] += red[tid+st]; __syncthreads(); }
    if (tid == 0) {
        double ce = -red[0] / (double)(NB*(NSEQ-1));
        out[0] = (float)(ce + (double)g_stats[20]);
    }
}

// ---------------- host driver ----------------
extern "C" void kernel_launch(void* const* d_in, const int* in_sizes, int n_in,
                              void* d_out, int out_size)
{
    (void)in_sizes; (void)n_in; (void)out_size;
    const int*   inputs    = (const int*)  d_in[0];
    const float* responses = (const float*)d_in[1];
    const float* noise     = (const float*)d_in[2];
    const float* emb       = (const float*)d_in[3];
    const float* loc_Wqkv  = (const float*)d_in[4];
    const float* loc_bqkv  = (const float*)d_in[5];
    const float* loc_Wo    = (const float*)d_in[6];
    const float* loc_bo    = (const float*)d_in[7];
    const float* loc_ln1g  = (const float*)d_in[8];
    const float* loc_ln1b  = (const float*)d_in[9];
    const float* loc_W1    = (const float*)d_in[10];
    const float* loc_b1    = (const float*)d_in[11];
    const float* loc_W2    = (const float*)d_in[12];
    const float* loc_b2    = (const float*)d_in[13];
    const float* loc_ln2g  = (const float*)d_in[14];
    const float* loc_ln2b  = (const float*)d_in[15];
    const float* enc_Wqkv  = (const float*)d_in[16];
    const float* enc_bqkv  = (const float*)d_in[17];
    const float* enc_Wo    = (const float*)d_in[18];
    const float* enc_bo    = (const float*)d_in[19];
    const float* enc_ln1g  = (const float*)d_in[20];
    const float* enc_ln1b  = (const float*)d_in[21];
    const float* enc_W1    = (const float*)d_in[22];
    const float* enc_b1    = (const float*)d_in[23];
    const float* enc_W2    = (const float*)d_in[24];
    const float* enc_b2    = (const float*)d_in[25];
    const float* enc_ln2g  = (const float*)d_in[26];
    const float* enc_ln2b  = (const float*)d_in[27];
    const float* gate_w    = (const float*)d_in[28];
    const float* gate_b    = (const float*)d_in[29];
    const float* dec_w     = (const float*)d_in[30];
    float* out = (float*)d_out;

    float *p_x, *p_qkv, *p_attn, *p_tmp, *p_ffh;
    float *p_sm_attn, *p_sm_x, *p_sm_tmp, *p_sm_ctx, *p_sm_ffh;
    cudaGetSymbolAddress((void**)&p_x, g_x);
    cudaGetSymbolAddress((void**)&p_qkv, g_qkv);
    cudaGetSymbolAddress((void**)&p_attn, g_attn);
    cudaGetSymbolAddress((void**)&p_tmp, g_tmp);
    cudaGetSymbolAddress((void**)&p_ffh, g_ffh);
    cudaGetSymbolAddress((void**)&p_sm_attn, g_sm_attn);
    cudaGetSymbolAddress((void**)&p_sm_x, g_sm_x);
    cudaGetSymbolAddress((void**)&p_sm_tmp, g_sm_tmp);
    cudaGetSymbolAddress((void**)&p_sm_ctx, g_sm_ctx);
    cudaGetSymbolAddress((void**)&p_sm_ffh, g_sm_ffh);

    // 1) embed
    embed_kernel<<<NROWS, 256>>>(inputs, emb);

    // 2) loc layer: only last position needed downstream.
    //    K,V for all rows:
    gemm_kernel<<<dim3(2048/BN, NROWS/BM), 256>>>(
        p_x, loc_Wqkv + (size_t)D_MODEL*D_MODEL, loc_bqkv + D_MODEL,
        p_qkv + D_MODEL, D_MODEL, QKV_LD, 0);
    //    Q for the 4 last-position rows:
    rowdot_kernel<<<D_MODEL, 128>>>(
        p_x + (size_t)(NSEQ-1)*D_MODEL, (long)NSEQ*D_MODEL,
        loc_Wqkv, loc_bqkv,
        p_qkv + (size_t)(NSEQ-1)*QKV_LD, (long)NSEQ*QKV_LD,
        NB, D_MODEL, 1.f, 0);
    attn_kernel<<<dim3(1, NHEAD, NB), 256>>>(p_qkv, p_sm_attn, 1, NSEQ-1);
    rowdot_kernel<<<D_MODEL, 128>>>(p_sm_attn, D_MODEL, loc_Wo, loc_bo,
                                    p_sm_tmp, D_MODEL, NB, D_MODEL, 1.f, 0);
    ln_kernel<<<NB, 256>>>(p_x + (size_t)(NSEQ-1)*D_MODEL, (long)NSEQ*D_MODEL,
                           p_sm_tmp, D_MODEL, p_sm_x, D_MODEL, loc_ln1g, loc_ln1b);
    rowdot_kernel<<<FF_DIM, 128>>>(p_sm_x, D_MODEL, loc_W1, loc_b1,
                                   p_sm_ffh, FF_DIM, NB, D_MODEL, 1.f, 1);
    rowdot_kernel<<<D_MODEL, 128>>>(p_sm_ffh, FF_DIM, loc_W2, loc_b2,
                                    p_sm_tmp, D_MODEL, NB, FF_DIM, 1.f, 0);
    ln_kernel<<<NB, 256>>>(p_sm_x, D_MODEL, p_sm_tmp, D_MODEL,
                           p_sm_ctx, D_MODEL, loc_ln2g, loc_ln2b);

    // 3) gate weights (sqrt(D)=32 scaling folded in); written straight to output
    rowdot_kernel<<<NEXP, 128>>>(p_sm_ctx, D_MODEL, gate_w, gate_b,
                                 out + 1, NEXP, NB, D_MODEL, 32.f, 0);

    // 4) stats / top-k / softmax / importance
    stats_kernel<<<1, 256>>>(out + 1, noise);

    // 5) mixture of responses -> g_x
    mix_kernel<<<(NROWS*D_MODEL)/256, 256>>>(responses);

    // 6) two encoder layers
    for (int l = 0; l < 2; l++) {
        const float* Wqkv = enc_Wqkv + (size_t)l*3*D_MODEL*D_MODEL;
        const float* bqkv = enc_bqkv + (size_t)l*3*D_MODEL;
        const float* Wo   = enc_Wo   + (size_t)l*D_MODEL*D_MODEL;
        const float* bo   = enc_bo   + (size_t)l*D_MODEL;
        const float* g1   = enc_ln1g + (size_t)l*D_MODEL;
        const float* b1l  = enc_ln1b + (size_t)l*D_MODEL;
        const float* W1   = enc_W1   + (size_t)l*FF_DIM*D_MODEL;
        const float* bb1  = enc_b1   + (size_t)l*FF_DIM;
        const float* W2   = enc_W2   + (size_t)l*D_MODEL*FF_DIM;
        const float* bb2  = enc_b2   + (size_t)l*D_MODEL;
        const float* g2   = enc_ln2g + (size_t)l*D_MODEL;
        const float* b2l  = enc_ln2b + (size_t)l*D_MODEL;

        gemm_kernel<<<dim3(QKV_LD/BN, NROWS/BM), 256>>>(p_x, Wqkv, bqkv, p_qkv, D_MODEL, QKV_LD, 0);
        attn_kernel<<<dim3(NSEQ, NHEAD, NB), 256>>>(p_qkv, p_attn, NSEQ, 0);
        gemm_kernel<<<dim3(D_MODEL/BN, NROWS/BM), 256>>>(p_attn, Wo, bo, p_tmp, D_MODEL, D_MODEL, 0);
        ln_kernel<<<NROWS, 256>>>(p_x, D_MODEL, p_tmp, D_MODEL, p_x, D_MODEL, g1, b1l);
        gemm_kernel<<<dim3(FF_DIM/BN, NROWS/BM), 256>>>(p_x, W1, bb1, p_ffh, D_MODEL, FF_DIM, 1);
        gemm_kernel<<<dim3(D_MODEL/BN, NROWS/BM), 256>>>(p_ffh, W2, bb2, p_tmp, FF_DIM, D_MODEL, 0);
        ln_kernel<<<NROWS, 256>>>(p_x, D_MODEL, p_tmp, D_MODEL, p_x, D_MODEL, g2, b2l);
    }

    // 7) fused decoder GEMM + logsumexp, label logits, CE + importance
    gemm_lse_kernel<<<dim3(NBLK_V, NROWS/BM), 256>>>(p_x, dec_w, D_MODEL);
    lse_reduce_kernel<<<NROWS, 128>>>();
    lablogit_kernel<<<dim3(NSEQ-1, NB), 128>>>(inputs, dec_w);
    final_kernel<<<1, 256>>>(out);
}

// round 2
// speedup vs baseline: 3.1690x; 3.1690x over previous
#include <cuda_runtime.h>
#include <math.h>
#include <stdint.h>

// ---------------- problem constants ----------------
#define D_MODEL 1024
#define NHEAD   16
#define DHEAD   64
#define FF_DIM  4096
#define NSEQ    256
#define NB      4
#define NTOK    50257
#define NEXP    2000
#define NKTOP   20
#define NROWS   (NB*NSEQ)      // 1024
#define QKV_LD  3072
#define NBLK_V  393            // ceil(50257/128)

// ---------------- scratch (static device memory; no allocation) ----------------
__device__ float g_x    [NROWS*D_MODEL];
__device__ float g_qkv  [NROWS*QKV_LD];
__device__ float g_attn [NROWS*D_MODEL];
__device__ float g_tmp  [NROWS*D_MODEL];
__device__ float g_ffh  [NROWS*FF_DIM];
__device__ float g_sm_attn[NB*D_MODEL];
__device__ float g_sm_x   [NB*D_MODEL];
__device__ float g_sm_tmp [NB*D_MODEL];
__device__ float g_sm_ctx [NB*D_MODEL];
__device__ float g_sm_ffh [NB*FF_DIM];
__device__ float g_pmax[NROWS*NBLK_V];
__device__ float g_psum[NROWS*NBLK_V];
__device__ float g_lse [NROWS];
__device__ float g_lab [NB*(NSEQ-1)];
__device__ float g_stats[32];   // [0..19] jw, [20] imp

// ---------------- embedding gather ----------------
__global__ void embed_kernel(const int* __restrict__ inputs, const float* __restrict__ emb)
{
    int r = blockIdx.x;
    int tok = inputs[r];
    const float4* src = (const float4*)(emb + (size_t)tok * D_MODEL);
    float4* dst = (float4*)(g_x + (size_t)r * D_MODEL);
    dst[threadIdx.x] = src[threadIdx.x];   // 256 threads * 4 = 1024
}

// ================= tf32 tensor-core GEMM core =================
// C[m,n] = sum_k A[m,k]*W[n,k].  A (M,K) row-major, W (N,K) row-major.
// Block tile 128x128, BK=16, 256 threads = 8 warps (2x4), warp tile 64x32.
__device__ __forceinline__ uint32_t f2tf32(float x)
{
    uint32_t u;
    asm("cvt.rna.tf32.f32 %0, %1;" : "=r"(u) : "f"(x));
    return u;
}

__device__ __forceinline__ void mma_mainloop(
    float acc[4][4][4],
    const float* __restrict__ A, const float* __restrict__ W,
    int K, int m0, int n0, int nmax)
{
    __shared__ uint32_t As[128][20];
    __shared__ uint32_t Bs[128][20];
    int tid  = threadIdx.x;
    int lane = tid & 31, wid = tid >> 5;
    int wm = wid >> 2, wn = wid & 3;
    int g = lane >> 2, tig = lane & 3;

    float4 ra[2], rb[2];
    {
        #pragma unroll
        for (int i = 0; i < 2; i++) {
            int flat = tid + i*256;
            int r = flat >> 2, c = (flat & 3) << 2;
            int nr = n0 + r; nr = (nr < nmax) ? nr : (nmax - 1);
            ra[i] = *(const float4*)(A + (size_t)(m0 + r)*K + c);
            rb[i] = *(const float4*)(W + (size_t)nr*K + c);
        }
    }
    for (int k0 = 0; k0 < K; k0 += 16) {
        #pragma unroll
        for (int i = 0; i < 2; i++) {
            int flat = tid + i*256;
            int r = flat >> 2, c = (flat & 3) << 2;
            uint4 ua = make_uint4(f2tf32(ra[i].x), f2tf32(ra[i].y),
                                  f2tf32(ra[i].z), f2tf32(ra[i].w));
            uint4 ub = make_uint4(f2tf32(rb[i].x), f2tf32(rb[i].y),
                                  f2tf32(rb[i].z), f2tf32(rb[i].w));
            *(uint4*)&As[r][c] = ua;
            *(uint4*)&Bs[r][c] = ub;
        }
        __syncthreads();
        if (k0 + 16 < K) {
            #pragma unroll
            for (int i = 0; i < 2; i++) {
                int flat = tid + i*256;
                int r = flat >> 2, c = (flat & 3) << 2;
                int nr = n0 + r; nr = (nr < nmax) ? nr : (nmax - 1);
                ra[i] = *(const float4*)(A + (size_t)(m0 + r)*K + (k0+16) + c);
                rb[i] = *(const float4*)(W + (size_t)nr*K + (k0+16) + c);
            }
        }
        #pragma unroll
        for (int ks = 0; ks < 16; ks += 8) {
            uint32_t af[4][4], bf[4][2];
            #pragma unroll
            for (int mt = 0; mt < 4; mt++) {
                int r0 = wm*64 + mt*16;
                af[mt][0] = As[r0+g  ][ks+tig  ];
                af[mt][1] = As[r0+g+8][ks+tig  ];
                af[mt][2] = As[r0+g  ][ks+tig+4];
                af[mt][3] = As[r0+g+8][ks+tig+4];
            }
            #pragma unroll
            for (int nt = 0; nt < 4; nt++) {
                int c0 = wn*32 + nt*8;
                bf[nt][0] = Bs[c0+g][ks+tig  ];
                bf[nt][1] = Bs[c0+g][ks+tig+4];
            }
            #pragma unroll
            for (int mt = 0; mt < 4; mt++)
                #pragma unroll
                for (int nt = 0; nt < 4; nt++) {
                    asm volatile(
                        "mma.sync.aligned.m16n8k8.row.col.f32.tf32.tf32.f32 "
                        "{%0,%1,%2,%3}, {%4,%5,%6,%7}, {%8,%9}, {%0,%1,%2,%3};\n"
                        : "+f"(acc[mt][nt][0]), "+f"(acc[mt][nt][1]),
                          "+f"(acc[mt][nt][2]), "+f"(acc[mt][nt][3])
                        : "r"(af[mt][0]), "r"(af[mt][1]),
                          "r"(af[mt][2]), "r"(af[mt][3]),
                          "r"(bf[nt][0]), "r"(bf[nt][1]));
                }
        }
        __syncthreads();
    }
}

__global__ __launch_bounds__(256, 2) void gemm_tc_kernel(
    const float* __restrict__ A, const float* __restrict__ W,
    const float* __restrict__ bias, float* __restrict__ C,
    int K, int ldC, int relu)
{
    float acc[4][4][4];
    #pragma unroll
    for (int a = 0; a < 4; a++)
        #pragma unroll
        for (int b = 0; b < 4; b++)
            #pragma unroll
            for (int c = 0; c < 4; c++) acc[a][b][c] = 0.f;

    int m0 = blockIdx.y * 128, n0 = blockIdx.x * 128;
    mma_mainloop(acc, A, W, K, m0, n0, 0x40000000);

    int tid = threadIdx.x;
    int lane = tid & 31, wid = tid >> 5;
    int wm = wid >> 2, wn = wid & 3;
    int g = lane >> 2, tig = lane & 3;
    int rowb = m0 + wm*64;
    int colb = n0 + wn*32;
    #pragma unroll
    for (int nt = 0; nt < 4; nt++) {
        int c = colb + nt*8 + 2*tig;
        float b0 = 0.f, b1 = 0.f;
        if (bias) { b0 = bias[c]; b1 = bias[c+1]; }
        #pragma unroll
        for (int mt = 0; mt < 4; mt++) {
            int r = rowb + mt*16 + g;
            float v0 = acc[mt][nt][0] + b0;
            float v1 = acc[mt][nt][1] + b1;
            float v2 = acc[mt][nt][2] + b0;
            float v3 = acc[mt][nt][3] + b1;
            if (relu) {
                v0 = fmaxf(v0, 0.f); v1 = fmaxf(v1, 0.f);
                v2 = fmaxf(v2, 0.f); v3 = fmaxf(v3, 0.f);
            }
            *(float2*)(C + (size_t)r*ldC + c)     = make_float2(v0, v1);
            *(float2*)(C + (size_t)(r+8)*ldC + c) = make_float2(v2, v3);
        }
    }
}

// decoder GEMM + fused per-tile online logsumexp partials
__global__ __launch_bounds__(256, 2) void gemm_lse_tc_kernel(
    const float* __restrict__ A, const float* __restrict__ W, int K)
{
    float acc[4][4][4];
    #pragma unroll
    for (int a = 0; a < 4; a++)
        #pragma unroll
        for (int b = 0; b < 4; b++)
            #pragma unroll
            for (int c = 0; c < 4; c++) acc[a][b][c] = 0.f;

    int m0 = blockIdx.y * 128, n0 = blockIdx.x * 128;
    mma_mainloop(acc, A, W, K, m0, n0, NTOK);

    __shared__ float red_m[4][128];
    __shared__ float red_s[4][128];
    int tid = threadIdx.x;
    int lane = tid & 31, wid = tid >> 5;
    int wm = wid >> 2, wn = wid & 3;
    int g = lane >> 2, tig = lane & 3;
    int colb = n0 + wn*32;

    #pragma unroll
    for (int mt = 0; mt < 4; mt++) {
        #pragma unroll
        for (int h = 0; h < 2; h++) {
            float m = -INFINITY;
            #pragma unroll
            for (int nt = 0; nt < 4; nt++) {
                int c = colb + nt*8 + 2*tig;
                if (c     < NTOK) m = fmaxf(m, acc[mt][nt][h*2+0]);
                if (c + 1 < NTOK) m = fmaxf(m, acc[mt][nt][h*2+1]);
            }
            m = fmaxf(m, __shfl_xor_sync(0xffffffffu, m, 1));
            m = fmaxf(m, __shfl_xor_sync(0xffffffffu, m, 2));
            float s = 0.f;
            #pragma unroll
            for (int nt = 0; nt < 4; nt++) {
                int c = colb + nt*8 + 2*tig;
                if (c     < NTOK) s += __expf(acc[mt][nt][h*2+0] - m);
                if (c + 1 < NTOK) s += __expf(acc[mt][nt][h*2+1] - m);
            }
            s += __shfl_xor_sync(0xffffffffu, s, 1);
            s += __shfl_xor_sync(0xffffffffu, s, 2);
            if (tig == 0) {
                int lr = wm*64 + mt*16 + h*8 + g;
                red_m[wn][lr] = m;
                red_s[wn][lr] = s;
            }
        }
    }
    __syncthreads();
    if (tid < 128) {
        float m0v = red_m[0][tid], m1v = red_m[1][tid];
        float m2v = red_m[2][tid], m3v = red_m[3][tid];
        float mx = fmaxf(fmaxf(m0v, m1v), fmaxf(m2v, m3v));
        float s = red_s[0][tid]*__expf(m0v-mx) + red_s[1][tid]*__expf(m1v-mx)
                + red_s[2][tid]*__expf(m2v-mx) + red_s[3][tid]*__expf(m3v-mx);
        int row = m0 + tid;
        g_pmax[(size_t)row*NBLK_V + blockIdx.x] = mx;
        g_psum[(size_t)row*NBLK_V + blockIdx.x] = s;
    }
}

__global__ void lse_reduce_kernel()
{
    int r = blockIdx.x, tid = threadIdx.x;
    __shared__ float red[128];
    float m = -INFINITY;
    for (int i = tid; i < NBLK_V; i += 128) m = fmaxf(m, g_pmax[(size_t)r*NBLK_V + i]);
    red[tid] = m; __syncthreads();
    for (int s = 64; s > 0; s >>= 1) { if (tid < s) red[tid] = fmaxf(red[tid], red[tid+s]); __syncthreads(); }
    float gm = red[0]; __syncthreads();
    double sum = 0.0;
    for (int i = tid; i < NBLK_V; i += 128)
        sum += (double)g_psum[(size_t)r*NBLK_V + i] * exp((double)g_pmax[(size_t)r*NBLK_V + i] - (double)gm);
    __shared__ double redd[128];
    redd[tid] = sum; __syncthreads();
    for (int s = 64; s > 0; s >>= 1) { if (tid < s) redd[tid] += redd[tid+s]; __syncthreads(); }
    if (tid == 0) g_lse[r] = gm + (float)log(redd[0]);
}

// ---------------- small-M GEMM (per-output-column block, warp-reduced) -------------
__global__ void rowdot_kernel(
    const float* __restrict__ A, long strideA,
    const float* __restrict__ W, const float* __restrict__ bias,
    float* __restrict__ C, long strideC,
    int M, int K, float alpha, int relu)
{
    int n = blockIdx.x;
    int tid = threadIdx.x;   // 128
    const float* w = W + (size_t)n * K;
    __shared__ float red[128];
    for (int m = 0; m < M; m++) {
        const float* a = A + (size_t)m * strideA;
        float s = 0.f;
        for (int k = tid; k < K; k += 128) s += a[k]*w[k];
        red[tid] = s; __syncthreads();
        for (int st = 64; st > 0; st >>= 1) { if (tid < st) red[tid] += red[tid+st]; __syncthreads(); }
        if (tid == 0) {
            float v = alpha*red[0] + (bias ? bias[n] : 0.f);
            if (relu) v = fmaxf(v, 0.f);
            C[(size_t)m*strideC + n] = v;
        }
        __syncthreads();
    }
}

// ---------------- attention (one block per (q,h,b)) ----------------
__global__ __launch_bounds__(256) void attn_kernel(
    const float* __restrict__ qkv, float* __restrict__ out, int nq, int sq_base)
{
    int qi = blockIdx.x, h = blockIdx.y, b = blockIdx.z;
    int sq = sq_base + qi;
    int tid = threadIdx.x;
    __shared__ float4 qrow[DHEAD/4];
    __shared__ float sc[NSEQ];
    __shared__ float red[256];
    __shared__ float sden;
    __shared__ float osum[4][DHEAD];
    const float* base = qkv + (size_t)b * NSEQ * QKV_LD;
    if (tid < DHEAD/4)
        qrow[tid] = ((const float4*)(base + (size_t)sq*QKV_LD + h*DHEAD))[tid];
    __syncthreads();
    {
        const float4* krow = (const float4*)(base + (size_t)tid*QKV_LD + D_MODEL + h*DHEAD);
        float d = 0.f;
        #pragma unroll
        for (int t = 0; t < DHEAD/4; t++) {
            float4 k4 = krow[t];
            float4 q4 = qrow[t];
            d += q4.x*k4.x + q4.y*k4.y + q4.z*k4.z + q4.w*k4.w;
        }
        sc[tid] = d * 0.125f;  // 1/sqrt(64)
    }
    __syncthreads();
    // softmax
    red[tid] = sc[tid]; __syncthreads();
    for (int s = 128; s > 0; s >>= 1) { if (tid < s) red[tid] = fmaxf(red[tid], red[tid+s]); __syncthreads(); }
    float mx = red[0]; __syncthreads();
    float e = expf(sc[tid] - mx);
    red[tid] = e; __syncthreads();
    for (int s = 128; s > 0; s >>= 1) { if (tid < s) red[tid] += red[tid+s]; __syncthreads(); }
    if (tid == 0) sden = red[0];
    __syncthreads();
    sc[tid] = e;
    __syncthreads();
    int d = tid & 63, g = tid >> 6;
    const float* vb = base + 2*D_MODEL + h*DHEAD + d;
    float o = 0.f;
    for (int j = g*64; j < (g+1)*64; j++) o += sc[j] * vb[(size_t)j*QKV_LD];
    osum[g][d] = o; __syncthreads();
    if (tid < DHEAD) {
        float r = (osum[0][tid]+osum[1][tid]+osum[2][tid]+osum[3][tid]) / sden;
        out[((size_t)(b*nq + qi))*D_MODEL + h*DHEAD + tid] = r;
    }
}

// ---------------- residual + layernorm ----------------
__global__ void ln_kernel(
    const float* __restrict__ in1, long s1,
    const float* __restrict__ in2, long s2,
    float* __restrict__ out, long so,
    const float* __restrict__ gam, const float* __restrict__ bet)
{
    int r = blockIdx.x, tid = threadIdx.x;   // 256 threads
    __shared__ float xr[D_MODEL];
    __shared__ float red[256];
    const float* p1 = in1 + (size_t)r*s1;
    const float* p2 = in2 + (size_t)r*s2;
    float ls = 0.f;
    for (int d = tid; d < D_MODEL; d += 256) { float v = p1[d]+p2[d]; xr[d] = v; ls += v; }
    red[tid] = ls; __syncthreads();
    for (int s = 128; s > 0; s >>= 1) { if (tid < s) red[tid] += red[tid+s]; __syncthreads(); }
    float mean = red[0] * (1.f/D_MODEL); __syncthreads();
    float lv = 0.f;
    for (int d = tid; d < D_MODEL; d += 256) { float t = xr[d]-mean; lv += t*t; }
    red[tid] = lv; __syncthreads();
    for (int s = 128; s > 0; s >>= 1) { if (tid < s) red[tid] += red[tid+s]; __syncthreads(); }
    float rstd = 1.f / sqrtf(red[0]*(1.f/D_MODEL) + 1e-5f);
    for (int d = tid; d < D_MODEL; d += 256)
        out[(size_t)r*so + d] = (xr[d]-mean)*rstd*gam[d] + bet[d];
}

// ---------------- gating statistics + top-k + softmax + importance ----------------
__global__ void stats_kernel(const float* __restrict__ w, const float* __restrict__ noise)
{
    __shared__ float tot[NEXP];
    __shared__ double redd[256];
    __shared__ float fv[256];
    __shared__ int   fi[256];
    __shared__ float topv[NKTOP];
    __shared__ double smean, sstd;
    int tid = threadIdx.x;
    double ls = 0.0;
    for (int n = tid; n < NEXP; n += 256) {
        float f = 0.25f*(w[n] + w[NEXP+n] + w[2*NEXP+n] + w[3*NEXP+n]);
        tot[n] = f; ls += (double)f;
    }
    redd[tid] = ls; __syncthreads();
    for (int s = 128; s > 0; s >>= 1) { if (tid < s) redd[tid] += redd[tid+s]; __syncthreads(); }
    if (tid == 0) smean = redd[0] / NEXP;
    __syncthreads();
    double mfm = smean;
    ls = 0.0;
    for (int n = tid; n < NEXP; n += 256) { double t = (double)tot[n]-mfm; ls += t*t; }
    redd[tid] = ls; __syncthreads();
    for (int s = 128; s > 0; s >>= 1) { if (tid < s) redd[tid] += redd[tid+s]; __syncthreads(); }
    if (tid == 0) sstd = sqrt(redd[0] / (NEXP-1));
    __syncthreads();
    float stdfm = (float)sstd;
    for (int n = tid; n < NEXP; n += 256) tot[n] = tot[n] + noise[n]*stdfm;
    __syncthreads();
    ls = 0.0;
    for (int n = tid; n < NEXP; n += 256) ls += (double)tot[n];
    redd[tid] = ls; __syncthreads();
    for (int s = 128; s > 0; s >>= 1) { if (tid < s) redd[tid] += redd[tid+s]; __syncthreads(); }
    if (tid == 0) smean = redd[0] / NEXP;
    __syncthreads();
    double mt = smean;
    ls = 0.0;
    for (int n = tid; n < NEXP; n += 256) { double t = (double)tot[n]-mt; ls += t*t; }
    redd[tid] = ls; __syncthreads();
    for (int s = 128; s > 0; s >>= 1) { if (tid < s) redd[tid] += redd[tid+s]; __syncthreads(); }
    if (tid == 0) {
        double st = sqrt(redd[0] / (NEXP-1));
        double ratio = st / mt;
        g_stats[20] = (float)(0.1 * ratio * ratio);
    }
    __syncthreads();
    for (int it = 0; it < NKTOP; it++) {
        float bv = -INFINITY; int bi = 0x7fffffff;
        for (int n = tid; n < NEXP; n += 256) {
            float v = tot[n];
            if (v > bv || (v == bv && n < bi)) { bv = v; bi = n; }
        }
        fv[tid] = bv; fi[tid] = bi; __syncthreads();
        for (int s = 128; s > 0; s >>= 1) {
            if (tid < s) {
                float v2 = fv[tid+s]; int i2 = fi[tid+s];
                if (v2 > fv[tid] || (v2 == fv[tid] && i2 < fi[tid])) { fv[tid] = v2; fi[tid] = i2; }
            }
            __syncthreads();
        }
        if (tid == 0) { topv[it] = fv[0]; tot[fi[0]] = -INFINITY; }
        __syncthreads();
    }
    if (tid == 0) {
        float m = topv[0];
        float s = 0.f;
        float e[NKTOP];
        for (int k = 0; k < NKTOP; k++) { e[k] = expf(topv[k]-m); s += e[k]; }
        for (int k = 0; k < NKTOP; k++) g_stats[k] = e[k]/s;
    }
}

// ---------------- response mixture ----------------
__global__ void mix_kernel(const float* __restrict__ responses)
{
    __shared__ float w[NKTOP];
    if (threadIdx.x < NKTOP) w[threadIdx.x] = g_stats[threadIdx.x];
    __syncthreads();
    int i = blockIdx.x*blockDim.x + threadIdx.x;   // float4 index
    if (i < (NROWS*D_MODEL)/4) {
        float4 s = make_float4(0.f, 0.f, 0.f, 0.f);
        #pragma unroll
        for (int k = 0; k < NKTOP; k++) {
            float4 v = ((const float4*)responses)[(size_t)k*((NROWS*D_MODEL)/4) + i];
            float wk = w[k];
            s.x += wk*v.x; s.y += wk*v.y; s.z += wk*v.z; s.w += wk*v.w;
        }
        ((float4*)g_x)[i] = s;
    }
}

// ---------------- label logit + final loss ----------------
__global__ void lablogit_kernel(const int* __restrict__ inputs, const float* __restrict__ dec_w)
{
    int s = blockIdx.x, b = blockIdx.y, tid = threadIdx.x;
    int lbl = inputs[b*NSEQ + s + 1];
    const float* a = g_x + ((size_t)(b*NSEQ + s))*D_MODEL;
    const float* wp = dec_w + (size_t)lbl*D_MODEL;
    __shared__ float red[128];
    float acc = 0.f;
    for (int k = tid; k < D_MODEL; k += 128) acc += a[k]*wp[k];
    red[tid] = acc; __syncthreads();
    for (int st = 64; st > 0; st >>= 1) { if (tid < st) red[tid] += red[tid+st]; __syncthreads(); }
    if (tid == 0) g_lab[b*(NSEQ-1)+s] = red[0];
}

__global__ void final_kernel(float* __restrict__ out)
{
    __shared__ double red[256];
    int tid = threadIdx.x;
    double s = 0.0;
    for (int i = tid; i < NB*(NSEQ-1); i += 256) {
        int b = i/(NSEQ-1), sp = i%(NSEQ-1);
        s += (double)g_lab[i] - (double)g_lse[b*NSEQ+sp];
    }
    red[tid] = s; __syncthreads();
    for (int st = 128; st > 0; st >>= 1) { if (tid < st) red[tid] += red[tid+st]; __syncthreads(); }
    if (tid == 0) {
        double ce = -red[0] / (double)(NB*(NSEQ-1));
        out[0] = (float)(ce + (double)g_stats[20]);
    }
}

// ---------------- host driver ----------------
extern "C" void kernel_launch(void* const* d_in, const int* in_sizes, int n_in,
                              void* d_out, int out_size)
{
    (void)in_sizes; (void)n_in; (void)out_size;
    const int*   inputs    = (const int*)  d_in[0];
    const float* responses = (const float*)d_in[1];
    const float* noise     = (const float*)d_in[2];
    const float* emb       = (const float*)d_in[3];
    const float* loc_Wqkv  = (const float*)d_in[4];
    const float* loc_bqkv  = (const float*)d_in[5];
    const float* loc_Wo    = (const float*)d_in[6];
    const float* loc_bo    = (const float*)d_in[7];
    const float* loc_ln1g  = (const float*)d_in[8];
    const float* loc_ln1b  = (const float*)d_in[9];
    const float* loc_W1    = (const float*)d_in[10];
    const float* loc_b1    = (const float*)d_in[11];
    const float* loc_W2    = (const float*)d_in[12];
    const float* loc_b2    = (const float*)d_in[13];
    const float* loc_ln2g  = (const float*)d_in[14];
    const float* loc_ln2b  = (const float*)d_in[15];
    const float* enc_Wqkv  = (const float*)d_in[16];
    const float* enc_bqkv  = (const float*)d_in[17];
    const float* enc_Wo    = (const float*)d_in[18];
    const float* enc_bo    = (const float*)d_in[19];
    const float* enc_ln1g  = (const float*)d_in[20];
    const float* enc_ln1b  = (const float*)d_in[21];
    const float* enc_W1    = (const float*)d_in[22];
    const float* enc_b1    = (const float*)d_in[23];
    const float* enc_W2    = (const float*)d_in[24];
    const float* enc_b2    = (const float*)d_in[25];
    const float* enc_ln2g  = (const float*)d_in[26];
    const float* enc_ln2b  = (const float*)d_in[27];
    const float* gate_w    = (const float*)d_in[28];
    const float* gate_b    = (const float*)d_in[29];
    const float* dec_w     = (const float*)d_in[30];
    float* out = (float*)d_out;

    float *p_x, *p_qkv, *p_attn, *p_tmp, *p_ffh;
    float *p_sm_attn, *p_sm_x, *p_sm_tmp, *p_sm_ctx, *p_sm_ffh;
    cudaGetSymbolAddress((void**)&p_x, g_x);
    cudaGetSymbolAddress((void**)&p_qkv, g_qkv);
    cudaGetSymbolAddress((void**)&p_attn, g_attn);
    cudaGetSymbolAddress((void**)&p_tmp, g_tmp);
    cudaGetSymbolAddress((void**)&p_ffh, g_ffh);
    cudaGetSymbolAddress((void**)&p_sm_attn, g_sm_attn);
    cudaGetSymbolAddress((void**)&p_sm_x, g_sm_x);
    cudaGetSymbolAddress((void**)&p_sm_tmp, g_sm_tmp);
    cudaGetSymbolAddress((void**)&p_sm_ctx, g_sm_ctx);
    cudaGetSymbolAddress((void**)&p_sm_ffh, g_sm_ffh);

    // 1) embed
    embed_kernel<<<NROWS, 256>>>(inputs, emb);

    // 2) loc layer: only last position needed downstream.
    gemm_tc_kernel<<<dim3(2048/128, NROWS/128), 256>>>(
        p_x, loc_Wqkv + (size_t)D_MODEL*D_MODEL, loc_bqkv + D_MODEL,
        p_qkv + D_MODEL, D_MODEL, QKV_LD, 0);
    rowdot_kernel<<<D_MODEL, 128>>>(
        p_x + (size_t)(NSEQ-1)*D_MODEL, (long)NSEQ*D_MODEL,
        loc_Wqkv, loc_bqkv,
        p_qkv + (size_t)(NSEQ-1)*QKV_LD, (long)NSEQ*QKV_LD,
        NB, D_MODEL, 1.f, 0);
    attn_kernel<<<dim3(1, NHEAD, NB), 256>>>(p_qkv, p_sm_attn, 1, NSEQ-1);
    rowdot_kernel<<<D_MODEL, 128>>>(p_sm_attn, D_MODEL, loc_Wo, loc_bo,
                                    p_sm_tmp, D_MODEL, NB, D_MODEL, 1.f, 0);
    ln_kernel<<<NB, 256>>>(p_x + (size_t)(NSEQ-1)*D_MODEL, (long)NSEQ*D_MODEL,
                           p_sm_tmp, D_MODEL, p_sm_x, D_MODEL, loc_ln1g, loc_ln1b);
    rowdot_kernel<<<FF_DIM, 128>>>(p_sm_x, D_MODEL, loc_W1, loc_b1,
                                   p_sm_ffh, FF_DIM, NB, D_MODEL, 1.f, 1);
    rowdot_kernel<<<D_MODEL, 128>>>(p_sm_ffh, FF_DIM, loc_W2, loc_b2,
                                    p_sm_tmp, D_MODEL, NB, FF_DIM, 1.f, 0);
    ln_kernel<<<NB, 256>>>(p_sm_x, D_MODEL, p_sm_tmp, D_MODEL,
                           p_sm_ctx, D_MODEL, loc_ln2g, loc_ln2b);

    // 3) gate weights (sqrt(D)=32 scaling folded in)
    rowdot_kernel<<<NEXP, 128>>>(p_sm_ctx, D_MODEL, gate_w, gate_b,
                                 out + 1, NEXP, NB, D_MODEL, 32.f, 0);

    // 4) stats / top-k / softmax / importance
    stats_kernel<<<1, 256>>>(out + 1, noise);

    // 5) mixture of responses -> g_x
    mix_kernel<<<(NROWS*D_MODEL/4 + 255)/256, 256>>>(responses);

    // 6) two encoder layers
    for (int l = 0; l < 2; l++) {
        const float* Wqkv = enc_Wqkv + (size_t)l*3*D_MODEL*D_MODEL;
        const float* bqkv = enc_bqkv + (size_t)l*3*D_MODEL;
        const float* Wo   = enc_Wo   + (size_t)l*D_MODEL*D_MODEL;
        const float* bo   = enc_bo   + (size_t)l*D_MODEL;
        const float* g1   = enc_ln1g + (size_t)l*D_MODEL;
        const float* b1l  = enc_ln1b + (size_t)l*D_MODEL;
        const float* W1   = enc_W1   + (size_t)l*FF_DIM*D_MODEL;
        const float* bb1  = enc_b1   + (size_t)l*FF_DIM;
        const float* W2   = enc_W2   + (size_t)l*D_MODEL*FF_DIM;
        const float* bb2  = enc_b2   + (size_t)l*D_MODEL;
        const float* g2   = enc_ln2g + (size_t)l*D_MODEL;
        const float* b2l  = enc_ln2b + (size_t)l*D_MODEL;

        gemm_tc_kernel<<<dim3(QKV_LD/128, NROWS/128), 256>>>(p_x, Wqkv, bqkv, p_qkv, D_MODEL, QKV_LD, 0);
        attn_kernel<<<dim3(NSEQ, NHEAD, NB), 256>>>(p_qkv, p_attn, NSEQ, 0);
        gemm_tc_kernel<<<dim3(D_MODEL/128, NROWS/128), 256>>>(p_attn, Wo, bo, p_tmp, D_MODEL, D_MODEL, 0);
        ln_kernel<<<NROWS, 256>>>(p_x, D_MODEL, p_tmp, D_MODEL, p_x, D_MODEL, g1, b1l);
        gemm_tc_kernel<<<dim3(FF_DIM/128, NROWS/128), 256>>>(p_x, W1, bb1, p_ffh, D_MODEL, FF_DIM, 1);
        gemm_tc_kernel<<<dim3(D_MODEL/128, NROWS/128), 256>>>(p_ffh, W2, bb2, p_tmp, FF_DIM, D_MODEL, 0);
        ln_kernel<<<NROWS, 256>>>(p_x, D_MODEL, p_tmp, D_MODEL, p_x, D_MODEL, g2, b2l);
    }

    // 7) fused decoder GEMM + logsumexp, label logits, CE + importance
    gemm_lse_tc_kernel<<<dim3(NBLK_V, NROWS/128), 256>>>(p_x, dec_w, D_MODEL);
    lse_reduce_kernel<<<NROWS, 128>>>();
    lablogit_kernel<<<dim3(NSEQ-1, NB), 128>>>(inputs, dec_w);
    final_kernel<<<1, 256>>>(out);
}

// round 3
// speedup vs baseline: 4.2176x; 1.3309x over previous
#include <cuda_runtime.h>
#include <math.h>
#include <stdint.h>

// ---------------- problem constants ----------------
#define D_MODEL 1024
#define NHEAD   16
#define DHEAD   64
#define FF_DIM  4096
#define NSEQ    256
#define NB      4
#define NTOK    50257
#define NEXP    2000
#define NKTOP   20
#define NROWS   (NB*NSEQ)      // 1024
#define QKV_LD  3072
#define NBLK_V  393            // ceil(50257/128)

// ---------------- scratch (static device memory; no allocation) ----------------
__device__ float g_x    [NROWS*D_MODEL];
__device__ float g_qkv  [NROWS*QKV_LD];
__device__ float g_attn [NROWS*D_MODEL];
__device__ float g_tmp  [NROWS*D_MODEL];
__device__ float g_ffh  [NROWS*FF_DIM];
__device__ float g_sm_attn[NB*D_MODEL];
__device__ float g_sm_x   [NB*D_MODEL];
__device__ float g_sm_tmp [NB*D_MODEL];
__device__ float g_sm_ctx [NB*D_MODEL];
__device__ float g_sm_ffh [NB*FF_DIM];
__device__ float g_pmax[NROWS*NBLK_V];
__device__ float g_psum[NROWS*NBLK_V];
__device__ float g_lse [NROWS];
__device__ float g_lab [NB*(NSEQ-1)];
__device__ float g_stats[32];   // [0..19] jw, [20] imp

// ---------------- embedding gather ----------------
__global__ void embed_kernel(const int* __restrict__ inputs, const float* __restrict__ emb)
{
    int r = blockIdx.x;
    int tok = inputs[r];
    const float4* src = (const float4*)(emb + (size_t)tok * D_MODEL);
    float4* dst = (float4*)(g_x + (size_t)r * D_MODEL);
    dst[threadIdx.x] = src[threadIdx.x];
}

// ================= tf32 tensor-core GEMM core (cp.async double-buffered) ==========
__device__ __forceinline__ void cp_async16(void* smem, const void* gmem)
{
    uint32_t s = (uint32_t)__cvta_generic_to_shared(smem);
    asm volatile("cp.async.ca.shared.global [%0], [%1], 16;\n" :: "r"(s), "l"(gmem));
}
__device__ __forceinline__ void cp_commit()
{
    asm volatile("cp.async.commit_group;\n" ::: "memory");
}
template<int N> __device__ __forceinline__ void cp_wait()
{
    asm volatile("cp.async.wait_group %0;\n" :: "n"(N) : "memory");
}

// C[m,n] = sum_k A[m,k]*W[n,k].  Block 128x128, BK=16, 256 thr, warp tile 64x32.
__device__ __forceinline__ void mma_mainloop(
    float acc[4][4][4],
    const float* __restrict__ A, const float* __restrict__ W,
    int K, int m0, int n0, int nmax)
{
    __shared__ uint32_t As[2][128][20];
    __shared__ uint32_t Bs[2][128][20];
    int tid  = threadIdx.x;
    int lane = tid & 31, wid = tid >> 5;
    int wm = wid >> 2, wn = wid & 3;
    int g = lane >> 2, tig = lane & 3;

    // per-thread copy slots: 2 chunks of 16B per matrix
    int r0c = tid >> 2,        c0c = (tid & 3) << 2;       // chunk 0: rows 0..63
    int r1c = (tid + 256) >> 2, c1c = (tid & 3) << 2;      // chunk 1: rows 64..127
    int nr0 = n0 + r0c; nr0 = (nr0 < nmax) ? nr0 : (nmax - 1);
    int nr1 = n0 + r1c; nr1 = (nr1 < nmax) ? nr1 : (nmax - 1);
    const float* pa0 = A + (size_t)(m0 + r0c)*K + c0c;
    const float* pa1 = A + (size_t)(m0 + r1c)*K + c1c;
    const float* pb0 = W + (size_t)nr0*K + c0c;
    const float* pb1 = W + (size_t)nr1*K + c1c;

    int niter = K >> 4;
    // prefetch stage 0
    cp_async16(&As[0][r0c][c0c], pa0);
    cp_async16(&As[0][r1c][c1c], pa1);
    cp_async16(&Bs[0][r0c][c0c], pb0);
    cp_async16(&Bs[0][r1c][c1c], pb1);
    cp_commit();

    for (int it = 0; it < niter; it++) {
        int st = it & 1;
        if (it + 1 < niter) {
            int off = (it + 1) << 4;
            int sn = st ^ 1;
            cp_async16(&As[sn][r0c][c0c], pa0 + off);
            cp_async16(&As[sn][r1c][c1c], pa1 + off);
            cp_async16(&Bs[sn][r0c][c0c], pb0 + off);
            cp_async16(&Bs[sn][r1c][c1c], pb1 + off);
            cp_commit();
            cp_wait<1>();
        } else {
            cp_wait<0>();
        }
        __syncthreads();
        #pragma unroll
        for (int ks = 0; ks < 16; ks += 8) {
            uint32_t af[4][4], bf[4][2];
            #pragma unroll
            for (int mt = 0; mt < 4; mt++) {
                int r0 = wm*64 + mt*16;
                af[mt][0] = As[st][r0+g  ][ks+tig  ];
                af[mt][1] = As[st][r0+g+8][ks+tig  ];
                af[mt][2] = As[st][r0+g  ][ks+tig+4];
                af[mt][3] = As[st][r0+g+8][ks+tig+4];
            }
            #pragma unroll
            for (int nt = 0; nt < 4; nt++) {
                int c0 = wn*32 + nt*8;
                bf[nt][0] = Bs[st][c0+g][ks+tig  ];
                bf[nt][1] = Bs[st][c0+g][ks+tig+4];
            }
            #pragma unroll
            for (int mt = 0; mt < 4; mt++)
                #pragma unroll
                for (int nt = 0; nt < 4; nt++) {
                    asm volatile(
                        "mma.sync.aligned.m16n8k8.row.col.f32.tf32.tf32.f32 "
                        "{%0,%1,%2,%3}, {%4,%5,%6,%7}, {%8,%9}, {%0,%1,%2,%3};\n"
                        : "+f"(acc[mt][nt][0]), "+f"(acc[mt][nt][1]),
                          "+f"(acc[mt][nt][2]), "+f"(acc[mt][nt][3])
                        : "r"(af[mt][0]), "r"(af[mt][1]),
                          "r"(af[mt][2]), "r"(af[mt][3]),
                          "r"(bf[nt][0]), "r"(bf[nt][1]));
                }
        }
        __syncthreads();
    }
}

__global__ __launch_bounds__(256, 2) void gemm_tc_kernel(
    const float* __restrict__ A, const float* __restrict__ W,
    const float* __restrict__ bias, float* __restrict__ C,
    int K, int ldC, int relu)
{
    float acc[4][4][4];
    #pragma unroll
    for (int a = 0; a < 4; a++)
        #pragma unroll
        for (int b = 0; b < 4; b++)
            #pragma unroll
            for (int c = 0; c < 4; c++) acc[a][b][c] = 0.f;

    int m0 = blockIdx.y * 128, n0 = blockIdx.x * 128;
    mma_mainloop(acc, A, W, K, m0, n0, 0x40000000);

    int tid = threadIdx.x;
    int lane = tid & 31, wid = tid >> 5;
    int wm = wid >> 2, wn = wid & 3;
    int g = lane >> 2, tig = lane & 3;
    int rowb = m0 + wm*64;
    int colb = n0 + wn*32;
    #pragma unroll
    for (int nt = 0; nt < 4; nt++) {
        int c = colb + nt*8 + 2*tig;
        float b0 = 0.f, b1 = 0.f;
        if (bias) { b0 = bias[c]; b1 = bias[c+1]; }
        #pragma unroll
        for (int mt = 0; mt < 4; mt++) {
            int r = rowb + mt*16 + g;
            float v0 = acc[mt][nt][0] + b0;
            float v1 = acc[mt][nt][1] + b1;
            float v2 = acc[mt][nt][2] + b0;
            float v3 = acc[mt][nt][3] + b1;
            if (relu) {
                v0 = fmaxf(v0, 0.f); v1 = fmaxf(v1, 0.f);
                v2 = fmaxf(v2, 0.f); v3 = fmaxf(v3, 0.f);
            }
            *(float2*)(C + (size_t)r*ldC + c)     = make_float2(v0, v1);
            *(float2*)(C + (size_t)(r+8)*ldC + c) = make_float2(v2, v3);
        }
    }
}

// decoder GEMM + fused per-tile online logsumexp partials
__global__ __launch_bounds__(256, 2) void gemm_lse_tc_kernel(
    const float* __restrict__ A, const float* __restrict__ W, int K)
{
    float acc[4][4][4];
    #pragma unroll
    for (int a = 0; a < 4; a++)
        #pragma unroll
        for (int b = 0; b < 4; b++)
            #pragma unroll
            for (int c = 0; c < 4; c++) acc[a][b][c] = 0.f;

    int m0 = blockIdx.y * 128, n0 = blockIdx.x * 128;
    mma_mainloop(acc, A, W, K, m0, n0, NTOK);

    __shared__ float red_m[4][128];
    __shared__ float red_s[4][128];
    int tid = threadIdx.x;
    int lane = tid & 31, wid = tid >> 5;
    int wm = wid >> 2, wn = wid & 3;
    int g = lane >> 2, tig = lane & 3;
    int colb = n0 + wn*32;

    #pragma unroll
    for (int mt = 0; mt < 4; mt++) {
        #pragma unroll
        for (int h = 0; h < 2; h++) {
            float m = -INFINITY;
            #pragma unroll
            for (int nt = 0; nt < 4; nt++) {
                int c = colb + nt*8 + 2*tig;
                if (c     < NTOK) m = fmaxf(m, acc[mt][nt][h*2+0]);
                if (c + 1 < NTOK) m = fmaxf(m, acc[mt][nt][h*2+1]);
            }
            m = fmaxf(m, __shfl_xor_sync(0xffffffffu, m, 1));
            m = fmaxf(m, __shfl_xor_sync(0xffffffffu, m, 2));
            float s = 0.f;
            #pragma unroll
            for (int nt = 0; nt < 4; nt++) {
                int c = colb + nt*8 + 2*tig;
                if (c     < NTOK) s += __expf(acc[mt][nt][h*2+0] - m);
                if (c + 1 < NTOK) s += __expf(acc[mt][nt][h*2+1] - m);
            }
            s += __shfl_xor_sync(0xffffffffu, s, 1);
            s += __shfl_xor_sync(0xffffffffu, s, 2);
            if (tig == 0) {
                int lr = wm*64 + mt*16 + h*8 + g;
                red_m[wn][lr] = m;
                red_s[wn][lr] = s;
            }
        }
    }
    __syncthreads();
    if (tid < 128) {
        float m0v = red_m[0][tid], m1v = red_m[1][tid];
        float m2v = red_m[2][tid], m3v = red_m[3][tid];
        float mx = fmaxf(fmaxf(m0v, m1v), fmaxf(m2v, m3v));
        float s = red_s[0][tid]*__expf(m0v-mx) + red_s[1][tid]*__expf(m1v-mx)
                + red_s[2][tid]*__expf(m2v-mx) + red_s[3][tid]*__expf(m3v-mx);
        int row = m0 + tid;
        g_pmax[(size_t)row*NBLK_V + blockIdx.x] = mx;
        g_psum[(size_t)row*NBLK_V + blockIdx.x] = s;
    }
}

__global__ void lse_reduce_kernel()
{
    int r = blockIdx.x, tid = threadIdx.x;
    __shared__ float red[128];
    float m = -INFINITY;
    for (int i = tid; i < NBLK_V; i += 128) m = fmaxf(m, g_pmax[(size_t)r*NBLK_V + i]);
    red[tid] = m; __syncthreads();
    for (int s = 64; s > 0; s >>= 1) { if (tid < s) red[tid] = fmaxf(red[tid], red[tid+s]); __syncthreads(); }
    float gm = red[0]; __syncthreads();
    double sum = 0.0;
    for (int i = tid; i < NBLK_V; i += 128)
        sum += (double)g_psum[(size_t)r*NBLK_V + i] * exp((double)g_pmax[(size_t)r*NBLK_V + i] - (double)gm);
    __shared__ double redd[128];
    redd[tid] = sum; __syncthreads();
    for (int s = 64; s > 0; s >>= 1) { if (tid < s) redd[tid] += redd[tid+s]; __syncthreads(); }
    if (tid == 0) g_lse[r] = gm + (float)log(redd[0]);
}

// ---------------- small-M GEMM ----------------
__global__ void rowdot_kernel(
    const float* __restrict__ A, long strideA,
    const float* __restrict__ W, const float* __restrict__ bias,
    float* __restrict__ C, long strideC,
    int M, int K, float alpha, int relu)
{
    int n = blockIdx.x;
    int tid = threadIdx.x;   // 128
    const float* w = W + (size_t)n * K;
    __shared__ float red[128];
    for (int m = 0; m < M; m++) {
        const float* a = A + (size_t)m * strideA;
        float s = 0.f;
        for (int k = tid; k < K; k += 128) s += a[k]*w[k];
        red[tid] = s; __syncthreads();
        for (int st = 64; st > 0; st >>= 1) { if (tid < st) red[tid] += red[tid+st]; __syncthreads(); }
        if (tid == 0) {
            float v = alpha*red[0] + (bias ? bias[n] : 0.f);
            if (relu) v = fmaxf(v, 0.f);
            C[(size_t)m*strideC + n] = v;
        }
        __syncthreads();
    }
}

// ---------------- attention, 8 queries per block ----------------
#define QT 8
__global__ __launch_bounds__(256) void attn8_kernel(
    const float* __restrict__ qkv, float* __restrict__ out)
{
    int qt = blockIdx.x, h = blockIdx.y, b = blockIdx.z;
    int tid = threadIdx.x;
    __shared__ float qs[QT][DHEAD];
    __shared__ float sc[QT][NSEQ];
    __shared__ float den[QT];
    const float* base = qkv + (size_t)b*NSEQ*QKV_LD;
    if (tid < 128) {
        int q = tid >> 4;
        int c = (tid & 15) * 4;
        *(float4*)&qs[q][c] =
            *(const float4*)(base + (size_t)(qt*QT+q)*QKV_LD + h*DHEAD + c);
    }
    __syncthreads();
    // scores: one thread per key
    {
        int j = tid;
        float4 kreg[16];
        const float4* kr = (const float4*)(base + (size_t)j*QKV_LD + D_MODEL + h*DHEAD);
        #pragma unroll
        for (int t = 0; t < 16; t++) kreg[t] = kr[t];
        #pragma unroll
        for (int q = 0; q < QT; q++) {
            float d = 0.f;
            #pragma unroll
            for (int t = 0; t < 16; t++) {
                float4 q4 = *(float4*)&qs[q][t*4];
                d += q4.x*kreg[t].x + q4.y*kreg[t].y + q4.z*kreg[t].z + q4.w*kreg[t].w;
            }
            sc[q][j] = d * 0.125f;
        }
    }
    __syncthreads();
    // softmax: warp w handles query w
    {
        int w = tid >> 5, lane = tid & 31;
        float v[8];
        float m = -INFINITY;
        #pragma unroll
        for (int t = 0; t < 8; t++) { v[t] = sc[w][lane + 32*t]; m = fmaxf(m, v[t]); }
        #pragma unroll
        for (int o = 16; o; o >>= 1) m = fmaxf(m, __shfl_xor_sync(0xffffffffu, m, o));
        float s = 0.f;
        #pragma unroll
        for (int t = 0; t < 8; t++) { v[t] = expf(v[t]-m); s += v[t]; }
        #pragma unroll
        for (int o = 16; o; o >>= 1) s += __shfl_xor_sync(0xffffffffu, s, o);
        #pragma unroll
        for (int t = 0; t < 8; t++) sc[w][lane + 32*t] = v[t];
        if (lane == 0) den[w] = s;
    }
    __syncthreads();
    // AV: d = tid&63, each thread two queries
    {
        int d = tid & 63, qp = tid >> 6;
        int q0 = qp*2, q1 = qp*2+1;
        const float* vb = base + 2*D_MODEL + h*DHEAD + d;
        float a0 = 0.f, a1 = 0.f;
        #pragma unroll 8
        for (int j = 0; j < NSEQ; j++) {
            float v = vb[(size_t)j*QKV_LD];
            a0 += sc[q0][j]*v;
            a1 += sc[q1][j]*v;
        }
        out[((size_t)(b*NSEQ + qt*QT + q0))*D_MODEL + h*DHEAD + d] = a0/den[q0];
        out[((size_t)(b*NSEQ + qt*QT + q1))*D_MODEL + h*DHEAD + d] = a1/den[q1];
    }
}

// ---------------- loc attention (single query per (h,b)) ----------------
__global__ __launch_bounds__(256) void attn_kernel(
    const float* __restrict__ qkv, float* __restrict__ out, int nq, int sq_base)
{
    int qi = blockIdx.x, h = blockIdx.y, b = blockIdx.z;
    int sq = sq_base + qi;
    int tid = threadIdx.x;
    __shared__ float4 qrow[DHEAD/4];
    __shared__ float sc[NSEQ];
    __shared__ float red[256];
    __shared__ float sden;
    __shared__ float osum[4][DHEAD];
    const float* base = qkv + (size_t)b * NSEQ * QKV_LD;
    if (tid < DHEAD/4)
        qrow[tid] = ((const float4*)(base + (size_t)sq*QKV_LD + h*DHEAD))[tid];
    __syncthreads();
    {
        const float4* krow = (const float4*)(base + (size_t)tid*QKV_LD + D_MODEL + h*DHEAD);
        float d = 0.f;
        #pragma unroll
        for (int t = 0; t < DHEAD/4; t++) {
            float4 k4 = krow[t];
            float4 q4 = qrow[t];
            d += q4.x*k4.x + q4.y*k4.y + q4.z*k4.z + q4.w*k4.w;
        }
        sc[tid] = d * 0.125f;
    }
    __syncthreads();
    red[tid] = sc[tid]; __syncthreads();
    for (int s = 128; s > 0; s >>= 1) { if (tid < s) red[tid] = fmaxf(red[tid], red[tid+s]); __syncthreads(); }
    float mx = red[0]; __syncthreads();
    float e = expf(sc[tid] - mx);
    red[tid] = e; __syncthreads();
    for (int s = 128; s > 0; s >>= 1) { if (tid < s) red[tid] += red[tid+s]; __syncthreads(); }
    if (tid == 0) sden = red[0];
    __syncthreads();
    sc[tid] = e;
    __syncthreads();
    int d = tid & 63, g = tid >> 6;
    const float* vb = base + 2*D_MODEL + h*DHEAD + d;
    float o = 0.f;
    for (int j = g*64; j < (g+1)*64; j++) o += sc[j] * vb[(size_t)j*QKV_LD];
    osum[g][d] = o; __syncthreads();
    if (tid < DHEAD) {
        float r = (osum[0][tid]+osum[1][tid]+osum[2][tid]+osum[3][tid]) / sden;
        out[((size_t)(b*nq + qi))*D_MODEL + h*DHEAD + tid] = r;
    }
}

// ---------------- residual + layernorm ----------------
__global__ void ln_kernel(
    const float* __restrict__ in1, long s1,
    const float* __restrict__ in2, long s2,
    float* __restrict__ out, long so,
    const float* __restrict__ gam, const float* __restrict__ bet)
{
    int r = blockIdx.x, tid = threadIdx.x;
    __shared__ float xr[D_MODEL];
    __shared__ float red[256];
    const float* p1 = in1 + (size_t)r*s1;
    const float* p2 = in2 + (size_t)r*s2;
    float ls = 0.f;
    for (int d = tid; d < D_MODEL; d += 256) { float v = p1[d]+p2[d]; xr[d] = v; ls += v; }
    red[tid] = ls; __syncthreads();
    for (int s = 128; s > 0; s >>= 1) { if (tid < s) red[tid] += red[tid+s]; __syncthreads(); }
    float mean = red[0] * (1.f/D_MODEL); __syncthreads();
    float lv = 0.f;
    for (int d = tid; d < D_MODEL; d += 256) { float t = xr[d]-mean; lv += t*t; }
    red[tid] = lv; __syncthreads();
    for (int s = 128; s > 0; s >>= 1) { if (tid < s) red[tid] += red[tid+s]; __syncthreads(); }
    float rstd = 1.f / sqrtf(red[0]*(1.f/D_MODEL) + 1e-5f);
    for (int d = tid; d < D_MODEL; d += 256)
        out[(size_t)r*so + d] = (xr[d]-mean)*rstd*gam[d] + bet[d];
}

// ---------------- gating statistics + top-k + softmax + importance ----------------
__global__ void stats_kernel(const float* __restrict__ w, const float* __restrict__ noise)
{
    __shared__ float tot[NEXP];
    __shared__ double redd[256];
    __shared__ float fv[256];
    __shared__ int   fi[256];
    __shared__ float topv[NKTOP];
    __shared__ double smean, sstd;
    int tid = threadIdx.x;
    double ls = 0.0;
    for (int n = tid; n < NEXP; n += 256) {
        float f = 0.25f*(w[n] + w[NEXP+n] + w[2*NEXP+n] + w[3*NEXP+n]);
        tot[n] = f; ls += (double)f;
    }
    redd[tid] = ls; __syncthreads();
    for (int s = 128; s > 0; s >>= 1) { if (tid < s) redd[tid] += redd[tid+s]; __syncthreads(); }
    if (tid == 0) smean = redd[0] / NEXP;
    __syncthreads();
    double mfm = smean;
    ls = 0.0;
    for (int n = tid; n < NEXP; n += 256) { double t = (double)tot[n]-mfm; ls += t*t; }
    redd[tid] = ls; __syncthreads();
    for (int s = 128; s > 0; s >>= 1) { if (tid < s) redd[tid] += redd[tid+s]; __syncthreads(); }
    if (tid == 0) sstd = sqrt(redd[0] / (NEXP-1));
    __syncthreads();
    float stdfm = (float)sstd;
    for (int n = tid; n < NEXP; n += 256) tot[n] = tot[n] + noise[n]*stdfm;
    __syncthreads();
    ls = 0.0;
    for (int n = tid; n < NEXP; n += 256) ls += (double)tot[n];
    redd[tid] = ls; __syncthreads();
    for (int s = 128; s > 0; s >>= 1) { if (tid < s) redd[tid] += redd[tid+s]; __syncthreads(); }
    if (tid == 0) smean = redd[0] / NEXP;
    __syncthreads();
    double mt = smean;
    ls = 0.0;
    for (int n = tid; n < NEXP; n += 256) { double t = (double)tot[n]-mt; ls += t*t; }
    redd[tid] = ls; __syncthreads();
    for (int s = 128; s > 0; s >>= 1) { if (tid < s) redd[tid] += redd[tid+s]; __syncthreads(); }
    if (tid == 0) {
        double st = sqrt(redd[0] / (NEXP-1));
        double ratio = st / mt;
        g_stats[20] = (float)(0.1 * ratio * ratio);
    }
    __syncthreads();
    for (int it = 0; it < NKTOP; it++) {
        float bv = -INFINITY; int bi = 0x7fffffff;
        for (int n = tid; n < NEXP; n += 256) {
            float v = tot[n];
            if (v > bv || (v == bv && n < bi)) { bv = v; bi = n; }
        }
        fv[tid] = bv; fi[tid] = bi; __syncthreads();
        for (int s = 128; s > 0; s >>= 1) {
            if (tid < s) {
                float v2 = fv[tid+s]; int i2 = fi[tid+s];
                if (v2 > fv[tid] || (v2 == fv[tid] && i2 < fi[tid])) { fv[tid] = v2; fi[tid] = i2; }
            }
            __syncthreads();
        }
        if (tid == 0) { topv[it] = fv[0]; tot[fi[0]] = -INFINITY; }
        __syncthreads();
    }
    if (tid == 0) {
        float m = topv[0];
        float s = 0.f;
        float e[NKTOP];
        for (int k = 0; k < NKTOP; k++) { e[k] = expf(topv[k]-m); s += e[k]; }
        for (int k = 0; k < NKTOP; k++) g_stats[k] = e[k]/s;
    }
}

// ---------------- response mixture ----------------
__global__ void mix_kernel(const float* __restrict__ responses)
{
    __shared__ float w[NKTOP];
    if (threadIdx.x < NKTOP) w[threadIdx.x] = g_stats[threadIdx.x];
    __syncthreads();
    int i = blockIdx.x*blockDim.x + threadIdx.x;
    if (i < (NROWS*D_MODEL)/4) {
        float4 s = make_float4(0.f, 0.f, 0.f, 0.f);
        #pragma unroll
        for (int k = 0; k < NKTOP; k++) {
            float4 v = ((const float4*)responses)[(size_t)k*((NROWS*D_MODEL)/4) + i];
            float wk = w[k];
            s.x += wk*v.x; s.y += wk*v.y; s.z += wk*v.z; s.w += wk*v.w;
        }
        ((float4*)g_x)[i] = s;
    }
}

// ---------------- label logit + final loss ----------------
__global__ void lablogit_kernel(const int* __restrict__ inputs, const float* __restrict__ dec_w)
{
    int s = blockIdx.x, b = blockIdx.y, tid = threadIdx.x;
    int lbl = inputs[b*NSEQ + s + 1];
    const float* a = g_x + ((size_t)(b*NSEQ + s))*D_MODEL;
    const float* wp = dec_w + (size_t)lbl*D_MODEL;
    __shared__ float red[128];
    float acc = 0.f;
    for (int k = tid; k < D_MODEL; k += 128) acc += a[k]*wp[k];
    red[tid] = acc; __syncthreads();
    for (int st = 64; st > 0; st >>= 1) { if (tid < st) red[tid] += red[tid+st]; __syncthreads(); }
    if (tid == 0) g_lab[b*(NSEQ-1)+s] = red[0];
}

__global__ void final_kernel(float* __restrict__ out)
{
    __shared__ double red[256];
    int tid = threadIdx.x;
    double s = 0.0;
    for (int i = tid; i < NB*(NSEQ-1); i += 256) {
        int b = i/(NSEQ-1), sp = i%(NSEQ-1);
        s += (double)g_lab[i] - (double)g_lse[b*NSEQ+sp];
    }
    red[tid] = s; __syncthreads();
    for (int st = 128; st > 0; st >>= 1) { if (tid < st) red[tid] += red[tid+st]; __syncthreads(); }
    if (tid == 0) {
        double ce = -red[0] / (double)(NB*(NSEQ-1));
        out[0] = (float)(ce + (double)g_stats[20]);
    }
}

// ---------------- host driver ----------------
extern "C" void kernel_launch(void* const* d_in, const int* in_sizes, int n_in,
                              void* d_out, int out_size)
{
    (void)in_sizes; (void)n_in; (void)out_size;
    const int*   inputs    = (const int*)  d_in[0];
    const float* responses = (const float*)d_in[1];
    const float* noise     = (const float*)d_in[2];
    const float* emb       = (const float*)d_in[3];
    const float* loc_Wqkv  = (const float*)d_in[4];
    const float* loc_bqkv  = (const float*)d_in[5];
    const float* loc_Wo    = (const float*)d_in[6];
    const float* loc_bo    = (const float*)d_in[7];
    const float* loc_ln1g  = (const float*)d_in[8];
    const float* loc_ln1b  = (const float*)d_in[9];
    const float* loc_W1    = (const float*)d_in[10];
    const float* loc_b1    = (const float*)d_in[11];
    const float* loc_W2    = (const float*)d_in[12];
    const float* loc_b2    = (const float*)d_in[13];
    const float* loc_ln2g  = (const float*)d_in[14];
    const float* loc_ln2b  = (const float*)d_in[15];
    const float* enc_Wqkv  = (const float*)d_in[16];
    const float* enc_bqkv  = (const float*)d_in[17];
    const float* enc_Wo    = (const float*)d_in[18];
    const float* enc_bo    = (const float*)d_in[19];
    const float* enc_ln1g  = (const float*)d_in[20];
    const float* enc_ln1b  = (const float*)d_in[21];
    const float* enc_W1    = (const float*)d_in[22];
    const float* enc_b1    = (const float*)d_in[23];
    const float* enc_W2    = (const float*)d_in[24];
    const float* enc_b2    = (const float*)d_in[25];
    const float* enc_ln2g  = (const float*)d_in[26];
    const float* enc_ln2b  = (const float*)d_in[27];
    const float* gate_w    = (const float*)d_in[28];
    const float* gate_b    = (const float*)d_in[29];
    const float* dec_w     = (const float*)d_in[30];
    float* out = (float*)d_out;

    float *p_x, *p_qkv, *p_attn, *p_tmp, *p_ffh;
    float *p_sm_attn, *p_sm_x, *p_sm_tmp, *p_sm_ctx, *p_sm_ffh;
    cudaGetSymbolAddress((void**)&p_x, g_x);
    cudaGetSymbolAddress((void**)&p_qkv, g_qkv);
    cudaGetSymbolAddress((void**)&p_attn, g_attn);
    cudaGetSymbolAddress((void**)&p_tmp, g_tmp);
    cudaGetSymbolAddress((void**)&p_ffh, g_ffh);
    cudaGetSymbolAddress((void**)&p_sm_attn, g_sm_attn);
    cudaGetSymbolAddress((void**)&p_sm_x, g_sm_x);
    cudaGetSymbolAddress((void**)&p_sm_tmp, g_sm_tmp);
    cudaGetSymbolAddress((void**)&p_sm_ctx, g_sm_ctx);
    cudaGetSymbolAddress((void**)&p_sm_ffh, g_sm_ffh);

    // 1) embed
    embed_kernel<<<NROWS, 256>>>(inputs, emb);

    // 2) loc layer (only last position needed downstream)
    gemm_tc_kernel<<<dim3(2048/128, NROWS/128), 256>>>(
        p_x, loc_Wqkv + (size_t)D_MODEL*D_MODEL, loc_bqkv + D_MODEL,
        p_qkv + D_MODEL, D_MODEL, QKV_LD, 0);
    rowdot_kernel<<<D_MODEL, 128>>>(
        p_x + (size_t)(NSEQ-1)*D_MODEL, (long)NSEQ*D_MODEL,
        loc_Wqkv, loc_bqkv,
        p_qkv + (size_t)(NSEQ-1)*QKV_LD, (long)NSEQ*QKV_LD,
        NB, D_MODEL, 1.f, 0);
    attn_kernel<<<dim3(1, NHEAD, NB), 256>>>(p_qkv, p_sm_attn, 1, NSEQ-1);
    rowdot_kernel<<<D_MODEL, 128>>>(p_sm_attn, D_MODEL, loc_Wo, loc_bo,
                                    p_sm_tmp, D_MODEL, NB, D_MODEL, 1.f, 0);
    ln_kernel<<<NB, 256>>>(p_x + (size_t)(NSEQ-1)*D_MODEL, (long)NSEQ*D_MODEL,
                           p_sm_tmp, D_MODEL, p_sm_x, D_MODEL, loc_ln1g, loc_ln1b);
    rowdot_kernel<<<FF_DIM, 128>>>(p_sm_x, D_MODEL, loc_W1, loc_b1,
                                   p_sm_ffh, FF_DIM, NB, D_MODEL, 1.f, 1);
    rowdot_kernel<<<D_MODEL, 128>>>(p_sm_ffh, FF_DIM, loc_W2, loc_b2,
                                    p_sm_tmp, D_MODEL, NB, FF_DIM, 1.f, 0);
    ln_kernel<<<NB, 256>>>(p_sm_x, D_MODEL, p_sm_tmp, D_MODEL,
                           p_sm_ctx, D_MODEL, loc_ln2g, loc_ln2b);

    // 3) gate weights (sqrt(D)=32 folded in)
    rowdot_kernel<<<NEXP, 128>>>(p_sm_ctx, D_MODEL, gate_w, gate_b,
                                 out + 1, NEXP, NB, D_MODEL, 32.f, 0);

    // 4) stats / top-k / softmax / importance
    stats_kernel<<<1, 256>>>(out + 1, noise);

    // 5) mixture of responses -> g_x
    mix_kernel<<<(NROWS*D_MODEL/4 + 255)/256, 256>>>(responses);

    // 6) two encoder layers
    for (int l = 0; l < 2; l++) {
        const float* Wqkv = enc_Wqkv + (size_t)l*3*D_MODEL*D_MODEL;
        const float* bqkv = enc_bqkv + (size_t)l*3*D_MODEL;
        const float* Wo   = enc_Wo   + (size_t)l*D_MODEL*D_MODEL;
        const float* bo   = enc_bo   + (size_t)l*D_MODEL;
        const float* g1   = enc_ln1g + (size_t)l*D_MODEL;
        const float* b1l  = enc_ln1b + (size_t)l*D_MODEL;
        const float* W1   = enc_W1   + (size_t)l*FF_DIM*D_MODEL;
        const float* bb1  = enc_b1   + (size_t)l*FF_DIM;
        const float* W2   = enc_W2   + (size_t)l*D_MODEL*FF_DIM;
        const float* bb2  = enc_b2   + (size_t)l*D_MODEL;
        const float* g2   = enc_ln2g + (size_t)l*D_MODEL;
        const float* b2l  = enc_ln2b + (size_t)l*D_MODEL;

        gemm_tc_kernel<<<dim3(QKV_LD/128, NROWS/128), 256>>>(p_x, Wqkv, bqkv, p_qkv, D_MODEL, QKV_LD, 0);
        attn8_kernel<<<dim3(NSEQ/QT, NHEAD, NB), 256>>>(p_qkv, p_attn);
        gemm_tc_kernel<<<dim3(D_MODEL/128, NROWS/128), 256>>>(p_attn, Wo, bo, p_tmp, D_MODEL, D_MODEL, 0);
        ln_kernel<<<NROWS, 256>>>(p_x, D_MODEL, p_tmp, D_MODEL, p_x, D_MODEL, g1, b1l);
        gemm_tc_kernel<<<dim3(FF_DIM/128, NROWS/128), 256>>>(p_x, W1, bb1, p_ffh, D_MODEL, FF_DIM, 1);
        gemm_tc_kernel<<<dim3(D_MODEL/128, NROWS/128), 256>>>(p_ffh, W2, bb2, p_tmp, FF_DIM, D_MODEL, 0);
        ln_kernel<<<NROWS, 256>>>(p_x, D_MODEL, p_tmp, D_MODEL, p_x, D_MODEL, g2, b2l);
    }

    // 7) fused decoder GEMM + logsumexp, label logits, CE + importance
    gemm_lse_tc_kernel<<<dim3(NBLK_V, NROWS/128), 256>>>(p_x, dec_w, D_MODEL);
    lse_reduce_kernel<<<NROWS, 128>>>();
    lablogit_kernel<<<dim3(NSEQ-1, NB), 128>>>(inputs, dec_w);
    final_kernel<<<1, 256>>>(out);
}

// round 4
// speedup vs baseline: 6.2930x; 1.4921x over previous
#include <cuda_runtime.h>
#include <cuda_bf16.h>
#include <math.h>
#include <stdint.h>

// ---------------- problem constants ----------------
#define D_MODEL 1024
#define NHEAD   16
#define DHEAD   64
#define FF_DIM  4096
#define NSEQ    256
#define NB      4
#define NTOK    50257
#define NEXP    2000
#define NKTOP   20
#define NROWS   (NB*NSEQ)      // 1024
#define QKV_LD  3072
#define NBLK_V  393            // ceil(50257/128)

// ---------------- scratch (static device memory; no allocation) ----------------
__device__ float g_x    [NROWS*D_MODEL];
__device__ float g_qkv  [NROWS*QKV_LD];
__device__ float g_tmp  [NROWS*D_MODEL];
__device__ float g_sm_attn[NB*D_MODEL];
__device__ float g_sm_x   [NB*D_MODEL];
__device__ float g_sm_tmp [NB*D_MODEL];
__device__ float g_sm_ctx [NB*D_MODEL];
__device__ float g_sm_ffh [NB*FF_DIM];
__device__ float g_pmax[NROWS*NBLK_V];
__device__ float g_psum[NROWS*NBLK_V];
__device__ float g_lse [NROWS];
__device__ float g_lab [NB*(NSEQ-1)];
__device__ float g_stats[32];   // [0..19] jw, [20] imp

// bf16 weight/activation mirrors
__device__ __align__(256) __nv_bfloat16 h_dec [NTOK*D_MODEL];
__device__ __align__(256) __nv_bfloat16 h_Wqkv[2*QKV_LD*D_MODEL];
__device__ __align__(256) __nv_bfloat16 h_Wo  [2*D_MODEL*D_MODEL];
__device__ __align__(256) __nv_bfloat16 h_W1  [2*FF_DIM*D_MODEL];
__device__ __align__(256) __nv_bfloat16 h_W2  [2*D_MODEL*FF_DIM];
__device__ __align__(256) __nv_bfloat16 h_x   [NROWS*D_MODEL];
__device__ __align__(256) __nv_bfloat16 h_attn[NROWS*D_MODEL];
__device__ __align__(256) __nv_bfloat16 h_ffh [NROWS*FF_DIM];

// ---------------- fp32 -> bf16 conversion ----------------
__global__ void f2h_kernel(const float* __restrict__ src, __nv_bfloat16* __restrict__ dst, int n4)
{
    int i = blockIdx.x*blockDim.x + threadIdx.x;
    if (i < n4) {
        float4 v = ((const float4*)src)[i];
        ((__nv_bfloat162*)dst)[2*i+0] = __floats2bfloat162_rn(v.x, v.y);
        ((__nv_bfloat162*)dst)[2*i+1] = __floats2bfloat162_rn(v.z, v.w);
    }
}

// ---------------- embedding gather ----------------
__global__ void embed_kernel(const int* __restrict__ inputs, const float* __restrict__ emb)
{
    int r = blockIdx.x;
    int tok = inputs[r];
    const float4* src = (const float4*)(emb + (size_t)tok * D_MODEL);
    float4* dst = (float4*)(g_x + (size_t)r * D_MODEL);
    dst[threadIdx.x] = src[threadIdx.x];
}

// ================= cp.async helpers =================
__device__ __forceinline__ void cp_async16(void* smem, const void* gmem)
{
    uint32_t s = (uint32_t)__cvta_generic_to_shared(smem);
    asm volatile("cp.async.ca.shared.global [%0], [%1], 16;\n" :: "r"(s), "l"(gmem));
}
__device__ __forceinline__ void cp_commit()
{
    asm volatile("cp.async.commit_group;\n" ::: "memory");
}
template<int N> __device__ __forceinline__ void cp_wait()
{
    asm volatile("cp.async.wait_group %0;\n" :: "n"(N) : "memory");
}

// ================= tf32 GEMM (loc KV path only; weights-output precision) =========
__device__ __forceinline__ void mma_mainloop(
    float acc[4][4][4],
    const float* __restrict__ A, const float* __restrict__ W,
    int K, int m0, int n0)
{
    __shared__ uint32_t As[2][128][20];
    __shared__ uint32_t Bs[2][128][20];
    int tid  = threadIdx.x;
    int lane = tid & 31, wid = tid >> 5;
    int wm = wid >> 2, wn = wid & 3;
    int g = lane >> 2, tig = lane & 3;

    int r0c = tid >> 2,         c0c = (tid & 3) << 2;
    int r1c = (tid + 256) >> 2, c1c = (tid & 3) << 2;
    const float* pa0 = A + (size_t)(m0 + r0c)*K + c0c;
    const float* pa1 = A + (size_t)(m0 + r1c)*K + c1c;
    const float* pb0 = W + (size_t)(n0 + r0c)*K + c0c;
    const float* pb1 = W + (size_t)(n0 + r1c)*K + c1c;

    int niter = K >> 4;
    cp_async16(&As[0][r0c][c0c], pa0);
    cp_async16(&As[0][r1c][c1c], pa1);
    cp_async16(&Bs[0][r0c][c0c], pb0);
    cp_async16(&Bs[0][r1c][c1c], pb1);
    cp_commit();

    for (int it = 0; it < niter; it++) {
        int st = it & 1;
        if (it + 1 < niter) {
            int off = (it + 1) << 4;
            int sn = st ^ 1;
            cp_async16(&As[sn][r0c][c0c], pa0 + off);
            cp_async16(&As[sn][r1c][c1c], pa1 + off);
            cp_async16(&Bs[sn][r0c][c0c], pb0 + off);
            cp_async16(&Bs[sn][r1c][c1c], pb1 + off);
            cp_commit();
            cp_wait<1>();
        } else {
            cp_wait<0>();
        }
        __syncthreads();
        #pragma unroll
        for (int ks = 0; ks < 16; ks += 8) {
            uint32_t af[4][4], bf[4][2];
            #pragma unroll
            for (int mt = 0; mt < 4; mt++) {
                int r0 = wm*64 + mt*16;
                af[mt][0] = As[st][r0+g  ][ks+tig  ];
                af[mt][1] = As[st][r0+g+8][ks+tig  ];
                af[mt][2] = As[st][r0+g  ][ks+tig+4];
                af[mt][3] = As[st][r0+g+8][ks+tig+4];
            }
            #pragma unroll
            for (int nt = 0; nt < 4; nt++) {
                int c0 = wn*32 + nt*8;
                bf[nt][0] = Bs[st][c0+g][ks+tig  ];
                bf[nt][1] = Bs[st][c0+g][ks+tig+4];
            }
            #pragma unroll
            for (int mt = 0; mt < 4; mt++)
                #pragma unroll
                for (int nt = 0; nt < 4; nt++) {
                    asm volatile(
                        "mma.sync.aligned.m16n8k8.row.col.f32.tf32.tf32.f32 "
                        "{%0,%1,%2,%3}, {%4,%5,%6,%7}, {%8,%9}, {%0,%1,%2,%3};\n"
                        : "+f"(acc[mt][nt][0]), "+f"(acc[mt][nt][1]),
                          "+f"(acc[mt][nt][2]), "+f"(acc[mt][nt][3])
                        : "r"(af[mt][0]), "r"(af[mt][1]),
                          "r"(af[mt][2]), "r"(af[mt][3]),
                          "r"(bf[nt][0]), "r"(bf[nt][1]));
                }
        }
        __syncthreads();
    }
}

__global__ __launch_bounds__(256, 2) void gemm_tc_kernel(
    const float* __restrict__ A, const float* __restrict__ W,
    const float* __restrict__ bias, float* __restrict__ C,
    int K, int ldC)
{
    float acc[4][4][4];
    #pragma unroll
    for (int a = 0; a < 4; a++)
        #pragma unroll
        for (int b = 0; b < 4; b++)
            #pragma unroll
            for (int c = 0; c < 4; c++) acc[a][b][c] = 0.f;

    int m0 = blockIdx.y * 128, n0 = blockIdx.x * 128;
    mma_mainloop(acc, A, W, K, m0, n0);

    int tid = threadIdx.x;
    int lane = tid & 31, wid = tid >> 5;
    int wm = wid >> 2, wn = wid & 3;
    int g = lane >> 2, tig = lane & 3;
    int rowb = m0 + wm*64;
    int colb = n0 + wn*32;
    #pragma unroll
    for (int nt = 0; nt < 4; nt++) {
        int c = colb + nt*8 + 2*tig;
        float b0 = bias[c], b1 = bias[c+1];
        #pragma unroll
        for (int mt = 0; mt < 4; mt++) {
            int r = rowb + mt*16 + g;
            *(float2*)(C + (size_t)r*ldC + c)     = make_float2(acc[mt][nt][0]+b0, acc[mt][nt][1]+b1);
            *(float2*)(C + (size_t)(r+8)*ldC + c) = make_float2(acc[mt][nt][2]+b0, acc[mt][nt][3]+b1);
        }
    }
}

// ================= bf16 GEMM core (m16n8k16), BK=32 =================
__device__ __forceinline__ void mma_bf16_mainloop(
    float acc[4][4][4],
    const __nv_bfloat16* __restrict__ A, const __nv_bfloat16* __restrict__ W,
    int K, int m0, int n0, int nmax)
{
    __shared__ uint32_t As[2][128][20];   // 16 used words = 32 bf16, pad 4
    __shared__ uint32_t Bs[2][128][20];
    int tid  = threadIdx.x;
    int lane = tid & 31, wid = tid >> 5;
    int wm = wid >> 2, wn = wid & 3;
    int g = lane >> 2, tig = lane & 3;

    int r0c = tid >> 2, r1c = r0c + 64;
    int cw = (tid & 3) * 4;   // word col
    int ce = (tid & 3) * 8;   // element col
    int nr0 = n0 + r0c; nr0 = (nr0 < nmax) ? nr0 : (nmax - 1);
    int nr1 = n0 + r1c; nr1 = (nr1 < nmax) ? nr1 : (nmax - 1);
    const __nv_bfloat16* pa0 = A + (size_t)(m0 + r0c)*K + ce;
    const __nv_bfloat16* pa1 = A + (size_t)(m0 + r1c)*K + ce;
    const __nv_bfloat16* pb0 = W + (size_t)nr0*K + ce;
    const __nv_bfloat16* pb1 = W + (size_t)nr1*K + ce;

    int niter = K >> 5;
    cp_async16(&As[0][r0c][cw], pa0);
    cp_async16(&As[0][r1c][cw], pa1);
    cp_async16(&Bs[0][r0c][cw], pb0);
    cp_async16(&Bs[0][r1c][cw], pb1);
    cp_commit();

    for (int it = 0; it < niter; it++) {
        int st = it & 1;
        if (it + 1 < niter) {
            int off = (it + 1) << 5;
            int sn = st ^ 1;
            cp_async16(&As[sn][r0c][cw], pa0 + off);
            cp_async16(&As[sn][r1c][cw], pa1 + off);
            cp_async16(&Bs[sn][r0c][cw], pb0 + off);
            cp_async16(&Bs[sn][r1c][cw], pb1 + off);
            cp_commit();
            cp_wait<1>();
        } else {
            cp_wait<0>();
        }
        __syncthreads();
        #pragma unroll
        for (int ks = 0; ks < 2; ks++) {
            int kb = ks*8;
            uint32_t af[4][4], bf[4][2];
            #pragma unroll
            for (int mt = 0; mt < 4; mt++) {
                int r0 = wm*64 + mt*16;
                af[mt][0] = As[st][r0+g  ][kb+tig  ];
                af[mt][1] = As[st][r0+g+8][kb+tig  ];
                af[mt][2] = As[st][r0+g  ][kb+tig+4];
                af[mt][3] = As[st][r0+g+8][kb+tig+4];
            }
            #pragma unroll
            for (int nt = 0; nt < 4; nt++) {
                int c0 = wn*32 + nt*8;
                bf[nt][0] = Bs[st][c0+g][kb+tig  ];
                bf[nt][1] = Bs[st][c0+g][kb+tig+4];
            }
            #pragma unroll
            for (int mt = 0; mt < 4; mt++)
                #pragma unroll
                for (int nt = 0; nt < 4; nt++) {
                    asm volatile(
                        "mma.sync.aligned.m16n8k16.row.col.f32.bf16.bf16.f32 "
                        "{%0,%1,%2,%3}, {%4,%5,%6,%7}, {%8,%9}, {%0,%1,%2,%3};\n"
                        : "+f"(acc[mt][nt][0]), "+f"(acc[mt][nt][1]),
                          "+f"(acc[mt][nt][2]), "+f"(acc[mt][nt][3])
                        : "r"(af[mt][0]), "r"(af[mt][1]),
                          "r"(af[mt][2]), "r"(af[mt][3]),
                          "r"(bf[nt][0]), "r"(bf[nt][1]));
                }
        }
        __syncthreads();
    }
}

// bf16 GEMM -> fp32 out (+bias)
__global__ __launch_bounds__(256, 2) void gemm_bf_f32_kernel(
    const __nv_bfloat16* __restrict__ A, const __nv_bfloat16* __restrict__ W,
    const float* __restrict__ bias, float* __restrict__ C, int K, int ldC)
{
    float acc[4][4][4];
    #pragma unroll
    for (int a = 0; a < 4; a++)
        #pragma unroll
        for (int b = 0; b < 4; b++)
            #pragma unroll
            for (int c = 0; c < 4; c++) acc[a][b][c] = 0.f;
    int m0 = blockIdx.y * 128, n0 = blockIdx.x * 128;
    mma_bf16_mainloop(acc, A, W, K, m0, n0, 0x40000000);

    int tid = threadIdx.x;
    int lane = tid & 31, wid = tid >> 5;
    int wm = wid >> 2, wn = wid & 3;
    int g = lane >> 2, tig = lane & 3;
    int rowb = m0 + wm*64, colb = n0 + wn*32;
    #pragma unroll
    for (int nt = 0; nt < 4; nt++) {
        int c = colb + nt*8 + 2*tig;
        float b0 = bias[c], b1 = bias[c+1];
        #pragma unroll
        for (int mt = 0; mt < 4; mt++) {
            int r = rowb + mt*16 + g;
            *(float2*)(C + (size_t)r*ldC + c)     = make_float2(acc[mt][nt][0]+b0, acc[mt][nt][1]+b1);
            *(float2*)(C + (size_t)(r+8)*ldC + c) = make_float2(acc[mt][nt][2]+b0, acc[mt][nt][3]+b1);
        }
    }
}

// bf16 GEMM -> bf16 out (+bias, +relu)  (FF1 path)
__global__ __launch_bounds__(256, 2) void gemm_bf_bf_relu_kernel(
    const __nv_bfloat16* __restrict__ A, const __nv_bfloat16* __restrict__ W,
    const float* __restrict__ bias, __nv_bfloat16* __restrict__ C, int K, int ldC)
{
    float acc[4][4][4];
    #pragma unroll
    for (int a = 0; a < 4; a++)
        #pragma unroll
        for (int b = 0; b < 4; b++)
            #pragma unroll
            for (int c = 0; c < 4; c++) acc[a][b][c] = 0.f;
    int m0 = blockIdx.y * 128, n0 = blockIdx.x * 128;
    mma_bf16_mainloop(acc, A, W, K, m0, n0, 0x40000000);

    int tid = threadIdx.x;
    int lane = tid & 31, wid = tid >> 5;
    int wm = wid >> 2, wn = wid & 3;
    int g = lane >> 2, tig = lane & 3;
    int rowb = m0 + wm*64, colb = n0 + wn*32;
    #pragma unroll
    for (int nt = 0; nt < 4; nt++) {
        int c = colb + nt*8 + 2*tig;
        float b0 = bias[c], b1 = bias[c+1];
        #pragma unroll
        for (int mt = 0; mt < 4; mt++) {
            int r = rowb + mt*16 + g;
            float v0 = fmaxf(acc[mt][nt][0]+b0, 0.f);
            float v1 = fmaxf(acc[mt][nt][1]+b1, 0.f);
            float v2 = fmaxf(acc[mt][nt][2]+b0, 0.f);
            float v3 = fmaxf(acc[mt][nt][3]+b1, 0.f);
            *(__nv_bfloat162*)(C + (size_t)r*ldC + c)     = __floats2bfloat162_rn(v0, v1);
            *(__nv_bfloat162*)(C + (size_t)(r+8)*ldC + c) = __floats2bfloat162_rn(v2, v3);
        }
    }
}

// decoder bf16 GEMM + fused per-tile online logsumexp partials
__global__ __launch_bounds__(256, 2) void gemm_lse_bf_kernel(
    const __nv_bfloat16* __restrict__ A, const __nv_bfloat16* __restrict__ W, int K)
{
    float acc[4][4][4];
    #pragma unroll
    for (int a = 0; a < 4; a++)
        #pragma unroll
        for (int b = 0; b < 4; b++)
            #pragma unroll
            for (int c = 0; c < 4; c++) acc[a][b][c] = 0.f;
    int m0 = blockIdx.y * 128, n0 = blockIdx.x * 128;
    mma_bf16_mainloop(acc, A, W, K, m0, n0, NTOK);

    __shared__ float red_m[4][128];
    __shared__ float red_s[4][128];
    int tid = threadIdx.x;
    int lane = tid & 31, wid = tid >> 5;
    int wm = wid >> 2, wn = wid & 3;
    int g = lane >> 2, tig = lane & 3;
    int colb = n0 + wn*32;

    #pragma unroll
    for (int mt = 0; mt < 4; mt++) {
        #pragma unroll
        for (int h = 0; h < 2; h++) {
            float m = -INFINITY;
            #pragma unroll
            for (int nt = 0; nt < 4; nt++) {
                int c = colb + nt*8 + 2*tig;
                if (c     < NTOK) m = fmaxf(m, acc[mt][nt][h*2+0]);
                if (c + 1 < NTOK) m = fmaxf(m, acc[mt][nt][h*2+1]);
            }
            m = fmaxf(m, __shfl_xor_sync(0xffffffffu, m, 1));
            m = fmaxf(m, __shfl_xor_sync(0xffffffffu, m, 2));
            float s = 0.f;
            #pragma unroll
            for (int nt = 0; nt < 4; nt++) {
                int c = colb + nt*8 + 2*tig;
                if (c     < NTOK) s += __expf(acc[mt][nt][h*2+0] - m);
                if (c + 1 < NTOK) s += __expf(acc[mt][nt][h*2+1] - m);
            }
            s += __shfl_xor_sync(0xffffffffu, s, 1);
            s += __shfl_xor_sync(0xffffffffu, s, 2);
            if (tig == 0) {
                int lr = wm*64 + mt*16 + h*8 + g;
                red_m[wn][lr] = m;
                red_s[wn][lr] = s;
            }
        }
    }
    __syncthreads();
    if (tid < 128) {
        float m0v = red_m[0][tid], m1v = red_m[1][tid];
        float m2v = red_m[2][tid], m3v = red_m[3][tid];
        float mx = fmaxf(fmaxf(m0v, m1v), fmaxf(m2v, m3v));
        float s = red_s[0][tid]*__expf(m0v-mx) + red_s[1][tid]*__expf(m1v-mx)
                + red_s[2][tid]*__expf(m2v-mx) + red_s[3][tid]*__expf(m3v-mx);
        int row = m0 + tid;
        g_pmax[(size_t)row*NBLK_V + blockIdx.x] = mx;
        g_psum[(size_t)row*NBLK_V + blockIdx.x] = s;
    }
}

__global__ void lse_reduce_kernel()
{
    int r = blockIdx.x, tid = threadIdx.x;
    __shared__ float red[128];
    float m = -INFINITY;
    for (int i = tid; i < NBLK_V; i += 128) m = fmaxf(m, g_pmax[(size_t)r*NBLK_V + i]);
    red[tid] = m; __syncthreads();
    for (int s = 64; s > 0; s >>= 1) { if (tid < s) red[tid] = fmaxf(red[tid], red[tid+s]); __syncthreads(); }
    float gm = red[0]; __syncthreads();
    double sum = 0.0;
    for (int i = tid; i < NBLK_V; i += 128)
        sum += (double)g_psum[(size_t)r*NBLK_V + i] * exp((double)g_pmax[(size_t)r*NBLK_V + i] - (double)gm);
    __shared__ double redd[128];
    redd[tid] = sum; __syncthreads();
    for (int s = 64; s > 0; s >>= 1) { if (tid < s) redd[tid] += redd[tid+s]; __syncthreads(); }
    if (tid == 0) g_lse[r] = gm + (float)log(redd[0]);
}

// ---------------- small-M GEMM ----------------
__global__ void rowdot_kernel(
    const float* __restrict__ A, long strideA,
    const float* __restrict__ W, const float* __restrict__ bias,
    float* __restrict__ C, long strideC,
    int M, int K, float alpha, int relu)
{
    int n = blockIdx.x;
    int tid = threadIdx.x;   // 128
    const float* w = W + (size_t)n * K;
    __shared__ float red[128];
    for (int m = 0; m < M; m++) {
        const float* a = A + (size_t)m * strideA;
        float s = 0.f;
        for (int k = tid; k < K; k += 128) s += a[k]*w[k];
        red[tid] = s; __syncthreads();
        for (int st = 64; st > 0; st >>= 1) { if (tid < st) red[tid] += red[tid+st]; __syncthreads(); }
        if (tid == 0) {
            float v = alpha*red[0] + (bias ? bias[n] : 0.f);
            if (relu) v = fmaxf(v, 0.f);
            C[(size_t)m*strideC + n] = v;
        }
        __syncthreads();
    }
}

// ---------------- attention, 8 queries per block, bf16 out ----------------
#define QT 8
__global__ __launch_bounds__(256) void attn8_kernel(
    const float* __restrict__ qkv, __nv_bfloat16* __restrict__ out)
{
    int qt = blockIdx.x, h = blockIdx.y, b = blockIdx.z;
    int tid = threadIdx.x;
    __shared__ float qs[QT][DHEAD];
    __shared__ float sc[QT][NSEQ];
    __shared__ float den[QT];
    const float* base = qkv + (size_t)b*NSEQ*QKV_LD;
    if (tid < 128) {
        int q = tid >> 4;
        int c = (tid & 15) * 4;
        *(float4*)&qs[q][c] =
            *(const float4*)(base + (size_t)(qt*QT+q)*QKV_LD + h*DHEAD + c);
    }
    __syncthreads();
    {
        int j = tid;
        float4 kreg[16];
        const float4* kr = (const float4*)(base + (size_t)j*QKV_LD + D_MODEL + h*DHEAD);
        #pragma unroll
        for (int t = 0; t < 16; t++) kreg[t] = kr[t];
        #pragma unroll
        for (int q = 0; q < QT; q++) {
            float d = 0.f;
            #pragma unroll
            for (int t = 0; t < 16; t++) {
                float4 q4 = *(float4*)&qs[q][t*4];
                d += q4.x*kreg[t].x + q4.y*kreg[t].y + q4.z*kreg[t].z + q4.w*kreg[t].w;
            }
            sc[q][j] = d * 0.125f;
        }
    }
    __syncthreads();
    {
        int w = tid >> 5, lane = tid & 31;
        float v[8];
        float m = -INFINITY;
        #pragma unroll
        for (int t = 0; t < 8; t++) { v[t] = sc[w][lane + 32*t]; m = fmaxf(m, v[t]); }
        #pragma unroll
        for (int o = 16; o; o >>= 1) m = fmaxf(m, __shfl_xor_sync(0xffffffffu, m, o));
        float s = 0.f;
        #pragma unroll
        for (int t = 0; t < 8; t++) { v[t] = expf(v[t]-m); s += v[t]; }
        #pragma unroll
        for (int o = 16; o; o >>= 1) s += __shfl_xor_sync(0xffffffffu, s, o);
        #pragma unroll
        for (int t = 0; t < 8; t++) sc[w][lane + 32*t] = v[t];
        if (lane == 0) den[w] = s;
    }
    __syncthreads();
    {
        int d = tid & 63, qp = tid >> 6;
        int q0 = qp*2, q1 = qp*2+1;
        const float* vb = base + 2*D_MODEL + h*DHEAD + d;
        float a0 = 0.f, a1 = 0.f;
        #pragma unroll 8
        for (int j = 0; j < NSEQ; j++) {
            float v = vb[(size_t)j*QKV_LD];
            a0 += sc[q0][j]*v;
            a1 += sc[q1][j]*v;
        }
        out[((size_t)(b*NSEQ + qt*QT + q0))*D_MODEL + h*DHEAD + d] = __float2bfloat16(a0/den[q0]);
        out[((size_t)(b*NSEQ + qt*QT + q1))*D_MODEL + h*DHEAD + d] = __float2bfloat16(a1/den[q1]);
    }
}

// ---------------- loc attention (single query per (h,b)), fp32 out ----------------
__global__ __launch_bounds__(256) void attn_kernel(
    const float* __restrict__ qkv, float* __restrict__ out, int nq, int sq_base)
{
    int qi = blockIdx.x, h = blockIdx.y, b = blockIdx.z;
    int sq = sq_base + qi;
    int tid = threadIdx.x;
    __shared__ float4 qrow[DHEAD/4];
    __shared__ float sc[NSEQ];
    __shared__ float red[256];
    __shared__ float sden;
    __shared__ float osum[4][DHEAD];
    const float* base = qkv + (size_t)b * NSEQ * QKV_LD;
    if (tid < DHEAD/4)
        qrow[tid] = ((const float4*)(base + (size_t)sq*QKV_LD + h*DHEAD))[tid];
    __syncthreads();
    {
        const float4* krow = (const float4*)(base + (size_t)tid*QKV_LD + D_MODEL + h*DHEAD);
        float d = 0.f;
        #pragma unroll
        for (int t = 0; t < DHEAD/4; t++) {
            float4 k4 = krow[t];
            float4 q4 = qrow[t];
            d += q4.x*k4.x + q4.y*k4.y + q4.z*k4.z + q4.w*k4.w;
        }
        sc[tid] = d * 0.125f;
    }
    __syncthreads();
    red[tid] = sc[tid]; __syncthreads();
    for (int s = 128; s > 0; s >>= 1) { if (tid < s) red[tid] = fmaxf(red[tid], red[tid+s]); __syncthreads(); }
    float mx = red[0]; __syncthreads();
    float e = expf(sc[tid] - mx);
    red[tid] = e; __syncthreads();
    for (int s = 128; s > 0; s >>= 1) { if (tid < s) red[tid] += red[tid+s]; __syncthreads(); }
    if (tid == 0) sden = red[0];
    __syncthreads();
    sc[tid] = e;
    __syncthreads();
    int d = tid & 63, g = tid >> 6;
    const float* vb = base + 2*D_MODEL + h*DHEAD + d;
    float o = 0.f;
    for (int j = g*64; j < (g+1)*64; j++) o += sc[j] * vb[(size_t)j*QKV_LD];
    osum[g][d] = o; __syncthreads();
    if (tid < DHEAD) {
        float r = (osum[0][tid]+osum[1][tid]+osum[2][tid]+osum[3][tid]) / sden;
        out[((size_t)(b*nq + qi))*D_MODEL + h*DHEAD + tid] = r;
    }
}

// ---------------- residual + layernorm (fp32 out + optional bf16 mirror) ----------
__global__ void ln_kernel(
    const float* __restrict__ in1, long s1,
    const float* __restrict__ in2, long s2,
    float* __restrict__ out, long so,
    __nv_bfloat16* __restrict__ outh,
    const float* __restrict__ gam, const float* __restrict__ bet)
{
    int r = blockIdx.x, tid = threadIdx.x;
    __shared__ float xr[D_MODEL];
    __shared__ float red[256];
    const float* p1 = in1 + (size_t)r*s1;
    const float* p2 = in2 + (size_t)r*s2;
    float ls = 0.f;
    for (int d = tid; d < D_MODEL; d += 256) { float v = p1[d]+p2[d]; xr[d] = v; ls += v; }
    red[tid] = ls; __syncthreads();
    for (int s = 128; s > 0; s >>= 1) { if (tid < s) red[tid] += red[tid+s]; __syncthreads(); }
    float mean = red[0] * (1.f/D_MODEL); __syncthreads();
    float lv = 0.f;
    for (int d = tid; d < D_MODEL; d += 256) { float t = xr[d]-mean; lv += t*t; }
    red[tid] = lv; __syncthreads();
    for (int s = 128; s > 0; s >>= 1) { if (tid < s) red[tid] += red[tid+s]; __syncthreads(); }
    float rstd = 1.f / sqrtf(red[0]*(1.f/D_MODEL) + 1e-5f);
    for (int d = tid; d < D_MODEL; d += 256) {
        float v = (xr[d]-mean)*rstd*gam[d] + bet[d];
        out[(size_t)r*so + d] = v;
        if (outh) outh[(size_t)r*D_MODEL + d] = __float2bfloat16(v);
    }
}

// ---------------- gating statistics + top-k + softmax + importance ----------------
__global__ void stats_kernel(const float* __restrict__ w, const float* __restrict__ noise)
{
    __shared__ float tot[NEXP];
    __shared__ double redd[256];
    __shared__ float fv[256];
    __shared__ int   fi[256];
    __shared__ float topv[NKTOP];
    __shared__ double smean, sstd;
    int tid = threadIdx.x;
    double ls = 0.0;
    for (int n = tid; n < NEXP; n += 256) {
        float f = 0.25f*(w[n] + w[NEXP+n] + w[2*NEXP+n] + w[3*NEXP+n]);
        tot[n] = f; ls += (double)f;
    }
    redd[tid] = ls; __syncthreads();
    for (int s = 128; s > 0; s >>= 1) { if (tid < s) redd[tid] += redd[tid+s]; __syncthreads(); }
    if (tid == 0) smean = redd[0] / NEXP;
    __syncthreads();
    double mfm = smean;
    ls = 0.0;
    for (int n = tid; n < NEXP; n += 256) { double t = (double)tot[n]-mfm; ls += t*t; }
    redd[tid] = ls; __syncthreads();
    for (int s = 128; s > 0; s >>= 1) { if (tid < s) redd[tid] += redd[tid+s]; __syncthreads(); }
    if (tid == 0) sstd = sqrt(redd[0] / (NEXP-1));
    __syncthreads();
    float stdfm = (float)sstd;
    for (int n = tid; n < NEXP; n += 256) tot[n] = tot[n] + noise[n]*stdfm;
    __syncthreads();
    ls = 0.0;
    for (int n = tid; n < NEXP; n += 256) ls += (double)tot[n];
    redd[tid] = ls; __syncthreads();
    for (int s = 128; s > 0; s >>= 1) { if (tid < s) redd[tid] += redd[tid+s]; __syncthreads(); }
    if (tid == 0) smean = redd[0] / NEXP;
    __syncthreads();
    double mt = smean;
    ls = 0.0;
    for (int n = tid; n < NEXP; n += 256) { double t = (double)tot[n]-mt; ls += t*t; }
    redd[tid] = ls; __syncthreads();
    for (int s = 128; s > 0; s >>= 1) { if (tid < s) redd[tid] += redd[tid+s]; __syncthreads(); }
    if (tid == 0) {
        double st = sqrt(redd[0] / (NEXP-1));
        double ratio = st / mt;
        g_stats[20] = (float)(0.1 * ratio * ratio);
    }
    __syncthreads();
    for (int it = 0; it < NKTOP; it++) {
        float bv = -INFINITY; int bi = 0x7fffffff;
        for (int n = tid; n < NEXP; n += 256) {
            float v = tot[n];
            if (v > bv || (v == bv && n < bi)) { bv = v; bi = n; }
        }
        fv[tid] = bv; fi[tid] = bi; __syncthreads();
        for (int s = 128; s > 0; s >>= 1) {
            if (tid < s) {
                float v2 = fv[tid+s]; int i2 = fi[tid+s];
                if (v2 > fv[tid] || (v2 == fv[tid] && i2 < fi[tid])) { fv[tid] = v2; fi[tid] = i2; }
            }
            __syncthreads();
        }
        if (tid == 0) { topv[it] = fv[0]; tot[fi[0]] = -INFINITY; }
        __syncthreads();
    }
    if (tid == 0) {
        float m = topv[0];
        float s = 0.f;
        float e[NKTOP];
        for (int k = 0; k < NKTOP; k++) { e[k] = expf(topv[k]-m); s += e[k]; }
        for (int k = 0; k < NKTOP; k++) g_stats[k] = e[k]/s;
    }
}

// ---------------- response mixture (fp32 + bf16 mirror) ----------------
__global__ void mix_kernel(const float* __restrict__ responses)
{
    __shared__ float w[NKTOP];
    if (threadIdx.x < NKTOP) w[threadIdx.x] = g_stats[threadIdx.x];
    __syncthreads();
    int i = blockIdx.x*blockDim.x + threadIdx.x;
    if (i < (NROWS*D_MODEL)/4) {
        float4 s = make_float4(0.f, 0.f, 0.f, 0.f);
        #pragma unroll
        for (int k = 0; k < NKTOP; k++) {
            float4 v = ((const float4*)responses)[(size_t)k*((NROWS*D_MODEL)/4) + i];
            float wk = w[k];
            s.x += wk*v.x; s.y += wk*v.y; s.z += wk*v.z; s.w += wk*v.w;
        }
        ((float4*)g_x)[i] = s;
        ((__nv_bfloat162*)h_x)[2*i+0] = __floats2bfloat162_rn(s.x, s.y);
        ((__nv_bfloat162*)h_x)[2*i+1] = __floats2bfloat162_rn(s.z, s.w);
    }
}

// ---------------- label logit + final loss ----------------
__global__ void lablogit_kernel(const int* __restrict__ inputs, const float* __restrict__ dec_w)
{
    int s = blockIdx.x, b = blockIdx.y, tid = threadIdx.x;
    int lbl = inputs[b*NSEQ + s + 1];
    const float* a = g_x + ((size_t)(b*NSEQ + s))*D_MODEL;
    const float* wp = dec_w + (size_t)lbl*D_MODEL;
    __shared__ float red[128];
    float acc = 0.f;
    for (int k = tid; k < D_MODEL; k += 128) acc += a[k]*wp[k];
    red[tid] = acc; __syncthreads();
    for (int st = 64; st > 0; st >>= 1) { if (tid < st) red[tid] += red[tid+st]; __syncthreads(); }
    if (tid == 0) g_lab[b*(NSEQ-1)+s] = red[0];
}

__global__ void final_kernel(float* __restrict__ out)
{
    __shared__ double red[256];
    int tid = threadIdx.x;
    double s = 0.0;
    for (int i = tid; i < NB*(NSEQ-1); i += 256) {
        int b = i/(NSEQ-1), sp = i%(NSEQ-1);
        s += (double)g_lab[i] - (double)g_lse[b*NSEQ+sp];
    }
    red[tid] = s; __syncthreads();
    for (int st = 128; st > 0; st >>= 1) { if (tid < st) red[tid] += red[tid+st]; __syncthreads(); }
    if (tid == 0) {
        double ce = -red[0] / (double)(NB*(NSEQ-1));
        out[0] = (float)(ce + (double)g_stats[20]);
    }
}

// ---------------- host driver ----------------
extern "C" void kernel_launch(void* const* d_in, const int* in_sizes, int n_in,
                              void* d_out, int out_size)
{
    (void)in_sizes; (void)n_in; (void)out_size;
    const int*   inputs    = (const int*)  d_in[0];
    const float* responses = (const float*)d_in[1];
    const float* noise     = (const float*)d_in[2];
    const float* emb       = (const float*)d_in[3];
    const float* loc_Wqkv  = (const float*)d_in[4];
    const float* loc_bqkv  = (const float*)d_in[5];
    const float* loc_Wo    = (const float*)d_in[6];
    const float* loc_bo    = (const float*)d_in[7];
    const float* loc_ln1g  = (const float*)d_in[8];
    const float* loc_ln1b  = (const float*)d_in[9];
    const float* loc_W1    = (const float*)d_in[10];
    const float* loc_b1    = (const float*)d_in[11];
    const float* loc_W2    = (const float*)d_in[12];
    const float* loc_b2    = (const float*)d_in[13];
    const float* loc_ln2g  = (const float*)d_in[14];
    const float* loc_ln2b  = (const float*)d_in[15];
    const float* enc_Wqkv  = (const float*)d_in[16];
    const float* enc_bqkv  = (const float*)d_in[17];
    const float* enc_Wo    = (const float*)d_in[18];
    const float* enc_bo    = (const float*)d_in[19];
    const float* enc_ln1g  = (const float*)d_in[20];
    const float* enc_ln1b  = (const float*)d_in[21];
    const float* enc_W1    = (const float*)d_in[22];
    const float* enc_b1    = (const float*)d_in[23];
    const float* enc_W2    = (const float*)d_in[24];
    const float* enc_b2    = (const float*)d_in[25];
    const float* enc_ln2g  = (const float*)d_in[26];
    const float* enc_ln2b  = (const float*)d_in[27];
    const float* gate_w    = (const float*)d_in[28];
    const float* gate_b    = (const float*)d_in[29];
    const float* dec_w     = (const float*)d_in[30];
    float* out = (float*)d_out;

    float *p_x, *p_qkv, *p_tmp;
    float *p_sm_attn, *p_sm_x, *p_sm_tmp, *p_sm_ctx, *p_sm_ffh;
    __nv_bfloat16 *p_hdec, *p_hWqkv, *p_hWo, *p_hW1, *p_hW2, *p_hx, *p_hattn, *p_hffh;
    cudaGetSymbolAddress((void**)&p_x, g_x);
    cudaGetSymbolAddress((void**)&p_qkv, g_qkv);
    cudaGetSymbolAddress((void**)&p_tmp, g_tmp);
    cudaGetSymbolAddress((void**)&p_sm_attn, g_sm_attn);
    cudaGetSymbolAddress((void**)&p_sm_x, g_sm_x);
    cudaGetSymbolAddress((void**)&p_sm_tmp, g_sm_tmp);
    cudaGetSymbolAddress((void**)&p_sm_ctx, g_sm_ctx);
    cudaGetSymbolAddress((void**)&p_sm_ffh, g_sm_ffh);
    cudaGetSymbolAddress((void**)&p_hdec, h_dec);
    cudaGetSymbolAddress((void**)&p_hWqkv, h_Wqkv);
    cudaGetSymbolAddress((void**)&p_hWo, h_Wo);
    cudaGetSymbolAddress((void**)&p_hW1, h_W1);
    cudaGetSymbolAddress((void**)&p_hW2, h_W2);
    cudaGetSymbolAddress((void**)&p_hx, h_x);
    cudaGetSymbolAddress((void**)&p_hattn, h_attn);
    cudaGetSymbolAddress((void**)&p_hffh, h_ffh);

    // 0) weight conversions (bf16 mirrors)
    f2h_kernel<<<(NTOK*D_MODEL/4 + 255)/256, 256>>>(dec_w, p_hdec, NTOK*D_MODEL/4);
    f2h_kernel<<<(2*QKV_LD*D_MODEL/4 + 255)/256, 256>>>(enc_Wqkv, p_hWqkv, 2*QKV_LD*D_MODEL/4);
    f2h_kernel<<<(2*D_MODEL*D_MODEL/4 + 255)/256, 256>>>(enc_Wo, p_hWo, 2*D_MODEL*D_MODEL/4);
    f2h_kernel<<<(2*FF_DIM*D_MODEL/4 + 255)/256, 256>>>(enc_W1, p_hW1, 2*FF_DIM*D_MODEL/4);
    f2h_kernel<<<(2*D_MODEL*FF_DIM/4 + 255)/256, 256>>>(enc_W2, p_hW2, 2*D_MODEL*FF_DIM/4);

    // 1) embed
    embed_kernel<<<NROWS, 256>>>(inputs, emb);

    // 2) loc layer (only last position needed downstream) — tf32/fp32 path
    gemm_tc_kernel<<<dim3(2048/128, NROWS/128), 256>>>(
        p_x, loc_Wqkv + (size_t)D_MODEL*D_MODEL, loc_bqkv + D_MODEL,
        p_qkv + D_MODEL, D_MODEL, QKV_LD);
    rowdot_kernel<<<D_MODEL, 128>>>(
        p_x + (size_t)(NSEQ-1)*D_MODEL, (long)NSEQ*D_MODEL,
        loc_Wqkv, loc_bqkv,
        p_qkv + (size_t)(NSEQ-1)*QKV_LD, (long)NSEQ*QKV_LD,
        NB, D_MODEL, 1.f, 0);
    attn_kernel<<<dim3(1, NHEAD, NB), 256>>>(p_qkv, p_sm_attn, 1, NSEQ-1);
    rowdot_kernel<<<D_MODEL, 128>>>(p_sm_attn, D_MODEL, loc_Wo, loc_bo,
                                    p_sm_tmp, D_MODEL, NB, D_MODEL, 1.f, 0);
    ln_kernel<<<NB, 256>>>(p_x + (size_t)(NSEQ-1)*D_MODEL, (long)NSEQ*D_MODEL,
                           p_sm_tmp, D_MODEL, p_sm_x, D_MODEL, (__nv_bfloat16*)0,
                           loc_ln1g, loc_ln1b);
    rowdot_kernel<<<FF_DIM, 128>>>(p_sm_x, D_MODEL, loc_W1, loc_b1,
                                   p_sm_ffh, FF_DIM, NB, D_MODEL, 1.f, 1);
    rowdot_kernel<<<D_MODEL, 128>>>(p_sm_ffh, FF_DIM, loc_W2, loc_b2,
                                    p_sm_tmp, D_MODEL, NB, FF_DIM, 1.f, 0);
    ln_kernel<<<NB, 256>>>(p_sm_x, D_MODEL, p_sm_tmp, D_MODEL,
                           p_sm_ctx, D_MODEL, (__nv_bfloat16*)0,
                           loc_ln2g, loc_ln2b);

    // 3) gate weights (sqrt(D)=32 folded in)
    rowdot_kernel<<<NEXP, 128>>>(p_sm_ctx, D_MODEL, gate_w, gate_b,
                                 out + 1, NEXP, NB, D_MODEL, 32.f, 0);

    // 4) stats / top-k / softmax / importance
    stats_kernel<<<1, 256>>>(out + 1, noise);

    // 5) mixture of responses -> g_x + h_x
    mix_kernel<<<(NROWS*D_MODEL/4 + 255)/256, 256>>>(responses);

    // 6) two encoder layers (bf16 tensor cores)
    for (int l = 0; l < 2; l++) {
        const __nv_bfloat16* Wqkv = p_hWqkv + (size_t)l*QKV_LD*D_MODEL;
        const float*         bqkv = enc_bqkv + (size_t)l*QKV_LD;
        const __nv_bfloat16* Wo   = p_hWo   + (size_t)l*D_MODEL*D_MODEL;
        const float*         bo   = enc_bo  + (size_t)l*D_MODEL;
        const float* g1   = enc_ln1g + (size_t)l*D_MODEL;
        const float* b1l  = enc_ln1b + (size_t)l*D_MODEL;
        const __nv_bfloat16* W1   = p_hW1   + (size_t)l*FF_DIM*D_MODEL;
        const float*         bb1  = enc_b1  + (size_t)l*FF_DIM;
        const __nv_bfloat16* W2   = p_hW2   + (size_t)l*D_MODEL*FF_DIM;
        const float*         bb2  = enc_b2  + (size_t)l*D_MODEL;
        const float* g2   = enc_ln2g + (size_t)l*D_MODEL;
        const float* b2l  = enc_ln2b + (size_t)l*D_MODEL;

        gemm_bf_f32_kernel<<<dim3(QKV_LD/128, NROWS/128), 256>>>(
            p_hx, Wqkv, bqkv, p_qkv, D_MODEL, QKV_LD);
        attn8_kernel<<<dim3(NSEQ/QT, NHEAD, NB), 256>>>(p_qkv, p_hattn);
        gemm_bf_f32_kernel<<<dim3(D_MODEL/128, NROWS/128), 256>>>(
            p_hattn, Wo, bo, p_tmp, D_MODEL, D_MODEL);
        ln_kernel<<<NROWS, 256>>>(p_x, D_MODEL, p_tmp, D_MODEL, p_x, D_MODEL, p_hx, g1, b1l);
        gemm_bf_bf_relu_kernel<<<dim3(FF_DIM/128, NROWS/128), 256>>>(
            p_hx, W1, bb1, p_hffh, D_MODEL, FF_DIM);
        gemm_bf_f32_kernel<<<dim3(D_MODEL/128, NROWS/128), 256>>>(
            p_hffh, W2, bb2, p_tmp, FF_DIM, D_MODEL);
        ln_kernel<<<NROWS, 256>>>(p_x, D_MODEL, p_tmp, D_MODEL, p_x, D_MODEL, p_hx, g2, b2l);
    }

    // 7) fused decoder GEMM + logsumexp, label logits, CE + importance
    gemm_lse_bf_kernel<<<dim3(NBLK_V, NROWS/128), 256>>>(p_hx, p_hdec, D_MODEL);
    lse_reduce_kernel<<<NROWS, 128>>>();
    lablogit_kernel<<<dim3(NSEQ-1, NB), 128>>>(inputs, dec_w);
    final_kernel<<<1, 256>>>(out);
}

// round 5
// speedup vs baseline: 6.6375x; 1.0547x over previous
#include <cuda_runtime.h>
#include <cuda_bf16.h>
#include <math.h>
#include <stdint.h>

// ---------------- problem constants ----------------
#define D_MODEL 1024
#define NHEAD   16
#define DHEAD   64
#define FF_DIM  4096
#define NSEQ    256
#define NB      4
#define NTOK    50257
#define NEXP    2000
#define NKTOP   20
#define NROWS   (NB*NSEQ)      // 1024
#define QKV_LD  3072
#define NBLK_V  393            // ceil(50257/128)

// ---------------- scratch (static device memory; no allocation) ----------------
__device__ float g_x    [NROWS*D_MODEL];
__device__ float g_qkv  [NROWS*QKV_LD];
__device__ float g_tmp  [NROWS*D_MODEL];
__device__ float g_sm_attn[NB*D_MODEL];
__device__ float g_sm_x   [NB*D_MODEL];
__device__ float g_sm_tmp [NB*D_MODEL];
__device__ float g_sm_ctx [NB*D_MODEL];
__device__ float g_sm_ffh [NB*FF_DIM];
__device__ float g_pmax[NROWS*NBLK_V];
__device__ float g_psum[NROWS*NBLK_V];
__device__ float g_lse [NROWS];
__device__ float g_lab [NB*(NSEQ-1)];
__device__ float g_stats[32];   // [0..19] jw, [20] imp

// bf16 weight/activation mirrors
__device__ __align__(256) __nv_bfloat16 h_dec [NTOK*D_MODEL];
__device__ __align__(256) __nv_bfloat16 h_Wqkv[2*QKV_LD*D_MODEL];
__device__ __align__(256) __nv_bfloat16 h_Wo  [2*D_MODEL*D_MODEL];
__device__ __align__(256) __nv_bfloat16 h_W1  [2*FF_DIM*D_MODEL];
__device__ __align__(256) __nv_bfloat16 h_W2  [2*D_MODEL*FF_DIM];
__device__ __align__(256) __nv_bfloat16 h_x   [NROWS*D_MODEL];
__device__ __align__(256) __nv_bfloat16 h_attn[NROWS*D_MODEL];
__device__ __align__(256) __nv_bfloat16 h_ffh [NROWS*FF_DIM];

// ---------------- fp32 -> bf16 conversion ----------------
__global__ void f2h_kernel(const float* __restrict__ src, __nv_bfloat16* __restrict__ dst, int n4)
{
    int i = blockIdx.x*blockDim.x + threadIdx.x;
    if (i < n4) {
        float4 v = ((const float4*)src)[i];
        ((__nv_bfloat162*)dst)[2*i+0] = __floats2bfloat162_rn(v.x, v.y);
        ((__nv_bfloat162*)dst)[2*i+1] = __floats2bfloat162_rn(v.z, v.w);
    }
}

// ---------------- embedding gather ----------------
__global__ void embed_kernel(const int* __restrict__ inputs, const float* __restrict__ emb)
{
    int r = blockIdx.x;
    int tok = inputs[r];
    const float4* src = (const float4*)(emb + (size_t)tok * D_MODEL);
    float4* dst = (float4*)(g_x + (size_t)r * D_MODEL);
    dst[threadIdx.x] = src[threadIdx.x];
}

// ================= cp.async / ldmatrix helpers =================
__device__ __forceinline__ void cp_async16(void* smem, const void* gmem)
{
    uint32_t s = (uint32_t)__cvta_generic_to_shared(smem);
    asm volatile("cp.async.ca.shared.global [%0], [%1], 16;\n" :: "r"(s), "l"(gmem));
}
__device__ __forceinline__ void cp_commit()
{
    asm volatile("cp.async.commit_group;\n" ::: "memory");
}
template<int N> __device__ __forceinline__ void cp_wait()
{
    asm volatile("cp.async.wait_group %0;\n" :: "n"(N) : "memory");
}
__device__ __forceinline__ void ldsm_x4(uint32_t& r0, uint32_t& r1, uint32_t& r2, uint32_t& r3,
                                        const void* smem)
{
    uint32_t a = (uint32_t)__cvta_generic_to_shared(smem);
    asm volatile("ldmatrix.sync.aligned.m8n8.x4.shared.b16 {%0,%1,%2,%3}, [%4];\n"
                 : "=r"(r0), "=r"(r1), "=r"(r2), "=r"(r3) : "r"(a));
}
__device__ __forceinline__ void ldsm_x2(uint32_t& r0, uint32_t& r1, const void* smem)
{
    uint32_t a = (uint32_t)__cvta_generic_to_shared(smem);
    asm volatile("ldmatrix.sync.aligned.m8n8.x2.shared.b16 {%0,%1}, [%2];\n"
                 : "=r"(r0), "=r"(r1) : "r"(a));
}

// ================= tf32 GEMM (loc KV path only) =================
__device__ __forceinline__ void mma_mainloop(
    float acc[4][4][4],
    const float* __restrict__ A, const float* __restrict__ W,
    int K, int m0, int n0)
{
    __shared__ uint32_t As[2][128][20];
    __shared__ uint32_t Bs[2][128][20];
    int tid  = threadIdx.x;
    int lane = tid & 31, wid = tid >> 5;
    int wm = wid >> 2, wn = wid & 3;
    int g = lane >> 2, tig = lane & 3;

    int r0c = tid >> 2,         c0c = (tid & 3) << 2;
    int r1c = (tid + 256) >> 2, c1c = (tid & 3) << 2;
    const float* pa0 = A + (size_t)(m0 + r0c)*K + c0c;
    const float* pa1 = A + (size_t)(m0 + r1c)*K + c1c;
    const float* pb0 = W + (size_t)(n0 + r0c)*K + c0c;
    const float* pb1 = W + (size_t)(n0 + r1c)*K + c1c;

    int niter = K >> 4;
    cp_async16(&As[0][r0c][c0c], pa0);
    cp_async16(&As[0][r1c][c1c], pa1);
    cp_async16(&Bs[0][r0c][c0c], pb0);
    cp_async16(&Bs[0][r1c][c1c], pb1);
    cp_commit();

    for (int it = 0; it < niter; it++) {
        int st = it & 1;
        if (it + 1 < niter) {
            int off = (it + 1) << 4;
            int sn = st ^ 1;
            cp_async16(&As[sn][r0c][c0c], pa0 + off);
            cp_async16(&As[sn][r1c][c1c], pa1 + off);
            cp_async16(&Bs[sn][r0c][c0c], pb0 + off);
            cp_async16(&Bs[sn][r1c][c1c], pb1 + off);
            cp_commit();
            cp_wait<1>();
        } else {
            cp_wait<0>();
        }
        __syncthreads();
        #pragma unroll
        for (int ks = 0; ks < 16; ks += 8) {
            uint32_t af[4][4], bf[4][2];
            #pragma unroll
            for (int mt = 0; mt < 4; mt++) {
                int r0 = wm*64 + mt*16;
                af[mt][0] = As[st][r0+g  ][ks+tig  ];
                af[mt][1] = As[st][r0+g+8][ks+tig  ];
                af[mt][2] = As[st][r0+g  ][ks+tig+4];
                af[mt][3] = As[st][r0+g+8][ks+tig+4];
            }
            #pragma unroll
            for (int nt = 0; nt < 4; nt++) {
                int c0 = wn*32 + nt*8;
                bf[nt][0] = Bs[st][c0+g][ks+tig  ];
                bf[nt][1] = Bs[st][c0+g][ks+tig+4];
            }
            #pragma unroll
            for (int mt = 0; mt < 4; mt++)
                #pragma unroll
                for (int nt = 0; nt < 4; nt++) {
                    asm volatile(
                        "mma.sync.aligned.m16n8k8.row.col.f32.tf32.tf32.f32 "
                        "{%0,%1,%2,%3}, {%4,%5,%6,%7}, {%8,%9}, {%0,%1,%2,%3};\n"
                        : "+f"(acc[mt][nt][0]), "+f"(acc[mt][nt][1]),
                          "+f"(acc[mt][nt][2]), "+f"(acc[mt][nt][3])
                        : "r"(af[mt][0]), "r"(af[mt][1]),
                          "r"(af[mt][2]), "r"(af[mt][3]),
                          "r"(bf[nt][0]), "r"(bf[nt][1]));
                }
        }
        __syncthreads();
    }
}

__global__ __launch_bounds__(256, 2) void gemm_tc_kernel(
    const float* __restrict__ A, const float* __restrict__ W,
    const float* __restrict__ bias, float* __restrict__ C,
    int K, int ldC)
{
    float acc[4][4][4];
    #pragma unroll
    for (int a = 0; a < 4; a++)
        #pragma unroll
        for (int b = 0; b < 4; b++)
            #pragma unroll
            for (int c = 0; c < 4; c++) acc[a][b][c] = 0.f;

    int m0 = blockIdx.y * 128, n0 = blockIdx.x * 128;
    mma_mainloop(acc, A, W, K, m0, n0);

    int tid = threadIdx.x;
    int lane = tid & 31, wid = tid >> 5;
    int wm = wid >> 2, wn = wid & 3;
    int g = lane >> 2, tig = lane & 3;
    int rowb = m0 + wm*64;
    int colb = n0 + wn*32;
    #pragma unroll
    for (int nt = 0; nt < 4; nt++) {
        int c = colb + nt*8 + 2*tig;
        float b0 = bias[c], b1 = bias[c+1];
        #pragma unroll
        for (int mt = 0; mt < 4; mt++) {
            int r = rowb + mt*16 + g;
            *(float2*)(C + (size_t)r*ldC + c)     = make_float2(acc[mt][nt][0]+b0, acc[mt][nt][1]+b1);
            *(float2*)(C + (size_t)(r+8)*ldC + c) = make_float2(acc[mt][nt][2]+b0, acc[mt][nt][3]+b1);
        }
    }
}

// ================= bf16 GEMM core (m16n8k16, ldmatrix), BK=32 =================
__device__ __forceinline__ void mma_bf16_mainloop(
    float acc[4][4][4],
    const __nv_bfloat16* __restrict__ A, const __nv_bfloat16* __restrict__ W,
    int K, int m0, int n0, int nmax)
{
    __shared__ uint32_t As[2][128][20];   // 16 used words = 32 bf16, pad 4
    __shared__ uint32_t Bs[2][128][20];
    int tid  = threadIdx.x;
    int lane = tid & 31, wid = tid >> 5;
    int wm = wid >> 2, wn = wid & 3;

    // ldmatrix per-lane source offsets
    int a_row = (lane & 7) + ((lane >> 3) & 1) * 8;   // + (quad>>1)? no: see mapping
    int a_wrd = (lane >> 4) * 4;
    int b_row = lane & 7;
    int b_wrd = ((lane >> 3) & 1) * 4;

    int r0c = tid >> 2, r1c = r0c + 64;
    int cw = (tid & 3) * 4;   // word col
    int ce = (tid & 3) * 8;   // element col
    int nr0 = n0 + r0c; nr0 = (nr0 < nmax) ? nr0 : (nmax - 1);
    int nr1 = n0 + r1c; nr1 = (nr1 < nmax) ? nr1 : (nmax - 1);
    const __nv_bfloat16* pa0 = A + (size_t)(m0 + r0c)*K + ce;
    const __nv_bfloat16* pa1 = A + (size_t)(m0 + r1c)*K + ce;
    const __nv_bfloat16* pb0 = W + (size_t)nr0*K + ce;
    const __nv_bfloat16* pb1 = W + (size_t)nr1*K + ce;

    int niter = K >> 5;
    cp_async16(&As[0][r0c][cw], pa0);
    cp_async16(&As[0][r1c][cw], pa1);
    cp_async16(&Bs[0][r0c][cw], pb0);
    cp_async16(&Bs[0][r1c][cw], pb1);
    cp_commit();

    for (int it = 0; it < niter; it++) {
        int st = it & 1;
        if (it + 1 < niter) {
            int off = (it + 1) << 5;
            int sn = st ^ 1;
            cp_async16(&As[sn][r0c][cw], pa0 + off);
            cp_async16(&As[sn][r1c][cw], pa1 + off);
            cp_async16(&Bs[sn][r0c][cw], pb0 + off);
            cp_async16(&Bs[sn][r1c][cw], pb1 + off);
            cp_commit();
            cp_wait<1>();
        } else {
            cp_wait<0>();
        }
        __syncthreads();
        #pragma unroll
        for (int ks = 0; ks < 2; ks++) {
            int kb = ks*8;
            uint32_t af[4][4], bf[4][2];
            #pragma unroll
            for (int mt = 0; mt < 4; mt++) {
                int r0 = wm*64 + mt*16;
                ldsm_x4(af[mt][0], af[mt][1], af[mt][2], af[mt][3],
                        &As[st][r0 + a_row][kb + a_wrd]);
            }
            #pragma unroll
            for (int nt = 0; nt < 4; nt++) {
                int c0 = wn*32 + nt*8;
                ldsm_x2(bf[nt][0], bf[nt][1],
                        &Bs[st][c0 + b_row][kb + b_wrd]);
            }
            #pragma unroll
            for (int mt = 0; mt < 4; mt++)
                #pragma unroll
                for (int nt = 0; nt < 4; nt++) {
                    asm volatile(
                        "mma.sync.aligned.m16n8k16.row.col.f32.bf16.bf16.f32 "
                        "{%0,%1,%2,%3}, {%4,%5,%6,%7}, {%8,%9}, {%0,%1,%2,%3};\n"
                        : "+f"(acc[mt][nt][0]), "+f"(acc[mt][nt][1]),
                          "+f"(acc[mt][nt][2]), "+f"(acc[mt][nt][3])
                        : "r"(af[mt][0]), "r"(af[mt][1]),
                          "r"(af[mt][2]), "r"(af[mt][3]),
                          "r"(bf[nt][0]), "r"(bf[nt][1]));
                }
        }
        __syncthreads();
    }
}

// bf16 GEMM -> fp32 out (+bias)
__global__ __launch_bounds__(256, 2) void gemm_bf_f32_kernel(
    const __nv_bfloat16* __restrict__ A, const __nv_bfloat16* __restrict__ W,
    const float* __restrict__ bias, float* __restrict__ C, int K, int ldC)
{
    float acc[4][4][4];
    #pragma unroll
    for (int a = 0; a < 4; a++)
        #pragma unroll
        for (int b = 0; b < 4; b++)
            #pragma unroll
            for (int c = 0; c < 4; c++) acc[a][b][c] = 0.f;
    int m0 = blockIdx.y * 128, n0 = blockIdx.x * 128;
    mma_bf16_mainloop(acc, A, W, K, m0, n0, 0x40000000);

    int tid = threadIdx.x;
    int lane = tid & 31, wid = tid >> 5;
    int wm = wid >> 2, wn = wid & 3;
    int g = lane >> 2, tig = lane & 3;
    int rowb = m0 + wm*64, colb = n0 + wn*32;
    #pragma unroll
    for (int nt = 0; nt < 4; nt++) {
        int c = colb + nt*8 + 2*tig;
        float b0 = bias[c], b1 = bias[c+1];
        #pragma unroll
        for (int mt = 0; mt < 4; mt++) {
            int r = rowb + mt*16 + g;
            *(float2*)(C + (size_t)r*ldC + c)     = make_float2(acc[mt][nt][0]+b0, acc[mt][nt][1]+b1);
            *(float2*)(C + (size_t)(r+8)*ldC + c) = make_float2(acc[mt][nt][2]+b0, acc[mt][nt][3]+b1);
        }
    }
}

// bf16 GEMM -> bf16 out (+bias, +relu)  (FF1 path)
__global__ __launch_bounds__(256, 2) void gemm_bf_bf_relu_kernel(
    const __nv_bfloat16* __restrict__ A, const __nv_bfloat16* __restrict__ W,
    const float* __restrict__ bias, __nv_bfloat16* __restrict__ C, int K, int ldC)
{
    float acc[4][4][4];
    #pragma unroll
    for (int a = 0; a < 4; a++)
        #pragma unroll
        for (int b = 0; b < 4; b++)
            #pragma unroll
            for (int c = 0; c < 4; c++) acc[a][b][c] = 0.f;
    int m0 = blockIdx.y * 128, n0 = blockIdx.x * 128;
    mma_bf16_mainloop(acc, A, W, K, m0, n0, 0x40000000);

    int tid = threadIdx.x;
    int lane = tid & 31, wid = tid >> 5;
    int wm = wid >> 2, wn = wid & 3;
    int g = lane >> 2, tig = lane & 3;
    int rowb = m0 + wm*64, colb = n0 + wn*32;
    #pragma unroll
    for (int nt = 0; nt < 4; nt++) {
        int c = colb + nt*8 + 2*tig;
        float b0 = bias[c], b1 = bias[c+1];
        #pragma unroll
        for (int mt = 0; mt < 4; mt++) {
            int r = rowb + mt*16 + g;
            float v0 = fmaxf(acc[mt][nt][0]+b0, 0.f);
            float v1 = fmaxf(acc[mt][nt][1]+b1, 0.f);
            float v2 = fmaxf(acc[mt][nt][2]+b0, 0.f);
            float v3 = fmaxf(acc[mt][nt][3]+b1, 0.f);
            *(__nv_bfloat162*)(C + (size_t)r*ldC + c)     = __floats2bfloat162_rn(v0, v1);
            *(__nv_bfloat162*)(C + (size_t)(r+8)*ldC + c) = __floats2bfloat162_rn(v2, v3);
        }
    }
}

// decoder bf16 GEMM + fused online-lse partials.
// Grid: x = m-tile (8, fastest) so all m-tiles of one n-tile run concurrently
// and share the B tile via L2 (dec_w read ~once from DRAM).
__global__ __launch_bounds__(256, 2) void gemm_lse_bf_kernel(
    const __nv_bfloat16* __restrict__ A, const __nv_bfloat16* __restrict__ W, int K)
{
    float acc[4][4][4];
    #pragma unroll
    for (int a = 0; a < 4; a++)
        #pragma unroll
        for (int b = 0; b < 4; b++)
            #pragma unroll
            for (int c = 0; c < 4; c++) acc[a][b][c] = 0.f;
    int m0 = blockIdx.x * 128, n0 = blockIdx.y * 128;
    int nblk = blockIdx.y;
    mma_bf16_mainloop(acc, A, W, K, m0, n0, NTOK);

    __shared__ float red_m[4][128];
    __shared__ float red_s[4][128];
    int tid = threadIdx.x;
    int lane = tid & 31, wid = tid >> 5;
    int wm = wid >> 2, wn = wid & 3;
    int g = lane >> 2, tig = lane & 3;
    int colb = n0 + wn*32;

    #pragma unroll
    for (int mt = 0; mt < 4; mt++) {
        #pragma unroll
        for (int h = 0; h < 2; h++) {
            float m = -INFINITY;
            #pragma unroll
            for (int nt = 0; nt < 4; nt++) {
                int c = colb + nt*8 + 2*tig;
                if (c     < NTOK) m = fmaxf(m, acc[mt][nt][h*2+0]);
                if (c + 1 < NTOK) m = fmaxf(m, acc[mt][nt][h*2+1]);
            }
            m = fmaxf(m, __shfl_xor_sync(0xffffffffu, m, 1));
            m = fmaxf(m, __shfl_xor_sync(0xffffffffu, m, 2));
            float s = 0.f;
            #pragma unroll
            for (int nt = 0; nt < 4; nt++) {
                int c = colb + nt*8 + 2*tig;
                if (c     < NTOK) s += __expf(acc[mt][nt][h*2+0] - m);
                if (c + 1 < NTOK) s += __expf(acc[mt][nt][h*2+1] - m);
            }
            s += __shfl_xor_sync(0xffffffffu, s, 1);
            s += __shfl_xor_sync(0xffffffffu, s, 2);
            if (tig == 0) {
                int lr = wm*64 + mt*16 + h*8 + g;
                red_m[wn][lr] = m;
                red_s[wn][lr] = s;
            }
        }
    }
    __syncthreads();
    if (tid < 128) {
        float m0v = red_m[0][tid], m1v = red_m[1][tid];
        float m2v = red_m[2][tid], m3v = red_m[3][tid];
        float mx = fmaxf(fmaxf(m0v, m1v), fmaxf(m2v, m3v));
        float s = red_s[0][tid]*__expf(m0v-mx) + red_s[1][tid]*__expf(m1v-mx)
                + red_s[2][tid]*__expf(m2v-mx) + red_s[3][tid]*__expf(m3v-mx);
        int row = m0 + tid;
        g_pmax[(size_t)row*NBLK_V + nblk] = mx;
        g_psum[(size_t)row*NBLK_V + nblk] = s;
    }
}

__global__ void lse_reduce_kernel()
{
    int r = blockIdx.x, tid = threadIdx.x;
    __shared__ float red[128];
    float m = -INFINITY;
    for (int i = tid; i < NBLK_V; i += 128) m = fmaxf(m, g_pmax[(size_t)r*NBLK_V + i]);
    red[tid] = m; __syncthreads();
    for (int s = 64; s > 0; s >>= 1) { if (tid < s) red[tid] = fmaxf(red[tid], red[tid+s]); __syncthreads(); }
    float gm = red[0]; __syncthreads();
    double sum = 0.0;
    for (int i = tid; i < NBLK_V; i += 128)
        sum += (double)g_psum[(size_t)r*NBLK_V + i] * exp((double)g_pmax[(size_t)r*NBLK_V + i] - (double)gm);
    __shared__ double redd[128];
    redd[tid] = sum; __syncthreads();
    for (int s = 64; s > 0; s >>= 1) { if (tid < s) redd[tid] += redd[tid+s]; __syncthreads(); }
    if (tid == 0) g_lse[r] = gm + (float)log(redd[0]);
}

// ---------------- small-M GEMM ----------------
__global__ void rowdot_kernel(
    const float* __restrict__ A, long strideA,
    const float* __restrict__ W, const float* __restrict__ bias,
    float* __restrict__ C, long strideC,
    int M, int K, float alpha, int relu)
{
    int n = blockIdx.x;
    int tid = threadIdx.x;   // 128
    const float* w = W + (size_t)n * K;
    __shared__ float red[128];
    for (int m = 0; m < M; m++) {
        const float* a = A + (size_t)m * strideA;
        float s = 0.f;
        for (int k = tid; k < K; k += 128) s += a[k]*w[k];
        red[tid] = s; __syncthreads();
        for (int st = 64; st > 0; st >>= 1) { if (tid < st) red[tid] += red[tid+st]; __syncthreads(); }
        if (tid == 0) {
            float v = alpha*red[0] + (bias ? bias[n] : 0.f);
            if (relu) v = fmaxf(v, 0.f);
            C[(size_t)m*strideC + n] = v;
        }
        __syncthreads();
    }
}

// ---------------- attention, 8 queries per block, bf16 out ----------------
#define QT 8
__global__ __launch_bounds__(256) void attn8_kernel(
    const float* __restrict__ qkv, __nv_bfloat16* __restrict__ out)
{
    int qt = blockIdx.x, h = blockIdx.y, b = blockIdx.z;
    int tid = threadIdx.x;
    __shared__ float qs[QT][DHEAD];
    __shared__ float sc[QT][NSEQ];
    __shared__ float den[QT];
    const float* base = qkv + (size_t)b*NSEQ*QKV_LD;
    if (tid < 128) {
        int q = tid >> 4;
        int c = (tid & 15) * 4;
        *(float4*)&qs[q][c] =
            *(const float4*)(base + (size_t)(qt*QT+q)*QKV_LD + h*DHEAD + c);
    }
    __syncthreads();
    {
        int j = tid;
        float4 kreg[16];
        const float4* kr = (const float4*)(base + (size_t)j*QKV_LD + D_MODEL + h*DHEAD);
        #pragma unroll
        for (int t = 0; t < 16; t++) kreg[t] = kr[t];
        #pragma unroll
        for (int q = 0; q < QT; q++) {
            float d = 0.f;
            #pragma unroll
            for (int t = 0; t < 16; t++) {
                float4 q4 = *(float4*)&qs[q][t*4];
                d += q4.x*kreg[t].x + q4.y*kreg[t].y + q4.z*kreg[t].z + q4.w*kreg[t].w;
            }
            sc[q][j] = d * 0.125f;
        }
    }
    __syncthreads();
    {
        int w = tid >> 5, lane = tid & 31;
        float v[8];
        float m = -INFINITY;
        #pragma unroll
        for (int t = 0; t < 8; t++) { v[t] = sc[w][lane + 32*t]; m = fmaxf(m, v[t]); }
        #pragma unroll
        for (int o = 16; o; o >>= 1) m = fmaxf(m, __shfl_xor_sync(0xffffffffu, m, o));
        float s = 0.f;
        #pragma unroll
        for (int t = 0; t < 8; t++) { v[t] = expf(v[t]-m); s += v[t]; }
        #pragma unroll
        for (int o = 16; o; o >>= 1) s += __shfl_xor_sync(0xffffffffu, s, o);
        #pragma unroll
        for (int t = 0; t < 8; t++) sc[w][lane + 32*t] = v[t];
        if (lane == 0) den[w] = s;
    }
    __syncthreads();
    {
        int d = tid & 63, qp = tid >> 6;
        int q0 = qp*2, q1 = qp*2+1;
        const float* vb = base + 2*D_MODEL + h*DHEAD + d;
        float a0 = 0.f, a1 = 0.f;
        #pragma unroll 8
        for (int j = 0; j < NSEQ; j++) {
            float v = vb[(size_t)j*QKV_LD];
            a0 += sc[q0][j]*v;
            a1 += sc[q1][j]*v;
        }
        out[((size_t)(b*NSEQ + qt*QT + q0))*D_MODEL + h*DHEAD + d] = __float2bfloat16(a0/den[q0]);
        out[((size_t)(b*NSEQ + qt*QT + q1))*D_MODEL + h*DHEAD + d] = __float2bfloat16(a1/den[q1]);
    }
}

// ---------------- loc attention (single query per (h,b)), fp32 out ----------------
__global__ __launch_bounds__(256) void attn_kernel(
    const float* __restrict__ qkv, float* __restrict__ out, int nq, int sq_base)
{
    int qi = blockIdx.x, h = blockIdx.y, b = blockIdx.z;
    int sq = sq_base + qi;
    int tid = threadIdx.x;
    __shared__ float4 qrow[DHEAD/4];
    __shared__ float sc[NSEQ];
    __shared__ float red[256];
    __shared__ float sden;
    __shared__ float osum[4][DHEAD];
    const float* base = qkv + (size_t)b * NSEQ * QKV_LD;
    if (tid < DHEAD/4)
        qrow[tid] = ((const float4*)(base + (size_t)sq*QKV_LD + h*DHEAD))[tid];
    __syncthreads();
    {
        const float4* krow = (const float4*)(base + (size_t)tid*QKV_LD + D_MODEL + h*DHEAD);
        float d = 0.f;
        #pragma unroll
        for (int t = 0; t < DHEAD/4; t++) {
            float4 k4 = krow[t];
            float4 q4 = qrow[t];
            d += q4.x*k4.x + q4.y*k4.y + q4.z*k4.z + q4.w*k4.w;
        }
        sc[tid] = d * 0.125f;
    }
    __syncthreads();
    red[tid] = sc[tid]; __syncthreads();
    for (int s = 128; s > 0; s >>= 1) { if (tid < s) red[tid] = fmaxf(red[tid], red[tid+s]); __syncthreads(); }
    float mx = red[0]; __syncthreads();
    float e = expf(sc[tid] - mx);
    red[tid] = e; __syncthreads();
    for (int s = 128; s > 0; s >>= 1) { if (tid < s) red[tid] += red[tid+s]; __syncthreads(); }
    if (tid == 0) sden = red[0];
    __syncthreads();
    sc[tid] = e;
    __syncthreads();
    int d = tid & 63, g = tid >> 6;
    const float* vb = base + 2*D_MODEL + h*DHEAD + d;
    float o = 0.f;
    for (int j = g*64; j < (g+1)*64; j++) o += sc[j] * vb[(size_t)j*QKV_LD];
    osum[g][d] = o; __syncthreads();
    if (tid < DHEAD) {
        float r = (osum[0][tid]+osum[1][tid]+osum[2][tid]+osum[3][tid]) / sden;
        out[((size_t)(b*nq + qi))*D_MODEL + h*DHEAD + tid] = r;
    }
}

// ---------------- residual + layernorm (fp32 out + optional bf16 mirror) ----------
__global__ void ln_kernel(
    const float* __restrict__ in1, long s1,
    const float* __restrict__ in2, long s2,
    float* __restrict__ out, long so,
    __nv_bfloat16* __restrict__ outh,
    const float* __restrict__ gam, const float* __restrict__ bet)
{
    int r = blockIdx.x, tid = threadIdx.x;
    __shared__ float xr[D_MODEL];
    __shared__ float red[256];
    const float* p1 = in1 + (size_t)r*s1;
    const float* p2 = in2 + (size_t)r*s2;
    float ls = 0.f;
    for (int d = tid; d < D_MODEL; d += 256) { float v = p1[d]+p2[d]; xr[d] = v; ls += v; }
    red[tid] = ls; __syncthreads();
    for (int s = 128; s > 0; s >>= 1) { if (tid < s) red[tid] += red[tid+s]; __syncthreads(); }
    float mean = red[0] * (1.f/D_MODEL); __syncthreads();
    float lv = 0.f;
    for (int d = tid; d < D_MODEL; d += 256) { float t = xr[d]-mean; lv += t*t; }
    red[tid] = lv; __syncthreads();
    for (int s = 128; s > 0; s >>= 1) { if (tid < s) red[tid] += red[tid+s]; __syncthreads(); }
    float rstd = 1.f / sqrtf(red[0]*(1.f/D_MODEL) + 1e-5f);
    for (int d = tid; d < D_MODEL; d += 256) {
        float v = (xr[d]-mean)*rstd*gam[d] + bet[d];
        out[(size_t)r*so + d] = v;
        if (outh) outh[(size_t)r*D_MODEL + d] = __float2bfloat16(v);
    }
}

// ---------------- gating statistics + top-k + softmax + importance ----------------
__global__ void stats_kernel(const float* __restrict__ w, const float* __restrict__ noise)
{
    __shared__ float tot[NEXP];
    __shared__ double redd[256];
    __shared__ float fv[256];
    __shared__ int   fi[256];
    __shared__ float topv[NKTOP];
    __shared__ double smean, sstd;
    int tid = threadIdx.x;
    double ls = 0.0;
    for (int n = tid; n < NEXP; n += 256) {
        float f = 0.25f*(w[n] + w[NEXP+n] + w[2*NEXP+n] + w[3*NEXP+n]);
        tot[n] = f; ls += (double)f;
    }
    redd[tid] = ls; __syncthreads();
    for (int s = 128; s > 0; s >>= 1) { if (tid < s) redd[tid] += redd[tid+s]; __syncthreads(); }
    if (tid == 0) smean = redd[0] / NEXP;
    __syncthreads();
    double mfm = smean;
    ls = 0.0;
    for (int n = tid; n < NEXP; n += 256) { double t = (double)tot[n]-mfm; ls += t*t; }
    redd[tid] = ls; __syncthreads();
    for (int s = 128; s > 0; s >>= 1) { if (tid < s) redd[tid] += redd[tid+s]; __syncthreads(); }
    if (tid == 0) sstd = sqrt(redd[0] / (NEXP-1));
    __syncthreads();
    float stdfm = (float)sstd;
    for (int n = tid; n < NEXP; n += 256) tot[n] = tot[n] + noise[n]*stdfm;
    __syncthreads();
    ls = 0.0;
    for (int n = tid; n < NEXP; n += 256) ls += (double)tot[n];
    redd[tid] = ls; __syncthreads();
    for (int s = 128; s > 0; s >>= 1) { if (tid < s) redd[tid] += redd[tid+s]; __syncthreads(); }
    if (tid == 0) smean = redd[0] / NEXP;
    __syncthreads();
    double mt = smean;
    ls = 0.0;
    for (int n = tid; n < NEXP; n += 256) { double t = (double)tot[n]-mt; ls += t*t; }
    redd[tid] = ls; __syncthreads();
    for (int s = 128; s > 0; s >>= 1) { if (tid < s) redd[tid] += redd[tid+s]; __syncthreads(); }
    if (tid == 0) {
        double st = sqrt(redd[0] / (NEXP-1));
        double ratio = st / mt;
        g_stats[20] = (float)(0.1 * ratio * ratio);
    }
    __syncthreads();
    for (int it = 0; it < NKTOP; it++) {
        float bv = -INFINITY; int bi = 0x7fffffff;
        for (int n = tid; n < NEXP; n += 256) {
            float v = tot[n];
            if (v > bv || (v == bv && n < bi)) { bv = v; bi = n; }
        }
        fv[tid] = bv; fi[tid] = bi; __syncthreads();
        for (int s = 128; s > 0; s >>= 1) {
            if (tid < s) {
                float v2 = fv[tid+s]; int i2 = fi[tid+s];
                if (v2 > fv[tid] || (v2 == fv[tid] && i2 < fi[tid])) { fv[tid] = v2; fi[tid] = i2; }
            }
            __syncthreads();
        }
        if (tid == 0) { topv[it] = fv[0]; tot[fi[0]] = -INFINITY; }
        __syncthreads();
    }
    if (tid == 0) {
        float m = topv[0];
        float s = 0.f;
        float e[NKTOP];
        for (int k = 0; k < NKTOP; k++) { e[k] = expf(topv[k]-m); s += e[k]; }
        for (int k = 0; k < NKTOP; k++) g_stats[k] = e[k]/s;
    }
}

// ---------------- response mixture (fp32 + bf16 mirror) ----------------
__global__ void mix_kernel(const float* __restrict__ responses)
{
    __shared__ float w[NKTOP];
    if (threadIdx.x < NKTOP) w[threadIdx.x] = g_stats[threadIdx.x];
    __syncthreads();
    int i = blockIdx.x*blockDim.x + threadIdx.x;
    if (i < (NROWS*D_MODEL)/4) {
        float4 s = make_float4(0.f, 0.f, 0.f, 0.f);
        #pragma unroll
        for (int k = 0; k < NKTOP; k++) {
            float4 v = ((const float4*)responses)[(size_t)k*((NROWS*D_MODEL)/4) + i];
            float wk = w[k];
            s.x += wk*v.x; s.y += wk*v.y; s.z += wk*v.z; s.w += wk*v.w;
        }
        ((float4*)g_x)[i] = s;
        ((__nv_bfloat162*)h_x)[2*i+0] = __floats2bfloat162_rn(s.x, s.y);
        ((__nv_bfloat162*)h_x)[2*i+1] = __floats2bfloat162_rn(s.z, s.w);
    }
}

// ---------------- label logit + final loss ----------------
__global__ void lablogit_kernel(const int* __restrict__ inputs, const float* __restrict__ dec_w)
{
    int s = blockIdx.x, b = blockIdx.y, tid = threadIdx.x;
    int lbl = inputs[b*NSEQ + s + 1];
    const float* a = g_x + ((size_t)(b*NSEQ + s))*D_MODEL;
    const float* wp = dec_w + (size_t)lbl*D_MODEL;
    __shared__ float red[128];
    float acc = 0.f;
    for (int k = tid; k < D_MODEL; k += 128) acc += a[k]*wp[k];
    red[tid] = acc; __syncthreads();
    for (int st = 64; st > 0; st >>= 1) { if (tid < st) red[tid] += red[tid+st]; __syncthreads(); }
    if (tid == 0) g_lab[b*(NSEQ-1)+s] = red[0];
}

__global__ void final_kernel(float* __restrict__ out)
{
    __shared__ double red[256];
    int tid = threadIdx.x;
    double s = 0.0;
    for (int i = tid; i < NB*(NSEQ-1); i += 256) {
        int b = i/(NSEQ-1), sp = i%(NSEQ-1);
        s += (double)g_lab[i] - (double)g_lse[b*NSEQ+sp];
    }
    red[tid] = s; __syncthreads();
    for (int st = 128; st > 0; st >>= 1) { if (tid < st) red[tid] += red[tid+st]; __syncthreads(); }
    if (tid == 0) {
        double ce = -red[0] / (double)(NB*(NSEQ-1));
        out[0] = (float)(ce + (double)g_stats[20]);
    }
}

// ---------------- host driver ----------------
extern "C" void kernel_launch(void* const* d_in, const int* in_sizes, int n_in,
                              void* d_out, int out_size)
{
    (void)in_sizes; (void)n_in; (void)out_size;
    const int*   inputs    = (const int*)  d_in[0];
    const float* responses = (const float*)d_in[1];
    const float* noise     = (const float*)d_in[2];
    const float* emb       = (const float*)d_in[3];
    const float* loc_Wqkv  = (const float*)d_in[4];
    const float* loc_bqkv  = (const float*)d_in[5];
    const float* loc_Wo    = (const float*)d_in[6];
    const float* loc_bo    = (const float*)d_in[7];
    const float* loc_ln1g  = (const float*)d_in[8];
    const float* loc_ln1b  = (const float*)d_in[9];
    const float* loc_W1    = (const float*)d_in[10];
    const float* loc_b1    = (const float*)d_in[11];
    const float* loc_W2    = (const float*)d_in[12];
    const float* loc_b2    = (const float*)d_in[13];
    const float* loc_ln2g  = (const float*)d_in[14];
    const float* loc_ln2b  = (const float*)d_in[15];
    const float* enc_Wqkv  = (const float*)d_in[16];
    const float* enc_bqkv  = (const float*)d_in[17];
    const float* enc_Wo    = (const float*)d_in[18];
    const float* enc_bo    = (const float*)d_in[19];
    const float* enc_ln1g  = (const float*)d_in[20];
    const float* enc_ln1b  = (const float*)d_in[21];
    const float* enc_W1    = (const float*)d_in[22];
    const float* enc_b1    = (const float*)d_in[23];
    const float* enc_W2    = (const float*)d_in[24];
    const float* enc_b2    = (const float*)d_in[25];
    const float* enc_ln2g  = (const float*)d_in[26];
    const float* enc_ln2b  = (const float*)d_in[27];
    const float* gate_w    = (const float*)d_in[28];
    const float* gate_b    = (const float*)d_in[29];
    const float* dec_w     = (const float*)d_in[30];
    float* out = (float*)d_out;

    float *p_x, *p_qkv, *p_tmp;
    float *p_sm_attn, *p_sm_x, *p_sm_tmp, *p_sm_ctx, *p_sm_ffh;
    __nv_bfloat16 *p_hdec, *p_hWqkv, *p_hWo, *p_hW1, *p_hW2, *p_hx, *p_hattn, *p_hffh;
    cudaGetSymbolAddress((void**)&p_x, g_x);
    cudaGetSymbolAddress((void**)&p_qkv, g_qkv);
    cudaGetSymbolAddress((void**)&p_tmp, g_tmp);
    cudaGetSymbolAddress((void**)&p_sm_attn, g_sm_attn);
    cudaGetSymbolAddress((void**)&p_sm_x, g_sm_x);
    cudaGetSymbolAddress((void**)&p_sm_tmp, g_sm_tmp);
    cudaGetSymbolAddress((void**)&p_sm_ctx, g_sm_ctx);
    cudaGetSymbolAddress((void**)&p_sm_ffh, g_sm_ffh);
    cudaGetSymbolAddress((void**)&p_hdec, h_dec);
    cudaGetSymbolAddress((void**)&p_hWqkv, h_Wqkv);
    cudaGetSymbolAddress((void**)&p_hWo, h_Wo);
    cudaGetSymbolAddress((void**)&p_hW1, h_W1);
    cudaGetSymbolAddress((void**)&p_hW2, h_W2);
    cudaGetSymbolAddress((void**)&p_hx, h_x);
    cudaGetSymbolAddress((void**)&p_hattn, h_attn);
    cudaGetSymbolAddress((void**)&p_hffh, h_ffh);

    // 0) weight conversions (bf16 mirrors)
    f2h_kernel<<<(NTOK*D_MODEL/4 + 255)/256, 256>>>(dec_w, p_hdec, NTOK*D_MODEL/4);
    f2h_kernel<<<(2*QKV_LD*D_MODEL/4 + 255)/256, 256>>>(enc_Wqkv, p_hWqkv, 2*QKV_LD*D_MODEL/4);
    f2h_kernel<<<(2*D_MODEL*D_MODEL/4 + 255)/256, 256>>>(enc_Wo, p_hWo, 2*D_MODEL*D_MODEL/4);
    f2h_kernel<<<(2*FF_DIM*D_MODEL/4 + 255)/256, 256>>>(enc_W1, p_hW1, 2*FF_DIM*D_MODEL/4);
    f2h_kernel<<<(2*D_MODEL*FF_DIM/4 + 255)/256, 256>>>(enc_W2, p_hW2, 2*D_MODEL*FF_DIM/4);

    // 1) embed
    embed_kernel<<<NROWS, 256>>>(inputs, emb);

    // 2) loc layer (only last position needed downstream) — tf32/fp32 path
    gemm_tc_kernel<<<dim3(2048/128, NROWS/128), 256>>>(
        p_x, loc_Wqkv + (size_t)D_MODEL*D_MODEL, loc_bqkv + D_MODEL,
        p_qkv + D_MODEL, D_MODEL, QKV_LD);
    rowdot_kernel<<<D_MODEL, 128>>>(
        p_x + (size_t)(NSEQ-1)*D_MODEL, (long)NSEQ*D_MODEL,
        loc_Wqkv, loc_bqkv,
        p_qkv + (size_t)(NSEQ-1)*QKV_LD, (long)NSEQ*QKV_LD,
        NB, D_MODEL, 1.f, 0);
    attn_kernel<<<dim3(1, NHEAD, NB), 256>>>(p_qkv, p_sm_attn, 1, NSEQ-1);
    rowdot_kernel<<<D_MODEL, 128>>>(p_sm_attn, D_MODEL, loc_Wo, loc_bo,
                                    p_sm_tmp, D_MODEL, NB, D_MODEL, 1.f, 0);
    ln_kernel<<<NB, 256>>>(p_x + (size_t)(NSEQ-1)*D_MODEL, (long)NSEQ*D_MODEL,
                           p_sm_tmp, D_MODEL, p_sm_x, D_MODEL, (__nv_bfloat16*)0,
                           loc_ln1g, loc_ln1b);
    rowdot_kernel<<<FF_DIM, 128>>>(p_sm_x, D_MODEL, loc_W1, loc_b1,
                                   p_sm_ffh, FF_DIM, NB, D_MODEL, 1.f, 1);
    rowdot_kernel<<<D_MODEL, 128>>>(p_sm_ffh, FF_DIM, loc_W2, loc_b2,
                                    p_sm_tmp, D_MODEL, NB, FF_DIM, 1.f, 0);
    ln_kernel<<<NB, 256>>>(p_sm_x, D_MODEL, p_sm_tmp, D_MODEL,
                           p_sm_ctx, D_MODEL, (__nv_bfloat16*)0,
                           loc_ln2g, loc_ln2b);

    // 3) gate weights (sqrt(D)=32 folded in)
    rowdot_kernel<<<NEXP, 128>>>(p_sm_ctx, D_MODEL, gate_w, gate_b,
                                 out + 1, NEXP, NB, D_MODEL, 32.f, 0);

    // 4) stats / top-k / softmax / importance
    stats_kernel<<<1, 256>>>(out + 1, noise);

    // 5) mixture of responses -> g_x + h_x
    mix_kernel<<<(NROWS*D_MODEL/4 + 255)/256, 256>>>(responses);

    // 6) two encoder layers (bf16 tensor cores)
    for (int l = 0; l < 2; l++) {
        const __nv_bfloat16* Wqkv = p_hWqkv + (size_t)l*QKV_LD*D_MODEL;
        const float*         bqkv = enc_bqkv + (size_t)l*QKV_LD;
        const __nv_bfloat16* Wo   = p_hWo   + (size_t)l*D_MODEL*D_MODEL;
        const float*         bo   = enc_bo  + (size_t)l*D_MODEL;
        const float* g1   = enc_ln1g + (size_t)l*D_MODEL;
        const float* b1l  = enc_ln1b + (size_t)l*D_MODEL;
        const __nv_bfloat16* W1   = p_hW1   + (size_t)l*FF_DIM*D_MODEL;
        const float*         bb1  = enc_b1  + (size_t)l*FF_DIM;
        const __nv_bfloat16* W2   = p_hW2   + (size_t)l*D_MODEL*FF_DIM;
        const float*         bb2  = enc_b2  + (size_t)l*D_MODEL;
        const float* g2   = enc_ln2g + (size_t)l*D_MODEL;
        const float* b2l  = enc_ln2b + (size_t)l*D_MODEL;

        gemm_bf_f32_kernel<<<dim3(QKV_LD/128, NROWS/128), 256>>>(
            p_hx, Wqkv, bqkv, p_qkv, D_MODEL, QKV_LD);
        attn8_kernel<<<dim3(NSEQ/QT, NHEAD, NB), 256>>>(p_qkv, p_hattn);
        gemm_bf_f32_kernel<<<dim3(D_MODEL/128, NROWS/128), 256>>>(
            p_hattn, Wo, bo, p_tmp, D_MODEL, D_MODEL);
        ln_kernel<<<NROWS, 256>>>(p_x, D_MODEL, p_tmp, D_MODEL, p_x, D_MODEL, p_hx, g1, b1l);
        gemm_bf_bf_relu_kernel<<<dim3(FF_DIM/128, NROWS/128), 256>>>(
            p_hx, W1, bb1, p_hffh, D_MODEL, FF_DIM);
        gemm_bf_f32_kernel<<<dim3(D_MODEL/128, NROWS/128), 256>>>(
            p_hffh, W2, bb2, p_tmp, FF_DIM, D_MODEL);
        ln_kernel<<<NROWS, 256>>>(p_x, D_MODEL, p_tmp, D_MODEL, p_x, D_MODEL, p_hx, g2, b2l);
    }

    // 7) fused decoder GEMM + logsumexp (m-tiles adjacent for L2 reuse of dec_w)
    gemm_lse_bf_kernel<<<dim3(NROWS/128, NBLK_V), 256>>>(p_hx, p_hdec, D_MODEL);
    lse_reduce_kernel<<<NROWS, 128>>>();
    lablogit_kernel<<<dim3(NSEQ-1, NB), 128>>>(inputs, dec_w);
    final_kernel<<<1, 256>>>(out);
}

// round 8
// speedup vs baseline: 6.6825x; 1.0068x over previous
#include <cuda_runtime.h>
#include <cuda_bf16.h>
#include <math.h>
#include <stdint.h>

// ---------------- problem constants ----------------
#define D_MODEL 1024
#define NHEAD   16
#define DHEAD   64
#define FF_DIM  4096
#define NSEQ    256
#define NB      4
#define NTOK    50257
#define NEXP    2000
#define NKTOP   20
#define NROWS   (NB*NSEQ)      // 1024
#define QKV_LD  3072
#define NBLK_V  393            // ceil(50257/128)

// ---------------- scratch (static device memory; no allocation) ----------------
__device__ float g_x    [NROWS*D_MODEL];
__device__ float g_qkv  [NROWS*QKV_LD];
__device__ float g_tmp  [NROWS*D_MODEL];
__device__ float g_sm_attn[NB*D_MODEL];
__device__ float g_sm_x   [NB*D_MODEL];
__device__ float g_sm_tmp [NB*D_MODEL];
__device__ float g_sm_ctx [NB*D_MODEL];
__device__ float g_sm_ffh [NB*FF_DIM];
__device__ float g_pmax[NROWS*NBLK_V];
__device__ float g_psum[NROWS*NBLK_V];
__device__ float g_lse [NROWS];
__device__ float g_lab [NB*(NSEQ-1)];
__device__ float g_stats[32];   // [0..19] jw, [20] imp

// bf16 weight/activation mirrors
__device__ __align__(256) __nv_bfloat16 h_dec [NTOK*D_MODEL];
__device__ __align__(256) __nv_bfloat16 h_Wqkv[2*QKV_LD*D_MODEL];
__device__ __align__(256) __nv_bfloat16 h_Wo  [2*D_MODEL*D_MODEL];
__device__ __align__(256) __nv_bfloat16 h_W1  [2*FF_DIM*D_MODEL];
__device__ __align__(256) __nv_bfloat16 h_W2  [2*D_MODEL*FF_DIM];
__device__ __align__(256) __nv_bfloat16 h_x   [NROWS*D_MODEL];
__device__ __align__(256) __nv_bfloat16 h_attn[NROWS*D_MODEL];
__device__ __align__(256) __nv_bfloat16 h_ffh [NROWS*FF_DIM];

// ---------------- fp32 -> bf16 conversion (2x float4 per thread) ----------------
__global__ void f2h_kernel(const float* __restrict__ src, __nv_bfloat16* __restrict__ dst, int n4)
{
    int i = (blockIdx.x*blockDim.x + threadIdx.x) * 2;
    #pragma unroll
    for (int t = 0; t < 2; t++) {
        int j = i + t;
        if (j < n4) {
            float4 v = ((const float4*)src)[j];
            ((__nv_bfloat162*)dst)[2*j+0] = __floats2bfloat162_rn(v.x, v.y);
            ((__nv_bfloat162*)dst)[2*j+1] = __floats2bfloat162_rn(v.z, v.w);
        }
    }
}

// ---------------- embedding gather ----------------
__global__ void embed_kernel(const int* __restrict__ inputs, const float* __restrict__ emb)
{
    int r = blockIdx.x;
    int tok = inputs[r];
    const float4* src = (const float4*)(emb + (size_t)tok * D_MODEL);
    float4* dst = (float4*)(g_x + (size_t)r * D_MODEL);
    dst[threadIdx.x] = src[threadIdx.x];
}

// ================= cp.async / ldmatrix helpers =================
__device__ __forceinline__ void cp_async16(void* smem, const void* gmem)
{
    uint32_t s = (uint32_t)__cvta_generic_to_shared(smem);
    asm volatile("cp.async.ca.shared.global [%0], [%1], 16;\n" :: "r"(s), "l"(gmem));
}
__device__ __forceinline__ void cp_commit()
{
    asm volatile("cp.async.commit_group;\n" ::: "memory");
}
template<int N> __device__ __forceinline__ void cp_wait()
{
    asm volatile("cp.async.wait_group %0;\n" :: "n"(N) : "memory");
}
__device__ __forceinline__ void ldsm_x4(uint32_t& r0, uint32_t& r1, uint32_t& r2, uint32_t& r3,
                                        const void* smem)
{
    uint32_t a = (uint32_t)__cvta_generic_to_shared(smem);
    asm volatile("ldmatrix.sync.aligned.m8n8.x4.shared.b16 {%0,%1,%2,%3}, [%4];\n"
                 : "=r"(r0), "=r"(r1), "=r"(r2), "=r"(r3) : "r"(a));
}
__device__ __forceinline__ void ldsm_x2(uint32_t& r0, uint32_t& r1, const void* smem)
{
    uint32_t a = (uint32_t)__cvta_generic_to_shared(smem);
    asm volatile("ldmatrix.sync.aligned.m8n8.x2.shared.b16 {%0,%1}, [%2];\n"
                 : "=r"(r0), "=r"(r1) : "r"(a));
}

// ================= tf32 GEMM (loc KV path only) =================
__device__ __forceinline__ void mma_mainloop(
    float acc[4][4][4],
    const float* __restrict__ A, const float* __restrict__ W,
    int K, int m0, int n0)
{
    __shared__ uint32_t As[2][128][20];
    __shared__ uint32_t Bs[2][128][20];
    int tid  = threadIdx.x;
    int lane = tid & 31, wid = tid >> 5;
    int wm = wid >> 2, wn = wid & 3;
    int g = lane >> 2, tig = lane & 3;

    int r0c = tid >> 2,         c0c = (tid & 3) << 2;
    int r1c = (tid + 256) >> 2, c1c = (tid & 3) << 2;
    const float* pa0 = A + (size_t)(m0 + r0c)*K + c0c;
    const float* pa1 = A + (size_t)(m0 + r1c)*K + c1c;
    const float* pb0 = W + (size_t)(n0 + r0c)*K + c0c;
    const float* pb1 = W + (size_t)(n0 + r1c)*K + c1c;

    int niter = K >> 4;
    cp_async16(&As[0][r0c][c0c], pa0);
    cp_async16(&As[0][r1c][c1c], pa1);
    cp_async16(&Bs[0][r0c][c0c], pb0);
    cp_async16(&Bs[0][r1c][c1c], pb1);
    cp_commit();

    for (int it = 0; it < niter; it++) {
        int st = it & 1;
        if (it + 1 < niter) {
            int off = (it + 1) << 4;
            int sn = st ^ 1;
            cp_async16(&As[sn][r0c][c0c], pa0 + off);
            cp_async16(&As[sn][r1c][c1c], pa1 + off);
            cp_async16(&Bs[sn][r0c][c0c], pb0 + off);
            cp_async16(&Bs[sn][r1c][c1c], pb1 + off);
            cp_commit();
            cp_wait<1>();
        } else {
            cp_wait<0>();
        }
        __syncthreads();
        #pragma unroll
        for (int ks = 0; ks < 16; ks += 8) {
            uint32_t af[4][4], bf[4][2];
            #pragma unroll
            for (int mt = 0; mt < 4; mt++) {
                int r0 = wm*64 + mt*16;
                af[mt][0] = As[st][r0+g  ][ks+tig  ];
                af[mt][1] = As[st][r0+g+8][ks+tig  ];
                af[mt][2] = As[st][r0+g  ][ks+tig+4];
                af[mt][3] = As[st][r0+g+8][ks+tig+4];
            }
            #pragma unroll
            for (int nt = 0; nt < 4; nt++) {
                int c0 = wn*32 + nt*8;
                bf[nt][0] = Bs[st][c0+g][ks+tig  ];
                bf[nt][1] = Bs[st][c0+g][ks+tig+4];
            }
            #pragma unroll
            for (int mt = 0; mt < 4; mt++)
                #pragma unroll
                for (int nt = 0; nt < 4; nt++) {
                    asm volatile(
                        "mma.sync.aligned.m16n8k8.row.col.f32.tf32.tf32.f32 "
                        "{%0,%1,%2,%3}, {%4,%5,%6,%7}, {%8,%9}, {%0,%1,%2,%3};\n"
                        : "+f"(acc[mt][nt][0]), "+f"(acc[mt][nt][1]),
                          "+f"(acc[mt][nt][2]), "+f"(acc[mt][nt][3])
                        : "r"(af[mt][0]), "r"(af[mt][1]),
                          "r"(af[mt][2]), "r"(af[mt][3]),
                          "r"(bf[nt][0]), "r"(bf[nt][1]));
                }
        }
        __syncthreads();
    }
}

__global__ __launch_bounds__(256, 2) void gemm_tc_kernel(
    const float* __restrict__ A, const float* __restrict__ W,
    const float* __restrict__ bias, float* __restrict__ C,
    int K, int ldC)
{
    float acc[4][4][4];
    #pragma unroll
    for (int a = 0; a < 4; a++)
        #pragma unroll
        for (int b = 0; b < 4; b++)
            #pragma unroll
            for (int c = 0; c < 4; c++) acc[a][b][c] = 0.f;

    int m0 = blockIdx.y * 128, n0 = blockIdx.x * 128;
    mma_mainloop(acc, A, W, K, m0, n0);

    int tid = threadIdx.x;
    int lane = tid & 31, wid = tid >> 5;
    int wm = wid >> 2, wn = wid & 3;
    int g = lane >> 2, tig = lane & 3;
    int rowb = m0 + wm*64;
    int colb = n0 + wn*32;
    #pragma unroll
    for (int nt = 0; nt < 4; nt++) {
        int c = colb + nt*8 + 2*tig;
        float b0 = bias[c], b1 = bias[c+1];
        #pragma unroll
        for (int mt = 0; mt < 4; mt++) {
            int r = rowb + mt*16 + g;
            *(float2*)(C + (size_t)r*ldC + c)     = make_float2(acc[mt][nt][0]+b0, acc[mt][nt][1]+b1);
            *(float2*)(C + (size_t)(r+8)*ldC + c) = make_float2(acc[mt][nt][2]+b0, acc[mt][nt][3]+b1);
        }
    }
}

// ================= bf16 GEMM core (m16n8k16, ldmatrix), BK=32 =================
__device__ __forceinline__ void mma_bf16_mainloop(
    float acc[4][4][4],
    const __nv_bfloat16* __restrict__ A, const __nv_bfloat16* __restrict__ W,
    int K, int m0, int n0, int nmax)
{
    __shared__ uint32_t As[2][128][20];
    __shared__ uint32_t Bs[2][128][20];
    int tid  = threadIdx.x;
    int lane = tid & 31, wid = tid >> 5;
    int wm = wid >> 2, wn = wid & 3;

    int a_row = (lane & 7) + ((lane >> 3) & 1) * 8;
    int a_wrd = (lane >> 4) * 4;
    int b_row = lane & 7;
    int b_wrd = ((lane >> 3) & 1) * 4;

    int r0c = tid >> 2, r1c = r0c + 64;
    int cw = (tid & 3) * 4;   // word col
    int ce = (tid & 3) * 8;   // element col
    int nr0 = n0 + r0c; nr0 = (nr0 < nmax) ? nr0 : (nmax - 1);
    int nr1 = n0 + r1c; nr1 = (nr1 < nmax) ? nr1 : (nmax - 1);
    const __nv_bfloat16* pa0 = A + (size_t)(m0 + r0c)*K + ce;
    const __nv_bfloat16* pa1 = A + (size_t)(m0 + r1c)*K + ce;
    const __nv_bfloat16* pb0 = W + (size_t)nr0*K + ce;
    const __nv_bfloat16* pb1 = W + (size_t)nr1*K + ce;

    int niter = K >> 5;
    cp_async16(&As[0][r0c][cw], pa0);
    cp_async16(&As[0][r1c][cw], pa1);
    cp_async16(&Bs[0][r0c][cw], pb0);
    cp_async16(&Bs[0][r1c][cw], pb1);
    cp_commit();

    for (int it = 0; it < niter; it++) {
        int st = it & 1;
        if (it + 1 < niter) {
            int off = (it + 1) << 5;
            int sn = st ^ 1;
            cp_async16(&As[sn][r0c][cw], pa0 + off);
            cp_async16(&As[sn][r1c][cw], pa1 + off);
            cp_async16(&Bs[sn][r0c][cw], pb0 + off);
            cp_async16(&Bs[sn][r1c][cw], pb1 + off);
            cp_commit();
            cp_wait<1>();
        } else {
            cp_wait<0>();
        }
        __syncthreads();
        #pragma unroll
        for (int ks = 0; ks < 2; ks++) {
            int kb = ks*8;
            uint32_t af[4][4], bf[4][2];
            #pragma unroll
            for (int mt = 0; mt < 4; mt++) {
                int r0 = wm*64 + mt*16;
                ldsm_x4(af[mt][0], af[mt][1], af[mt][2], af[mt][3],
                        &As[st][r0 + a_row][kb + a_wrd]);
            }
            #pragma unroll
            for (int nt = 0; nt < 4; nt++) {
                int c0 = wn*32 + nt*8;
                ldsm_x2(bf[nt][0], bf[nt][1],
                        &Bs[st][c0 + b_row][kb + b_wrd]);
            }
            #pragma unroll
            for (int mt = 0; mt < 4; mt++)
                #pragma unroll
                for (int nt = 0; nt < 4; nt++) {
                    asm volatile(
                        "mma.sync.aligned.m16n8k16.row.col.f32.bf16.bf16.f32 "
                        "{%0,%1,%2,%3}, {%4,%5,%6,%7}, {%8,%9}, {%0,%1,%2,%3};\n"
                        : "+f"(acc[mt][nt][0]), "+f"(acc[mt][nt][1]),
                          "+f"(acc[mt][nt][2]), "+f"(acc[mt][nt][3])
                        : "r"(af[mt][0]), "r"(af[mt][1]),
                          "r"(af[mt][2]), "r"(af[mt][3]),
                          "r"(bf[nt][0]), "r"(bf[nt][1]));
                }
        }
        __syncthreads();
    }
}

// bf16 GEMM -> fp32 out (+bias)
__global__ __launch_bounds__(256, 2) void gemm_bf_f32_kernel(
    const __nv_bfloat16* __restrict__ A, const __nv_bfloat16* __restrict__ W,
    const float* __restrict__ bias, float* __restrict__ C, int K, int ldC)
{
    float acc[4][4][4];
    #pragma unroll
    for (int a = 0; a < 4; a++)
        #pragma unroll
        for (int b = 0; b < 4; b++)
            #pragma unroll
            for (int c = 0; c < 4; c++) acc[a][b][c] = 0.f;
    int m0 = blockIdx.y * 128, n0 = blockIdx.x * 128;
    mma_bf16_mainloop(acc, A, W, K, m0, n0, 0x40000000);

    int tid = threadIdx.x;
    int lane = tid & 31, wid = tid >> 5;
    int wm = wid >> 2, wn = wid & 3;
    int g = lane >> 2, tig = lane & 3;
    int rowb = m0 + wm*64, colb = n0 + wn*32;
    #pragma unroll
    for (int nt = 0; nt < 4; nt++) {
        int c = colb + nt*8 + 2*tig;
        float b0 = bias[c], b1 = bias[c+1];
        #pragma unroll
        for (int mt = 0; mt < 4; mt++) {
            int r = rowb + mt*16 + g;
            *(float2*)(C + (size_t)r*ldC + c)     = make_float2(acc[mt][nt][0]+b0, acc[mt][nt][1]+b1);
            *(float2*)(C + (size_t)(r+8)*ldC + c) = make_float2(acc[mt][nt][2]+b0, acc[mt][nt][3]+b1);
        }
    }
}

// bf16 GEMM -> bf16 out (+bias, +relu)  (FF1 path)
__global__ __launch_bounds__(256, 2) void gemm_bf_bf_relu_kernel(
    const __nv_bfloat16* __restrict__ A, const __nv_bfloat16* __restrict__ W,
    const float* __restrict__ bias, __nv_bfloat16* __restrict__ C, int K, int ldC)
{
    float acc[4][4][4];
    #pragma unroll
    for (int a = 0; a < 4; a++)
        #pragma unroll
        for (int b = 0; b < 4; b++)
            #pragma unroll
            for (int c = 0; c < 4; c++) acc[a][b][c] = 0.f;
    int m0 = blockIdx.y * 128, n0 = blockIdx.x * 128;
    mma_bf16_mainloop(acc, A, W, K, m0, n0, 0x40000000);

    int tid = threadIdx.x;
    int lane = tid & 31, wid = tid >> 5;
    int wm = wid >> 2, wn = wid & 3;
    int g = lane >> 2, tig = lane & 3;
    int rowb = m0 + wm*64, colb = n0 + wn*32;
    #pragma unroll
    for (int nt = 0; nt < 4; nt++) {
        int c = colb + nt*8 + 2*tig;
        float b0 = bias[c], b1 = bias[c+1];
        #pragma unroll
        for (int mt = 0; mt < 4; mt++) {
            int r = rowb + mt*16 + g;
            float v0 = fmaxf(acc[mt][nt][0]+b0, 0.f);
            float v1 = fmaxf(acc[mt][nt][1]+b1, 0.f);
            float v2 = fmaxf(acc[mt][nt][2]+b0, 0.f);
            float v3 = fmaxf(acc[mt][nt][3]+b1, 0.f);
            *(__nv_bfloat162*)(C + (size_t)r*ldC + c)     = __floats2bfloat162_rn(v0, v1);
            *(__nv_bfloat162*)(C + (size_t)(r+8)*ldC + c) = __floats2bfloat162_rn(v2, v3);
        }
    }
}

// decoder bf16 GEMM + fused online-lse partials (m-tiles adjacent for L2 reuse)
__global__ __launch_bounds__(256, 2) void gemm_lse_bf_kernel(
    const __nv_bfloat16* __restrict__ A, const __nv_bfloat16* __restrict__ W, int K)
{
    float acc[4][4][4];
    #pragma unroll
    for (int a = 0; a < 4; a++)
        #pragma unroll
        for (int b = 0; b < 4; b++)
            #pragma unroll
            for (int c = 0; c < 4; c++) acc[a][b][c] = 0.f;
    int m0 = blockIdx.x * 128, n0 = blockIdx.y * 128;
    int nblk = blockIdx.y;
    mma_bf16_mainloop(acc, A, W, K, m0, n0, NTOK);

    __shared__ float red_m[4][128];
    __shared__ float red_s[4][128];
    int tid = threadIdx.x;
    int lane = tid & 31, wid = tid >> 5;
    int wm = wid >> 2, wn = wid & 3;
    int g = lane >> 2, tig = lane & 3;
    int colb = n0 + wn*32;

    #pragma unroll
    for (int mt = 0; mt < 4; mt++) {
        #pragma unroll
        for (int h = 0; h < 2; h++) {
            float m = -INFINITY;
            #pragma unroll
            for (int nt = 0; nt < 4; nt++) {
                int c = colb + nt*8 + 2*tig;
                if (c     < NTOK) m = fmaxf(m, acc[mt][nt][h*2+0]);
                if (c + 1 < NTOK) m = fmaxf(m, acc[mt][nt][h*2+1]);
            }
            m = fmaxf(m, __shfl_xor_sync(0xffffffffu, m, 1));
            m = fmaxf(m, __shfl_xor_sync(0xffffffffu, m, 2));
            float s = 0.f;
            #pragma unroll
            for (int nt = 0; nt < 4; nt++) {
                int c = colb + nt*8 + 2*tig;
                if (c     < NTOK) s += __expf(acc[mt][nt][h*2+0] - m);
                if (c + 1 < NTOK) s += __expf(acc[mt][nt][h*2+1] - m);
            }
            s += __shfl_xor_sync(0xffffffffu, s, 1);
            s += __shfl_xor_sync(0xffffffffu, s, 2);
            if (tig == 0) {
                int lr = wm*64 + mt*16 + h*8 + g;
                red_m[wn][lr] = m;
                red_s[wn][lr] = s;
            }
        }
    }
    __syncthreads();
    if (tid < 128) {
        float m0v = red_m[0][tid], m1v = red_m[1][tid];
        float m2v = red_m[2][tid], m3v = red_m[3][tid];
        float mx = fmaxf(fmaxf(m0v, m1v), fmaxf(m2v, m3v));
        float s = red_s[0][tid]*__expf(m0v-mx) + red_s[1][tid]*__expf(m1v-mx)
                + red_s[2][tid]*__expf(m2v-mx) + red_s[3][tid]*__expf(m3v-mx);
        int row = m0 + tid;
        g_pmax[(size_t)row*NBLK_V + nblk] = mx;
        g_psum[(size_t)row*NBLK_V + nblk] = s;
    }
}

__global__ void lse_reduce_kernel()
{
    int r = blockIdx.x, tid = threadIdx.x;
    __shared__ float red[128];
    float m = -INFINITY;
    for (int i = tid; i < NBLK_V; i += 128) m = fmaxf(m, g_pmax[(size_t)r*NBLK_V + i]);
    red[tid] = m; __syncthreads();
    for (int s = 64; s > 0; s >>= 1) { if (tid < s) red[tid] = fmaxf(red[tid], red[tid+s]); __syncthreads(); }
    float gm = red[0]; __syncthreads();
    double sum = 0.0;
    for (int i = tid; i < NBLK_V; i += 128)
        sum += (double)g_psum[(size_t)r*NBLK_V + i] * exp((double)g_pmax[(size_t)r*NBLK_V + i] - (double)gm);
    __shared__ double redd[128];
    redd[tid] = sum; __syncthreads();
    for (int s = 64; s > 0; s >>= 1) { if (tid < s) redd[tid] += redd[tid+s]; __syncthreads(); }
    if (tid == 0) g_lse[r] = gm + (float)log(redd[0]);
}

// ---------------- small-M GEMM ----------------
__global__ void rowdot_kernel(
    const float* __restrict__ A, long strideA,
    const float* __restrict__ W, const float* __restrict__ bias,
    float* __restrict__ C, long strideC,
    int M, int K, float alpha, int relu)
{
    int n = blockIdx.x;
    int tid = threadIdx.x;   // 128
    const float* w = W + (size_t)n * K;
    __shared__ float red[128];
    for (int m = 0; m < M; m++) {
        const float* a = A + (size_t)m * strideA;
        float s = 0.f;
        for (int k = tid; k < K; k += 128) s += a[k]*w[k];
        red[tid] = s; __syncthreads();
        for (int st = 64; st > 0; st >>= 1) { if (tid < st) red[tid] += red[tid+st]; __syncthreads(); }
        if (tid == 0) {
            float v = alpha*red[0] + (bias ? bias[n] : 0.f);
            if (relu) v = fmaxf(v, 0.f);
            C[(size_t)m*strideC + n] = v;
        }
        __syncthreads();
    }
}

// ---------------- attention, 8 queries per block, bf16 out ----------------
#define QT 8
__global__ __launch_bounds__(256) void attn8_kernel(
    const float* __restrict__ qkv, __nv_bfloat16* __restrict__ out)
{
    int qt = blockIdx.x, h = blockIdx.y, b = blockIdx.z;
    int tid = threadIdx.x;
    __shared__ float qs[QT][DHEAD];
    __shared__ float sc[QT][NSEQ];
    __shared__ float den[QT];
    const float* base = qkv + (size_t)b*NSEQ*QKV_LD;
    if (tid < 128) {
        int q = tid >> 4;
        int c = (tid & 15) * 4;
        *(float4*)&qs[q][c] =
            *(const float4*)(base + (size_t)(qt*QT+q)*QKV_LD + h*DHEAD + c);
    }
    __syncthreads();
    {
        int j = tid;
        float4 kreg[16];
        const float4* kr = (const float4*)(base + (size_t)j*QKV_LD + D_MODEL + h*DHEAD);
        #pragma unroll
        for (int t = 0; t < 16; t++) kreg[t] = kr[t];
        #pragma unroll
        for (int q = 0; q < QT; q++) {
            float d = 0.f;
            #pragma unroll
            for (int t = 0; t < 16; t++) {
                float4 q4 = *(float4*)&qs[q][t*4];
                d += q4.x*kreg[t].x + q4.y*kreg[t].y + q4.z*kreg[t].z + q4.w*kreg[t].w;
            }
            sc[q][j] = d * 0.125f;
        }
    }
    __syncthreads();
    {
        int w = tid >> 5, lane = tid & 31;
        float v[8];
        float m = -INFINITY;
        #pragma unroll
        for (int t = 0; t < 8; t++) { v[t] = sc[w][lane + 32*t]; m = fmaxf(m, v[t]); }
        #pragma unroll
        for (int o = 16; o; o >>= 1) m = fmaxf(m, __shfl_xor_sync(0xffffffffu, m, o));
        float s = 0.f;
        #pragma unroll
        for (int t = 0; t < 8; t++) { v[t] = expf(v[t]-m); s += v[t]; }
        #pragma unroll
        for (int o = 16; o; o >>= 1) s += __shfl_xor_sync(0xffffffffu, s, o);
        #pragma unroll
        for (int t = 0; t < 8; t++) sc[w][lane + 32*t] = v[t];
        if (lane == 0) den[w] = s;
    }
    __syncthreads();
    {
        int d = tid & 63, qp = tid >> 6;
        int q0 = qp*2, q1 = qp*2+1;
        const float* vb = base + 2*D_MODEL + h*DHEAD + d;
        float a0 = 0.f, a1 = 0.f;
        #pragma unroll 8
        for (int j = 0; j < NSEQ; j++) {
            float v = vb[(size_t)j*QKV_LD];
            a0 += sc[q0][j]*v;
            a1 += sc[q1][j]*v;
        }
        out[((size_t)(b*NSEQ + qt*QT + q0))*D_MODEL + h*DHEAD + d] = __float2bfloat16(a0/den[q0]);
        out[((size_t)(b*NSEQ + qt*QT + q1))*D_MODEL + h*DHEAD + d] = __float2bfloat16(a1/den[q1]);
    }
}

// ---------------- loc attention (single query per (h,b)), fp32 out ----------------
__global__ __launch_bounds__(256) void attn_kernel(
    const float* __restrict__ qkv, float* __restrict__ out, int nq, int sq_base)
{
    int qi = blockIdx.x, h = blockIdx.y, b = blockIdx.z;
    int sq = sq_base + qi;
    int tid = threadIdx.x;
    __shared__ float4 qrow[DHEAD/4];
    __shared__ float sc[NSEQ];
    __shared__ float red[256];
    __shared__ float sden;
    __shared__ float osum[4][DHEAD];
    const float* base = qkv + (size_t)b * NSEQ * QKV_LD;
    if (tid < DHEAD/4)
        qrow[tid] = ((const float4*)(base + (size_t)sq*QKV_LD + h*DHEAD))[tid];
    __syncthreads();
    {
        const float4* krow = (const float4*)(base + (size_t)tid*QKV_LD + D_MODEL + h*DHEAD);
        float d = 0.f;
        #pragma unroll
        for (int t = 0; t < DHEAD/4; t++) {
            float4 k4 = krow[t];
            float4 q4 = qrow[t];
            d += q4.x*k4.x + q4.y*k4.y + q4.z*k4.z + q4.w*k4.w;
        }
        sc[tid] = d * 0.125f;
    }
    __syncthreads();
    red[tid] = sc[tid]; __syncthreads();
    for (int s = 128; s > 0; s >>= 1) { if (tid < s) red[tid] = fmaxf(red[tid], red[tid+s]); __syncthreads(); }
    float mx = red[0]; __syncthreads();
    float e = expf(sc[tid] - mx);
    red[tid] = e; __syncthreads();
    for (int s = 128; s > 0; s >>= 1) { if (tid < s) red[tid] += red[tid+s]; __syncthreads(); }
    if (tid == 0) sden = red[0];
    __syncthreads();
    sc[tid] = e;
    __syncthreads();
    int d = tid & 63, g = tid >> 6;
    const float* vb = base + 2*D_MODEL + h*DHEAD + d;
    float o = 0.f;
    for (int j = g*64; j < (g+1)*64; j++) o += sc[j] * vb[(size_t)j*QKV_LD];
    osum[g][d] = o; __syncthreads();
    if (tid < DHEAD) {
        float r = (osum[0][tid]+osum[1][tid]+osum[2][tid]+osum[3][tid]) / sden;
        out[((size_t)(b*nq + qi))*D_MODEL + h*DHEAD + tid] = r;
    }
}

// ---------------- residual + layernorm (fp32 out + optional bf16 mirror) ----------
__global__ void ln_kernel(
    const float* __restrict__ in1, long s1,
    const float* __restrict__ in2, long s2,
    float* __restrict__ out, long so,
    __nv_bfloat16* __restrict__ outh,
    const float* __restrict__ gam, const float* __restrict__ bet)
{
    int r = blockIdx.x, tid = threadIdx.x;
    __shared__ float xr[D_MODEL];
    __shared__ float red[256];
    const float* p1 = in1 + (size_t)r*s1;
    const float* p2 = in2 + (size_t)r*s2;
    float ls = 0.f;
    for (int d = tid; d < D_MODEL; d += 256) { float v = p1[d]+p2[d]; xr[d] = v; ls += v; }
    red[tid] = ls; __syncthreads();
    for (int s = 128; s > 0; s >>= 1) { if (tid < s) red[tid] += red[tid+s]; __syncthreads(); }
    float mean = red[0] * (1.f/D_MODEL); __syncthreads();
    float lv = 0.f;
    for (int d = tid; d < D_MODEL; d += 256) { float t = xr[d]-mean; lv += t*t; }
    red[tid] = lv; __syncthreads();
    for (int s = 128; s > 0; s >>= 1) { if (tid < s) red[tid] += red[tid+s]; __syncthreads(); }
    float rstd = 1.f / sqrtf(red[0]*(1.f/D_MODEL) + 1e-5f);
    for (int d = tid; d < D_MODEL; d += 256) {
        float v = (xr[d]-mean)*rstd*gam[d] + bet[d];
        out[(size_t)r*so + d] = v;
        if (outh) outh[(size_t)r*D_MODEL + d] = __float2bfloat16(v);
    }
}

// ---------------- gating statistics + top-k + softmax + importance ----------------
__global__ void stats_kernel(const float* __restrict__ w, const float* __restrict__ noise)
{
    __shared__ float tot[NEXP];
    __shared__ double redd[256];
    __shared__ float fv[256];
    __shared__ int   fi[256];
    __shared__ float topv[NKTOP];
    __shared__ double smean, sstd;
    int tid = threadIdx.x;
    double ls = 0.0;
    for (int n = tid; n < NEXP; n += 256) {
        float f = 0.25f*(w[n] + w[NEXP+n] + w[2*NEXP+n] + w[3*NEXP+n]);
        tot[n] = f; ls += (double)f;
    }
    redd[tid] = ls; __syncthreads();
    for (int s = 128; s > 0; s >>= 1) { if (tid < s) redd[tid] += redd[tid+s]; __syncthreads(); }
    if (tid == 0) smean = redd[0] / NEXP;
    __syncthreads();
    double mfm = smean;
    ls = 0.0;
    for (int n = tid; n < NEXP; n += 256) { double t = (double)tot[n]-mfm; ls += t*t; }
    redd[tid] = ls; __syncthreads();
    for (int s = 128; s > 0; s >>= 1) { if (tid < s) redd[tid] += redd[tid+s]; __syncthreads(); }
    if (tid == 0) sstd = sqrt(redd[0] / (NEXP-1));
    __syncthreads();
    float stdfm = (float)sstd;
    for (int n = tid; n < NEXP; n += 256) tot[n] = tot[n] + noise[n]*stdfm;
    __syncthreads();
    ls = 0.0;
    for (int n = tid; n < NEXP; n += 256) ls += (double)tot[n];
    redd[tid] = ls; __syncthreads();
    for (int s = 128; s > 0; s >>= 1) { if (tid < s) redd[tid] += redd[tid+s]; __syncthreads(); }
    if (tid == 0) smean = redd[0] / NEXP;
    __syncthreads();
    double mt = smean;
    ls = 0.0;
    for (int n = tid; n < NEXP; n += 256) { double t = (double)tot[n]-mt; ls += t*t; }
    redd[tid] = ls; __syncthreads();
    for (int s = 128; s > 0; s >>= 1) { if (tid < s) redd[tid] += redd[tid+s]; __syncthreads(); }
    if (tid == 0) {
        double st = sqrt(redd[0] / (NEXP-1));
        double ratio = st / mt;
        g_stats[20] = (float)(0.1 * ratio * ratio);
    }
    __syncthreads();
    for (int it = 0; it < NKTOP; it++) {
        float bv = -INFINITY; int bi = 0x7fffffff;
        for (int n = tid; n < NEXP; n += 256) {
            float v = tot[n];
            if (v > bv || (v == bv && n < bi)) { bv = v; bi = n; }
        }
        fv[tid] = bv; fi[tid] = bi; __syncthreads();
        for (int s = 128; s > 0; s >>= 1) {
            if (tid < s) {
                float v2 = fv[tid+s]; int i2 = fi[tid+s];
                if (v2 > fv[tid] || (v2 == fv[tid] && i2 < fi[tid])) { fv[tid] = v2; fi[tid] = i2; }
            }
            __syncthreads();
        }
        if (tid == 0) { topv[it] = fv[0]; tot[fi[0]] = -INFINITY; }
        __syncthreads();
    }
    if (tid == 0) {
        float m = topv[0];
        float s = 0.f;
        float e[NKTOP];
        for (int k = 0; k < NKTOP; k++) { e[k] = expf(topv[k]-m); s += e[k]; }
        for (int k = 0; k < NKTOP; k++) g_stats[k] = e[k]/s;
    }
}

// ---------------- response mixture (fp32 + bf16 mirror) ----------------
__global__ void mix_kernel(const float* __restrict__ responses)
{
    __shared__ float w[NKTOP];
    if (threadIdx.x < NKTOP) w[threadIdx.x] = g_stats[threadIdx.x];
    __syncthreads();
    int i = blockIdx.x*blockDim.x + threadIdx.x;
    if (i < (NROWS*D_MODEL)/4) {
        float4 s = make_float4(0.f, 0.f, 0.f, 0.f);
        #pragma unroll
        for (int k = 0; k < NKTOP; k++) {
            float4 v = ((const float4*)responses)[(size_t)k*((NROWS*D_MODEL)/4) + i];
            float wk = w[k];
            s.x += wk*v.x; s.y += wk*v.y; s.z += wk*v.z; s.w += wk*v.w;
        }
        ((float4*)g_x)[i] = s;
        ((__nv_bfloat162*)h_x)[2*i+0] = __floats2bfloat162_rn(s.x, s.y);
        ((__nv_bfloat162*)h_x)[2*i+1] = __floats2bfloat162_rn(s.z, s.w);
    }
}

// ---------------- label logit + final loss ----------------
__global__ void lablogit_kernel(const int* __restrict__ inputs, const float* __restrict__ dec_w)
{
    int s = blockIdx.x, b = blockIdx.y, tid = threadIdx.x;
    int lbl = inputs[b*NSEQ + s + 1];
    const float* a = g_x + ((size_t)(b*NSEQ + s))*D_MODEL;
    const float* wp = dec_w + (size_t)lbl*D_MODEL;
    __shared__ float red[128];
    float acc = 0.f;
    for (int k = tid; k < D_MODEL; k += 128) acc += a[k]*wp[k];
    red[tid] = acc; __syncthreads();
    for (int st = 64; st > 0; st >>= 1) { if (tid < st) red[tid] += red[tid+st]; __syncthreads(); }
    if (tid == 0) g_lab[b*(NSEQ-1)+s] = red[0];
}

__global__ void final_kernel(float* __restrict__ out)
{
    __shared__ double red[256];
    int tid = threadIdx.x;
    double s = 0.0;
    for (int i = tid; i < NB*(NSEQ-1); i += 256) {
        int b = i/(NSEQ-1), sp = i%(NSEQ-1);
        s += (double)g_lab[i] - (double)g_lse[b*NSEQ+sp];
    }
    red[tid] = s; __syncthreads();
    for (int st = 128; st > 0; st >>= 1) { if (tid < st) red[tid] += red[tid+st]; __syncthreads(); }
    if (tid == 0) {
        double ce = -red[0] / (double)(NB*(NSEQ-1));
        out[0] = (float)(ce + (double)g_stats[20]);
    }
}

// ---------------- host driver ----------------
extern "C" void kernel_launch(void* const* d_in, const int* in_sizes, int n_in,
                              void* d_out, int out_size)
{
    (void)in_sizes; (void)n_in; (void)out_size;
    const int*   inputs    = (const int*)  d_in[0];
    const float* responses = (const float*)d_in[1];
    const float* noise     = (const float*)d_in[2];
    const float* emb       = (const float*)d_in[3];
    const float* loc_Wqkv  = (const float*)d_in[4];
    const float* loc_bqkv  = (const float*)d_in[5];
    const float* loc_Wo    = (const float*)d_in[6];
    const float* loc_bo    = (const float*)d_in[7];
    const float* loc_ln1g  = (const float*)d_in[8];
    const float* loc_ln1b  = (const float*)d_in[9];
    const float* loc_W1    = (const float*)d_in[10];
    const float* loc_b1    = (const float*)d_in[11];
    const float* loc_W2    = (const float*)d_in[12];
    const float* loc_b2    = (const float*)d_in[13];
    const float* loc_ln2g  = (const float*)d_in[14];
    const float* loc_ln2b  = (const float*)d_in[15];
    const float* enc_Wqkv  = (const float*)d_in[16];
    const float* enc_bqkv  = (const float*)d_in[17];
    const float* enc_Wo    = (const float*)d_in[18];
    const float* enc_bo    = (const float*)d_in[19];
    const float* enc_ln1g  = (const float*)d_in[20];
    const float* enc_ln1b  = (const float*)d_in[21];
    const float* enc_W1    = (const float*)d_in[22];
    const float* enc_b1    = (const float*)d_in[23];
    const float* enc_W2    = (const float*)d_in[24];
    const float* enc_b2    = (const float*)d_in[25];
    const float* enc_ln2g  = (const float*)d_in[26];
    const float* enc_ln2b  = (const float*)d_in[27];
    const float* gate_w    = (const float*)d_in[28];
    const float* gate_b    = (const float*)d_in[29];
    const float* dec_w     = (const float*)d_in[30];
    float* out = (float*)d_out;

    float *p_x, *p_qkv, *p_tmp;
    float *p_sm_attn, *p_sm_x, *p_sm_tmp, *p_sm_ctx, *p_sm_ffh;
    __nv_bfloat16 *p_hdec, *p_hWqkv, *p_hWo, *p_hW1, *p_hW2, *p_hx, *p_hattn, *p_hffh;
    cudaGetSymbolAddress((void**)&p_x, g_x);
    cudaGetSymbolAddress((void**)&p_qkv, g_qkv);
    cudaGetSymbolAddress((void**)&p_tmp, g_tmp);
    cudaGetSymbolAddress((void**)&p_sm_attn, g_sm_attn);
    cudaGetSymbolAddress((void**)&p_sm_x, g_sm_x);
    cudaGetSymbolAddress((void**)&p_sm_tmp, g_sm_tmp);
    cudaGetSymbolAddress((void**)&p_sm_ctx, g_sm_ctx);
    cudaGetSymbolAddress((void**)&p_sm_ffh, g_sm_ffh);
    cudaGetSymbolAddress((void**)&p_hdec, h_dec);
    cudaGetSymbolAddress((void**)&p_hWqkv, h_Wqkv);
    cudaGetSymbolAddress((void**)&p_hWo, h_Wo);
    cudaGetSymbolAddress((void**)&p_hW1, h_W1);
    cudaGetSymbolAddress((void**)&p_hW2, h_W2);
    cudaGetSymbolAddress((void**)&p_hx, h_x);
    cudaGetSymbolAddress((void**)&p_hattn, h_attn);
    cudaGetSymbolAddress((void**)&p_hffh, h_ffh);

    // ---- capture-forked side stream for weight conversions ----
    cudaStream_t s2;
    cudaStreamCreateWithFlags(&s2, cudaStreamNonBlocking);
    cudaEvent_t evFork, evEnc, evDec;
    cudaEventCreateWithFlags(&evFork, cudaEventDisableTiming);
    cudaEventCreateWithFlags(&evEnc,  cudaEventDisableTiming);
    cudaEventCreateWithFlags(&evDec,  cudaEventDisableTiming);

    cudaEventRecord(evFork, 0);
    cudaStreamWaitEvent(s2, evFork, 0);

    // s2: encoder weight conversions first (needed earlier), then decoder
    f2h_kernel<<<(2*QKV_LD*D_MODEL/8 + 255)/256, 256, 0, s2>>>(enc_Wqkv, p_hWqkv, 2*QKV_LD*D_MODEL/4);
    f2h_kernel<<<(2*D_MODEL*D_MODEL/8 + 255)/256, 256, 0, s2>>>(enc_Wo, p_hWo, 2*D_MODEL*D_MODEL/4);
    f2h_kernel<<<(2*FF_DIM*D_MODEL/8 + 255)/256, 256, 0, s2>>>(enc_W1, p_hW1, 2*FF_DIM*D_MODEL/4);
    f2h_kernel<<<(2*D_MODEL*FF_DIM/8 + 255)/256, 256, 0, s2>>>(enc_W2, p_hW2, 2*D_MODEL*FF_DIM/4);
    cudaEventRecord(evEnc, s2);
    f2h_kernel<<<(NTOK*D_MODEL/8 + 255)/256, 256, 0, s2>>>(dec_w, p_hdec, NTOK*D_MODEL/4);
    cudaEventRecord(evDec, s2);

    // default stream: embed + loc layer + gating (overlapped with f2h)
    embed_kernel<<<NROWS, 256>>>(inputs, emb);
    gemm_tc_kernel<<<dim3(2048/128, NROWS/128), 256>>>(
        p_x, loc_Wqkv + (size_t)D_MODEL*D_MODEL, loc_bqkv + D_MODEL,
        p_qkv + D_MODEL, D_MODEL, QKV_LD);
    rowdot_kernel<<<D_MODEL, 128>>>(
        p_x + (size_t)(NSEQ-1)*D_MODEL, (long)NSEQ*D_MODEL,
        loc_Wqkv, loc_bqkv,
        p_qkv + (size_t)(NSEQ-1)*QKV_LD, (long)NSEQ*QKV_LD,
        NB, D_MODEL, 1.f, 0);
    attn_kernel<<<dim3(1, NHEAD, NB), 256>>>(p_qkv, p_sm_attn, 1, NSEQ-1);
    rowdot_kernel<<<D_MODEL, 128>>>(p_sm_attn, D_MODEL, loc_Wo, loc_bo,
                                    p_sm_tmp, D_MODEL, NB, D_MODEL, 1.f, 0);
    ln_kernel<<<NB, 256>>>(p_x + (size_t)(NSEQ-1)*D_MODEL, (long)NSEQ*D_MODEL,
                           p_sm_tmp, D_MODEL, p_sm_x, D_MODEL, (__nv_bfloat16*)0,
                           loc_ln1g, loc_ln1b);
    rowdot_kernel<<<FF_DIM, 128>>>(p_sm_x, D_MODEL, loc_W1, loc_b1,
                                   p_sm_ffh, FF_DIM, NB, D_MODEL, 1.f, 1);
    rowdot_kernel<<<D_MODEL, 128>>>(p_sm_ffh, FF_DIM, loc_W2, loc_b2,
                                    p_sm_tmp, D_MODEL, NB, FF_DIM, 1.f, 0);
    ln_kernel<<<NB, 256>>>(p_sm_x, D_MODEL, p_sm_tmp, D_MODEL,
                           p_sm_ctx, D_MODEL, (__nv_bfloat16*)0,
                           loc_ln2g, loc_ln2b);

    rowdot_kernel<<<NEXP, 128>>>(p_sm_ctx, D_MODEL, gate_w, gate_b,
                                 out + 1, NEXP, NB, D_MODEL, 32.f, 0);
    stats_kernel<<<1, 256>>>(out + 1, noise);
    mix_kernel<<<(NROWS*D_MODEL/4 + 255)/256, 256>>>(responses);

    // join: encoder weights must be converted before the encoder loop
    cudaStreamWaitEvent(0, evEnc, 0);

    // two encoder layers (bf16 tensor cores)
    for (int l = 0; l < 2; l++) {
        const __nv_bfloat16* Wqkv = p_hWqkv + (size_t)l*QKV_LD*D_MODEL;
        const float*         bqkv = enc_bqkv + (size_t)l*QKV_LD;
        const __nv_bfloat16* Wo   = p_hWo   + (size_t)l*D_MODEL*D_MODEL;
        const float*         bo   = enc_bo  + (size_t)l*D_MODEL;
        const float* g1   = enc_ln1g + (size_t)l*D_MODEL;
        const float* b1l  = enc_ln1b + (size_t)l*D_MODEL;
        const __nv_bfloat16* W1   = p_hW1   + (size_t)l*FF_DIM*D_MODEL;
        const float*         bb1  = enc_b1  + (size_t)l*FF_DIM;
        const __nv_bfloat16* W2   = p_hW2   + (size_t)l*D_MODEL*FF_DIM;
        const float*         bb2  = enc_b2  + (size_t)l*D_MODEL;
        const float* g2   = enc_ln2g + (size_t)l*D_MODEL;
        const float* b2l  = enc_ln2b + (size_t)l*D_MODEL;

        gemm_bf_f32_kernel<<<dim3(QKV_LD/128, NROWS/128), 256>>>(
            p_hx, Wqkv, bqkv, p_qkv, D_MODEL, QKV_LD);
        attn8_kernel<<<dim3(NSEQ/QT, NHEAD, NB), 256>>>(p_qkv, p_hattn);
        gemm_bf_f32_kernel<<<dim3(D_MODEL/128, NROWS/128), 256>>>(
            p_hattn, Wo, bo, p_tmp, D_MODEL, D_MODEL);
        ln_kernel<<<NROWS, 256>>>(p_x, D_MODEL, p_tmp, D_MODEL, p_x, D_MODEL, p_hx, g1, b1l);
        gemm_bf_bf_relu_kernel<<<dim3(FF_DIM/128, NROWS/128), 256>>>(
            p_hx, W1, bb1, p_hffh, D_MODEL, FF_DIM);
        gemm_bf_f32_kernel<<<dim3(D_MODEL/128, NROWS/128), 256>>>(
            p_hffh, W2, bb2, p_tmp, FF_DIM, D_MODEL);
        ln_kernel<<<NROWS, 256>>>(p_x, D_MODEL, p_tmp, D_MODEL, p_x, D_MODEL, p_hx, g2, b2l);
    }

    // join: decoder bf16 weights ready
    cudaStreamWaitEvent(0, evDec, 0);

    // fused decoder GEMM + logsumexp (m-tiles adjacent for L2 reuse of dec_w)
    gemm_lse_bf_kernel<<<dim3(NROWS/128, NBLK_V), 256>>>(p_hx, p_hdec, D_MODEL);
    lse_reduce_kernel<<<NROWS, 128>>>();
    lablogit_kernel<<<dim3(NSEQ-1, NB), 128>>>(inputs, dec_w);
    final_kernel<<<1, 256>>>(out);

    cudaEventDestroy(evFork);
    cudaEventDestroy(evEnc);
    cudaEventDestroy(evDec);
    cudaStreamDestroy(s2);
}